// round 1
// baseline (speedup 1.0000x reference)
#include <cuda_runtime.h>
#include <math.h>

// Dims (fixed for this problem)
#define Bz    4
#define Tl    8192
#define Ed    512
#define Hd    8
#define KDd   64
#define HDd   128
#define Cd    256
#define NCd   32
#define E2d   1024
#define Mtot  32768   // B*T

// ---------------- scratch (device globals; no runtime alloc) ----------------
__device__ float g_q[(size_t)Mtot * Ed];
__device__ float g_k[(size_t)Mtot * Ed];
__device__ float g_v[(size_t)Mtot * E2d];
__device__ float g_g[(size_t)Mtot * E2d];
__device__ float g_act[(size_t)Mtot * E2d];
__device__ float g_kv[(size_t)Bz * NCd * Hd * KDd * HDd];
__device__ float g_state[(size_t)Bz * NCd * Hd * KDd * HDd];
__device__ float g_cscale[Bz * NCd * Hd];

// ---------------- generic fp32 SGEMM: C = alpha * A(MxK) @ B(KxN) ----------------
// BM=BN=128, BK=16, 256 threads, 8x8 micro-tile. All dims divisible.
__global__ __launch_bounds__(256) void sgemm_kernel(
    const float* __restrict__ A, const float* __restrict__ B,
    float* __restrict__ C, int M, int N, int K, float alpha)
{
    __shared__ float As[16][128];
    __shared__ float Bs[16][128];
    int tid = threadIdx.x;
    int tx = tid % 16, ty = tid / 16;
    int rowBlk = blockIdx.y * 128, colBlk = blockIdx.x * 128;

    float acc[8][8];
#pragma unroll
    for (int i = 0; i < 8; i++)
#pragma unroll
        for (int j = 0; j < 8; j++) acc[i][j] = 0.f;

    int aCol = (tid % 4) * 4;   // k in tile
    int aRow = tid / 4;         // 0..63
    int bCol = (tid % 32) * 4;
    int bRow = tid / 32;        // 0..7

    for (int k0 = 0; k0 < K; k0 += 16) {
#pragma unroll
        for (int i = 0; i < 2; i++) {
            float4 a = *(const float4*)&A[(size_t)(rowBlk + aRow + i * 64) * K + k0 + aCol];
            As[aCol + 0][aRow + i * 64] = a.x;
            As[aCol + 1][aRow + i * 64] = a.y;
            As[aCol + 2][aRow + i * 64] = a.z;
            As[aCol + 3][aRow + i * 64] = a.w;
        }
#pragma unroll
        for (int i = 0; i < 2; i++) {
            *(float4*)&Bs[bRow + i * 8][bCol] =
                *(const float4*)&B[(size_t)(k0 + bRow + i * 8) * N + colBlk + bCol];
        }
        __syncthreads();
#pragma unroll
        for (int k = 0; k < 16; k++) {
            float ra[8], rb[8];
#pragma unroll
            for (int i = 0; i < 8; i++) ra[i] = As[k][ty * 8 + i];
#pragma unroll
            for (int j = 0; j < 8; j++) rb[j] = Bs[k][tx * 8 + j];
#pragma unroll
            for (int i = 0; i < 8; i++)
#pragma unroll
                for (int j = 0; j < 8; j++) acc[i][j] += ra[i] * rb[j];
        }
        __syncthreads();
    }
#pragma unroll
    for (int i = 0; i < 8; i++)
#pragma unroll
        for (int j = 0; j < 8; j += 4) {
            float4 o;
            o.x = acc[i][j + 0] * alpha;
            o.y = acc[i][j + 1] * alpha;
            o.z = acc[i][j + 2] * alpha;
            o.w = acc[i][j + 3] * alpha;
            *(float4*)&C[(size_t)(rowBlk + ty * 8 + i) * N + colBlk + tx * 8 + j] = o;
        }
}

// ---------------- rotary (theta shift) in place ----------------
__global__ void rotary_kernel(float* __restrict__ q,
                              const float* __restrict__ sinp,
                              const float* __restrict__ cosp)
{
    long p = (long)blockIdx.x * 256 + threadIdx.x;   // pair index, total Mtot*Ed/2
    long base = p * 2;
    int e = (int)(base % Ed);
    long row = base / Ed;
    int t = (int)(row % Tl);
    int d = e % KDd;                  // even
    float s0 = sinp[t * KDd + d],     c0 = cosp[t * KDd + d];
    float s1 = sinp[t * KDd + d + 1], c1 = cosp[t * KDd + d + 1];
    float q0 = q[base], q1 = q[base + 1];
    q[base]     = q0 * c0 - q1 * s0;
    q[base + 1] = q1 * c1 + q0 * s1;
}

// ---------------- kv per chunk: kv[k,e] = sum_c kr[c,k]*v[c,e]*vid[h,c] ----------------
__global__ __launch_bounds__(256) void kv_kernel(const float* __restrict__ k,
                                                 const float* __restrict__ v,
                                                 const float* __restrict__ vid,
                                                 float* __restrict__ kv)
{
    __shared__ float kr_s[32 * 64];
    __shared__ float v_s[32 * 128];
    __shared__ float vid_s[32];
    int bx = blockIdx.x;                 // (b*NC+n)*H + h
    int h = bx % Hd;
    int n = (bx / Hd) % NCd;
    int b = bx / (Hd * NCd);
    int tid = threadIdx.x;
    int tx = tid % 32, ty = tid / 32;
    float acc[8][4];
#pragma unroll
    for (int i = 0; i < 8; i++)
#pragma unroll
        for (int j = 0; j < 4; j++) acc[i][j] = 0.f;

    long row0 = (long)b * Tl + n * Cd;
    for (int c0 = 0; c0 < Cd; c0 += 32) {
        {
            int col = (tid % 16) * 4, r = tid / 16;
#pragma unroll
            for (int i = 0; i < 2; i++)
                *(float4*)&kr_s[(r + i * 16) * 64 + col] =
                    *(const float4*)&k[(row0 + c0 + r + i * 16) * Ed + h * KDd + col];
            int col2 = (tid % 32) * 4, r2 = tid / 32;
#pragma unroll
            for (int i = 0; i < 4; i++)
                *(float4*)&v_s[(r2 + i * 8) * 128 + col2] =
                    *(const float4*)&v[(row0 + c0 + r2 + i * 8) * E2d + h * HDd + col2];
            if (tid < 32) vid_s[tid] = vid[h * Cd + c0 + tid];
        }
        __syncthreads();
#pragma unroll 4
        for (int c = 0; c < 32; c++) {
            float vv = vid_s[c];
            float4 v4 = *(float4*)&v_s[c * 128 + tx * 4];
            float rb[4] = {v4.x * vv, v4.y * vv, v4.z * vv, v4.w * vv};
#pragma unroll
            for (int i = 0; i < 8; i++) {
                float ka = kr_s[c * 64 + ty * 8 + i];
#pragma unroll
                for (int j = 0; j < 4; j++) acc[i][j] += ka * rb[j];
            }
        }
        __syncthreads();
    }
    float* outp = kv + (size_t)bx * (KDd * HDd);
#pragma unroll
    for (int i = 0; i < 8; i++) {
        float4 o = {acc[i][0], acc[i][1], acc[i][2], acc[i][3]};
        *(float4*)&outp[(ty * 8 + i) * 128 + tx * 4] = o;
    }
}

// ---------------- scan: per-element recurrence (raw state, no normalization) ----------------
__global__ void scan_kernel(const float* __restrict__ kv,
                            const float* __restrict__ cd,
                            float* __restrict__ state)
{
    int idx = blockIdx.x * 256 + threadIdx.x;   // 0 .. B*H*KD*HD-1
    int eidx = idx % (KDd * HDd);
    int bh = idx / (KDd * HDd);
    int h = bh % Hd, b = bh / Hd;
    float c = cd[h];
    float s = 0.f;
    for (int n = 0; n < NCd; n++) {
        size_t off = ((size_t)((b * NCd + n) * Hd + h)) * (KDd * HDd) + eidx;
        state[off] = s;
        s = s * c + kv[off];
    }
}

// ---------------- cross_scale: clip(max_e sum_k |state|, 1) ----------------
__global__ void cscale_kernel(const float* __restrict__ state, float* __restrict__ cs)
{
    int bx = blockIdx.x;
    int e = threadIdx.x;  // 0..127
    const float* sp = state + (size_t)bx * (KDd * HDd);
    float s = 0.f;
#pragma unroll 8
    for (int k2 = 0; k2 < KDd; k2++) s += fabsf(sp[k2 * HDd + e]);
#pragma unroll
    for (int o = 16; o > 0; o >>= 1) s = fmaxf(s, __shfl_xor_sync(0xffffffff, s, o));
    __shared__ float wmax[4];
    if ((e & 31) == 0) wmax[e >> 5] = s;
    __syncthreads();
    if (e == 0) {
        float m = fmaxf(fmaxf(wmax[0], wmax[1]), fmaxf(wmax[2], wmax[3]));
        cs[bx] = fmaxf(m, 1.0f);
    }
}

// ---------------- fused attention per (b,n,h,c-slab of 64 rows) ----------------
// qk = (qr @ kr^T)*mask ; iscale = max(1, rowsum|qk|) ;
// out = (qk@V + qid*(qr@state)) / max(iscale, cscale) ; rms over HD ; * silu(g)
__global__ __launch_bounds__(256) void attn_kernel(
    const float* __restrict__ q, const float* __restrict__ k,
    const float* __restrict__ v, const float* __restrict__ g,
    const float* __restrict__ state, const float* __restrict__ cs,
    const float* __restrict__ mask, const float* __restrict__ qid,
    float* __restrict__ act)
{
    extern __shared__ float sm[];
    float* qrT     = sm;                   // 64 * 65
    float* krT     = qrT + 64 * 65;        // 64 * 257
    float* qk_s    = krT + 64 * 257;       // 64 * 257
    float* v_s     = qk_s + 64 * 257;      // 64 * 128
    float* iscale_s = v_s + 64 * 128;      // 64
    float* qid_s   = iscale_s + 64;        // 64

    int bx = blockIdx.x;
    int cb = bx % 4;
    int h  = (bx / 4) % Hd;
    int n  = (bx / (4 * Hd)) % NCd;
    int b  = bx / (4 * Hd * NCd);
    int tid = threadIdx.x;
    int tx = tid % 16, ty = tid / 16;
    long row0 = (long)b * Tl + n * Cd;     // chunk start token row

    // ---- load qr (64x64 -> transposed) and kr (256x64 -> transposed)
    {
        int kg = (tid % 16) * 4;
        int cr = tid / 16;
#pragma unroll
        for (int p = 0; p < 4; p++) {
            int c = cr + p * 16;
            float4 a = *(const float4*)&q[(row0 + cb * 64 + c) * Ed + h * KDd + kg];
            qrT[(kg + 0) * 65 + c] = a.x;
            qrT[(kg + 1) * 65 + c] = a.y;
            qrT[(kg + 2) * 65 + c] = a.z;
            qrT[(kg + 3) * 65 + c] = a.w;
        }
#pragma unroll
        for (int p = 0; p < 16; p++) {
            int d = cr + p * 16;
            float4 a = *(const float4*)&k[(row0 + d) * Ed + h * KDd + kg];
            krT[(kg + 0) * 257 + d] = a.x;
            krT[(kg + 1) * 257 + d] = a.y;
            krT[(kg + 2) * 257 + d] = a.z;
            krT[(kg + 3) * 257 + d] = a.w;
        }
        if (tid < 64) qid_s[tid] = qid[h * Cd + cb * 64 + tid];
    }
    __syncthreads();

    // ---- phase 1: qk[64 x 256]
    float acc[4][16];
#pragma unroll
    for (int i = 0; i < 4; i++)
#pragma unroll
        for (int j = 0; j < 16; j++) acc[i][j] = 0.f;

#pragma unroll 4
    for (int kk = 0; kk < 64; kk++) {
        float ra[4], rb[16];
#pragma unroll
        for (int i = 0; i < 4; i++) ra[i] = qrT[kk * 65 + i * 16 + ty];
#pragma unroll
        for (int j = 0; j < 16; j++) rb[j] = krT[kk * 257 + j * 16 + tx];
#pragma unroll
        for (int i = 0; i < 4; i++)
#pragma unroll
            for (int j = 0; j < 16; j++) acc[i][j] += ra[i] * rb[j];
    }

    // ---- mask, abs row-sum, store to smem
    const float* mrow = mask + ((size_t)h * Cd + cb * 64) * Cd;
    float rs[4] = {0.f, 0.f, 0.f, 0.f};
#pragma unroll
    for (int i = 0; i < 4; i++) {
        int c = i * 16 + ty;
#pragma unroll
        for (int j = 0; j < 16; j++) {
            int d = j * 16 + tx;
            acc[i][j] *= mrow[c * Cd + d];
            rs[i] += fabsf(acc[i][j]);
        }
    }
#pragma unroll
    for (int o = 1; o < 16; o <<= 1)
#pragma unroll
        for (int i = 0; i < 4; i++) rs[i] += __shfl_xor_sync(0xffffffff, rs[i], o);
    if (tx == 0)
#pragma unroll
        for (int i = 0; i < 4; i++) iscale_s[i * 16 + ty] = fmaxf(rs[i], 1.0f);
#pragma unroll
    for (int i = 0; i < 4; i++)
#pragma unroll
        for (int j = 0; j < 16; j++)
            qk_s[(i * 16 + ty) * 257 + j * 16 + tx] = acc[i][j];
    __syncthreads();

    // ---- phase 2: inner = qk_s @ V   (stream V in 64-row chunks)
    float acc2[4][8];
#pragma unroll
    for (int i = 0; i < 4; i++)
#pragma unroll
        for (int j = 0; j < 8; j++) acc2[i][j] = 0.f;

    for (int dc = 0; dc < 4; dc++) {
        {
            int col = (tid % 32) * 4, r = tid / 32;
#pragma unroll
            for (int p = 0; p < 8; p++)
                *(float4*)&v_s[(r + p * 8) * 128 + col] =
                    *(const float4*)&v[(row0 + dc * 64 + r + p * 8) * E2d + h * HDd + col];
        }
        __syncthreads();
#pragma unroll 4
        for (int dd = 0; dd < 64; dd++) {
            int d = dc * 64 + dd;
            float ra[4], rb[8];
#pragma unroll
            for (int i = 0; i < 4; i++) ra[i] = qk_s[(i * 16 + ty) * 257 + d];
#pragma unroll
            for (int j = 0; j < 8; j++) rb[j] = v_s[dd * 128 + j * 16 + tx];
#pragma unroll
            for (int i = 0; i < 4; i++)
#pragma unroll
                for (int j = 0; j < 8; j++) acc2[i][j] += ra[i] * rb[j];
        }
        __syncthreads();
    }

    // ---- cross: acc3 = qr @ state ; state is [KD x HD] raw
    {
        const float* sp = state + ((size_t)((b * NCd + n) * Hd + h)) * (KDd * HDd);
        int col = (tid % 32) * 4, r = tid / 32;
#pragma unroll
        for (int p = 0; p < 8; p++)
            *(float4*)&v_s[(r + p * 8) * 128 + col] =
                *(const float4*)&sp[(r + p * 8) * 128 + col];
    }
    __syncthreads();
    float acc3[4][8];
#pragma unroll
    for (int i = 0; i < 4; i++)
#pragma unroll
        for (int j = 0; j < 8; j++) acc3[i][j] = 0.f;
#pragma unroll 4
    for (int kk = 0; kk < 64; kk++) {
        float ra[4], rb[8];
#pragma unroll
        for (int i = 0; i < 4; i++) ra[i] = qrT[kk * 65 + i * 16 + ty];
#pragma unroll
        for (int j = 0; j < 8; j++) rb[j] = v_s[kk * 128 + j * 16 + tx];
#pragma unroll
        for (int i = 0; i < 4; i++)
#pragma unroll
            for (int j = 0; j < 8; j++) acc3[i][j] += ra[i] * rb[j];
    }

    float csc = cs[(b * NCd + n) * Hd + h];

    // ---- combine, rms over HD per row, silu(g) gate, write act
#pragma unroll
    for (int i = 0; i < 4; i++) {
        int c = i * 16 + ty;
        float qd = qid_s[c];
        float alls = fmaxf(iscale_s[c], csc);
        float inv = 1.0f / alls;
        float val[8];
        float ss = 0.f;
#pragma unroll
        for (int j = 0; j < 8; j++) {
            val[j] = (acc2[i][j] + qd * acc3[i][j]) * inv;
            ss += val[j] * val[j];
        }
#pragma unroll
        for (int o = 1; o < 16; o <<= 1) ss += __shfl_xor_sync(0xffffffff, ss, o);
        float rnorm = rsqrtf(ss * (1.0f / 128.0f) + 1e-6f);
        long row = row0 + cb * 64 + c;
#pragma unroll
        for (int j = 0; j < 8; j++) {
            int e = j * 16 + tx;
            float gv = g[row * E2d + h * HDd + e];
            float sig = 1.0f / (1.0f + expf(-gv));
            act[row * E2d + h * HDd + e] = val[j] * rnorm * gv * sig;
        }
    }
}

// ---------------- host launch ----------------
extern "C" void kernel_launch(void* const* d_in, const int* in_sizes, int n_in,
                              void* d_out, int out_size)
{
    const float* x    = (const float*)d_in[0];
    const float* sinp = (const float*)d_in[1];
    const float* cosp = (const float*)d_in[2];
    const float* mask = (const float*)d_in[3];
    const float* cdec = (const float*)d_in[4];
    const float* qid  = (const float*)d_in[5];
    const float* vid  = (const float*)d_in[6];
    const float* Wq   = (const float*)d_in[7];
    const float* Wk   = (const float*)d_in[8];
    const float* Wv   = (const float*)d_in[9];
    const float* Wg   = (const float*)d_in[10];
    const float* Wo   = (const float*)d_in[11];
    float* out = (float*)d_out;

    float *p_q, *p_k, *p_v, *p_g, *p_act, *p_kv, *p_state, *p_cs;
    cudaGetSymbolAddress((void**)&p_q, g_q);
    cudaGetSymbolAddress((void**)&p_k, g_k);
    cudaGetSymbolAddress((void**)&p_v, g_v);
    cudaGetSymbolAddress((void**)&p_g, g_g);
    cudaGetSymbolAddress((void**)&p_act, g_act);
    cudaGetSymbolAddress((void**)&p_kv, g_kv);
    cudaGetSymbolAddress((void**)&p_state, g_state);
    cudaGetSymbolAddress((void**)&p_cs, g_cscale);

    const int smem_attn = (64 * 65 + 64 * 257 + 64 * 257 + 64 * 128 + 128) * 4;
    cudaFuncSetAttribute(attn_kernel, cudaFuncAttributeMaxDynamicSharedMemorySize, smem_attn);

    // projections
    sgemm_kernel<<<dim3(Ed / 128, Mtot / 128), 256>>>(x, Wq, p_q, Mtot, Ed, Ed, 1.0f);
    sgemm_kernel<<<dim3(Ed / 128, Mtot / 128), 256>>>(x, Wk, p_k, Mtot, Ed, Ed, 0.125f); // KD^-0.5
    sgemm_kernel<<<dim3(E2d / 128, Mtot / 128), 256>>>(x, Wv, p_v, Mtot, E2d, Ed, 1.0f);
    sgemm_kernel<<<dim3(E2d / 128, Mtot / 128), 256>>>(x, Wg, p_g, Mtot, E2d, Ed, 1.0f);

    // rotary on q and k
    int rot_blocks = (Mtot * Ed / 2) / 256;
    rotary_kernel<<<rot_blocks, 256>>>(p_q, sinp, cosp);
    rotary_kernel<<<rot_blocks, 256>>>(p_k, sinp, cosp);

    // per-chunk kv, scan, cross scale
    kv_kernel<<<Bz * NCd * Hd, 256>>>(p_k, p_v, vid, p_kv);
    scan_kernel<<<(Bz * Hd * KDd * HDd) / 256, 256>>>(p_kv, cdec, p_state);
    cscale_kernel<<<Bz * NCd * Hd, 128>>>(p_state, p_cs);

    // fused attention + combine + rms + silu
    attn_kernel<<<Bz * NCd * Hd * 4, 256, smem_attn>>>(
        p_q, p_k, p_v, p_g, p_state, p_cs, mask, qid, p_act);

    // output projection
    sgemm_kernel<<<dim3(Ed / 128, Mtot / 128), 256>>>(p_act, Wo, out, Mtot, Ed, E2d, 1.0f);
}

// round 3
// speedup vs baseline: 1.7593x; 1.7593x over previous
#include <cuda_runtime.h>
#include <math.h>
#include <stdint.h>

// Dims (fixed for this problem)
#define Bz    4
#define Tl    8192
#define Ed    512
#define Hd    8
#define KDd   64
#define HDd   128
#define Cd    256
#define NCd   32
#define E2d   1024
#define Mtot  32768   // B*T

// ---------------- scratch (device globals; no runtime alloc) ----------------
__device__ float g_q[(size_t)Mtot * Ed];
__device__ float g_k[(size_t)Mtot * Ed];
__device__ float g_v[(size_t)Mtot * E2d];
__device__ float g_g[(size_t)Mtot * E2d];
__device__ float g_act[(size_t)Mtot * E2d];
__device__ float g_kv[(size_t)Bz * NCd * Hd * KDd * HDd];
__device__ float g_state[(size_t)Bz * NCd * Hd * KDd * HDd];
__device__ float g_cscale[Bz * NCd * Hd];
__device__ float g_wt[2097152];   // transposed weights (WqT,WkT,WvT,WgT,WoT)

__device__ __forceinline__ uint32_t smem_u32(const void* p) {
    uint32_t a;
    asm("{ .reg .u64 t; cvta.to.shared.u64 t, %1; cvt.u32.u64 %0, t; }"
        : "=r"(a) : "l"(p));
    return a;
}
__device__ __forceinline__ float to_tf32(float x) {
    uint32_t r;
    asm("cvt.rna.tf32.f32 %0, %1;" : "=r"(r) : "f"(x));
    return __uint_as_float(r);
}

#define LDSM4(r0, r1, r2, r3, a)                                               \
    asm volatile("ldmatrix.sync.aligned.m8n8.x4.shared.b16 {%0,%1,%2,%3}, [%4];" \
                 : "=r"(r0), "=r"(r1), "=r"(r2), "=r"(r3) : "r"(a))

#define MMA_TF32(c, a, b0, b1)                                                 \
    asm volatile("mma.sync.aligned.m16n8k8.row.col.f32.tf32.tf32.f32 "         \
                 "{%0,%1,%2,%3},{%4,%5,%6,%7},{%8,%9},{%0,%1,%2,%3};"          \
                 : "+f"((c)[0]), "+f"((c)[1]), "+f"((c)[2]), "+f"((c)[3])      \
                 : "r"((a)[0]), "r"((a)[1]), "r"((a)[2]), "r"((a)[3]),         \
                   "r"(b0), "r"(b1))

// ---------------- weight transpose: Wt[N,K] = W[K,N]^T ----------------
__global__ void transpose_kernel(const float* __restrict__ W, float* __restrict__ Wt,
                                 int K, int N)
{
    __shared__ float t[32][33];
    int n0 = blockIdx.x * 32, k0 = blockIdx.y * 32;
    int tx = threadIdx.x, ty = threadIdx.y;  // 32 x 8
#pragma unroll
    for (int i = 0; i < 4; i++)
        t[ty + i * 8][tx] = W[(size_t)(k0 + ty + i * 8) * N + n0 + tx];
    __syncthreads();
#pragma unroll
    for (int i = 0; i < 4; i++)
        Wt[(size_t)(n0 + ty + i * 8) * K + k0 + tx] = t[tx][ty + i * 8];
}

// ---------------- tf32 tensor-core GEMM: C = alpha * A[M,K] @ Bt[N,K]^T ----------------
// CTA tile 128x128, BK=32, 8 warps (each 64x32 via 4x4 m16n8k8 mma.sync).
__global__ __launch_bounds__(256, 2) void mma_gemm(
    const float* __restrict__ A, const float* __restrict__ Bt,
    float* __restrict__ C, int M, int N, int K, float alpha)
{
    __shared__ float As[128 * 32];
    __shared__ float Bs[128 * 32];

    int tid = threadIdx.x;
    int lane = tid & 31;
    int w = tid >> 5;
    int wm = w & 1;        // 0..1 -> 64-row half
    int wn = w >> 1;       // 0..3 -> 32-col quarter
    int rowBlk = blockIdx.y * 128, colBlk = blockIdx.x * 128;

    float acc[4][4][4];
#pragma unroll
    for (int mi = 0; mi < 4; mi++)
#pragma unroll
        for (int ni = 0; ni < 4; ni++)
#pragma unroll
            for (int r = 0; r < 4; r++) acc[mi][ni][r] = 0.f;

    uint32_t sA = smem_u32(As), sB = smem_u32(Bs);

    // ldmatrix base addresses (XOR-swizzled rows of 128B)
    int rowA0 = wm * 64 + (lane & 15);
    uint32_t baA = sA + rowA0 * 128 + (((lane >> 4) * 16) ^ ((rowA0 & 7) << 4));
    int nB0 = wn * 32 + (lane & 7) + ((lane & 16) ? 8 : 0);
    uint32_t baB = sB + nB0 * 128 + ((((lane >> 3) & 1) * 16) ^ ((nB0 & 7) << 4));

    int ldrow = tid >> 3;          // 0..31
    int kq = (tid & 7) * 4;        // float offset in 32-float row
    const int L = K >> 5;

    for (int kt = 0; kt < L; kt++) {
        int k0 = kt * 32;
#pragma unroll
        for (int p = 0; p < 4; p++) {
            int row = p * 32 + ldrow;
            int foff = row * 32 + ((((kq * 4) ^ ((row & 7) << 4))) >> 2);
            float4 a = *(const float4*)&A[(size_t)(rowBlk + row) * K + k0 + kq];
            a.x = to_tf32(a.x); a.y = to_tf32(a.y); a.z = to_tf32(a.z); a.w = to_tf32(a.w);
            *(float4*)&As[foff] = a;
            float4 b = *(const float4*)&Bt[(size_t)(colBlk + row) * K + k0 + kq];
            b.x = to_tf32(b.x); b.y = to_tf32(b.y); b.z = to_tf32(b.z); b.w = to_tf32(b.w);
            *(float4*)&Bs[foff] = b;
        }
        __syncthreads();
#pragma unroll
        for (int s = 0; s < 4; s++) {
            uint32_t af[4][4];
#pragma unroll
            for (int mi = 0; mi < 4; mi++)
                LDSM4(af[mi][0], af[mi][1], af[mi][2], af[mi][3],
                      (baA + mi * 2048) ^ (uint32_t)(s * 32));
            uint32_t bf[8];
            LDSM4(bf[0], bf[1], bf[2], bf[3], baB ^ (uint32_t)(s * 32));
            LDSM4(bf[4], bf[5], bf[6], bf[7], (baB + 2048) ^ (uint32_t)(s * 32));
#pragma unroll
            for (int mi = 0; mi < 4; mi++)
#pragma unroll
                for (int ni = 0; ni < 4; ni++)
                    MMA_TF32(acc[mi][ni], af[mi], bf[ni * 2], bf[ni * 2 + 1]);
        }
        __syncthreads();
    }

    // epilogue: fragment layout c0,c1 at (lane/4, 2*(lane%4)+{0,1}), c2,c3 at row+8
    int r0 = lane >> 2, cp = (lane & 3) * 2;
#pragma unroll
    for (int mi = 0; mi < 4; mi++) {
#pragma unroll
        for (int ni = 0; ni < 4; ni++) {
            size_t row = (size_t)(rowBlk + wm * 64 + mi * 16 + r0);
            int col = colBlk + wn * 32 + ni * 8 + cp;
            float2 o0 = {acc[mi][ni][0] * alpha, acc[mi][ni][1] * alpha};
            float2 o1 = {acc[mi][ni][2] * alpha, acc[mi][ni][3] * alpha};
            *(float2*)&C[row * N + col] = o0;
            *(float2*)&C[(row + 8) * N + col] = o1;
        }
    }
}

// ---------------- rotary (theta shift) in place ----------------
__global__ void rotary_kernel(float* __restrict__ q,
                              const float* __restrict__ sinp,
                              const float* __restrict__ cosp)
{
    long p = (long)blockIdx.x * 256 + threadIdx.x;
    long base = p * 2;
    int e = (int)(base % Ed);
    long row = base / Ed;
    int t = (int)(row % Tl);
    int d = e % KDd;
    float s0 = sinp[t * KDd + d],     c0 = cosp[t * KDd + d];
    float s1 = sinp[t * KDd + d + 1], c1 = cosp[t * KDd + d + 1];
    float q0 = q[base], q1 = q[base + 1];
    q[base]     = q0 * c0 - q1 * s0;
    q[base + 1] = q1 * c1 + q0 * s1;
}

// ---------------- kv per chunk: kv[k,e] = sum_c kr[c,k]*v[c,e]*vid[h,c] ----------------
__global__ __launch_bounds__(256) void kv_kernel(const float* __restrict__ k,
                                                 const float* __restrict__ v,
                                                 const float* __restrict__ vid,
                                                 float* __restrict__ kv)
{
    __shared__ float kr_s[32 * 64];
    __shared__ float v_s[32 * 128];
    __shared__ float vid_s[32];
    int bx = blockIdx.x;
    int h = bx % Hd;
    int n = (bx / Hd) % NCd;
    int b = bx / (Hd * NCd);
    int tid = threadIdx.x;
    int tx = tid % 32, ty = tid / 32;
    float acc[8][4];
#pragma unroll
    for (int i = 0; i < 8; i++)
#pragma unroll
        for (int j = 0; j < 4; j++) acc[i][j] = 0.f;

    long row0 = (long)b * Tl + n * Cd;
    for (int c0 = 0; c0 < Cd; c0 += 32) {
        {
            int col = (tid % 16) * 4, r = tid / 16;
#pragma unroll
            for (int i = 0; i < 2; i++)
                *(float4*)&kr_s[(r + i * 16) * 64 + col] =
                    *(const float4*)&k[(row0 + c0 + r + i * 16) * Ed + h * KDd + col];
            int col2 = (tid % 32) * 4, r2 = tid / 32;
#pragma unroll
            for (int i = 0; i < 4; i++)
                *(float4*)&v_s[(r2 + i * 8) * 128 + col2] =
                    *(const float4*)&v[(row0 + c0 + r2 + i * 8) * E2d + h * HDd + col2];
            if (tid < 32) vid_s[tid] = vid[h * Cd + c0 + tid];
        }
        __syncthreads();
#pragma unroll 4
        for (int c = 0; c < 32; c++) {
            float vv = vid_s[c];
            float4 v4 = *(float4*)&v_s[c * 128 + tx * 4];
            float rb[4] = {v4.x * vv, v4.y * vv, v4.z * vv, v4.w * vv};
#pragma unroll
            for (int i = 0; i < 8; i++) {
                float ka = kr_s[c * 64 + ty * 8 + i];
#pragma unroll
                for (int j = 0; j < 4; j++) acc[i][j] += ka * rb[j];
            }
        }
        __syncthreads();
    }
    float* outp = kv + (size_t)bx * (KDd * HDd);
#pragma unroll
    for (int i = 0; i < 8; i++) {
        float4 o = {acc[i][0], acc[i][1], acc[i][2], acc[i][3]};
        *(float4*)&outp[(ty * 8 + i) * 128 + tx * 4] = o;
    }
}

// ---------------- scan: per-element recurrence (raw state) ----------------
__global__ void scan_kernel(const float* __restrict__ kv,
                            const float* __restrict__ cd,
                            float* __restrict__ state)
{
    int idx = blockIdx.x * 256 + threadIdx.x;
    int eidx = idx % (KDd * HDd);
    int bh = idx / (KDd * HDd);
    int h = bh % Hd, b = bh / Hd;
    float c = cd[h];
    float s = 0.f;
    for (int n = 0; n < NCd; n++) {
        size_t off = ((size_t)((b * NCd + n) * Hd + h)) * (KDd * HDd) + eidx;
        state[off] = s;
        s = s * c + kv[off];
    }
}

// ---------------- cross_scale: clip(max_e sum_k |state|, 1) ----------------
__global__ void cscale_kernel(const float* __restrict__ state, float* __restrict__ cs)
{
    int bx = blockIdx.x;
    int e = threadIdx.x;
    const float* sp = state + (size_t)bx * (KDd * HDd);
    float s = 0.f;
#pragma unroll 8
    for (int k2 = 0; k2 < KDd; k2++) s += fabsf(sp[k2 * HDd + e]);
#pragma unroll
    for (int o = 16; o > 0; o >>= 1) s = fmaxf(s, __shfl_xor_sync(0xffffffff, s, o));
    __shared__ float wmax[4];
    if ((e & 31) == 0) wmax[e >> 5] = s;
    __syncthreads();
    if (e == 0) {
        float m = fmaxf(fmaxf(wmax[0], wmax[1]), fmaxf(wmax[2], wmax[3]));
        cs[bx] = fmaxf(m, 1.0f);
    }
}

// ---------------- fused attention per (b,n,h,c-slab of 64 rows) ----------------
__global__ __launch_bounds__(256) void attn_kernel(
    const float* __restrict__ q, const float* __restrict__ k,
    const float* __restrict__ v, const float* __restrict__ g,
    const float* __restrict__ state, const float* __restrict__ cs,
    const float* __restrict__ mask, const float* __restrict__ qid,
    float* __restrict__ act)
{
    extern __shared__ float sm[];
    float* qrT      = sm;
    float* krT      = qrT + 64 * 65;
    float* qk_s     = krT + 64 * 257;
    float* v_s      = qk_s + 64 * 257;
    float* iscale_s = v_s + 64 * 128;
    float* qid_s    = iscale_s + 64;

    int bx = blockIdx.x;
    int cb = bx % 4;
    int h  = (bx / 4) % Hd;
    int n  = (bx / (4 * Hd)) % NCd;
    int b  = bx / (4 * Hd * NCd);
    int tid = threadIdx.x;
    int tx = tid % 16, ty = tid / 16;
    long row0 = (long)b * Tl + n * Cd;

    {
        int kg = (tid % 16) * 4;
        int cr = tid / 16;
#pragma unroll
        for (int p = 0; p < 4; p++) {
            int c = cr + p * 16;
            float4 a = *(const float4*)&q[(row0 + cb * 64 + c) * Ed + h * KDd + kg];
            qrT[(kg + 0) * 65 + c] = a.x;
            qrT[(kg + 1) * 65 + c] = a.y;
            qrT[(kg + 2) * 65 + c] = a.z;
            qrT[(kg + 3) * 65 + c] = a.w;
        }
#pragma unroll
        for (int p = 0; p < 16; p++) {
            int d = cr + p * 16;
            float4 a = *(const float4*)&k[(row0 + d) * Ed + h * KDd + kg];
            krT[(kg + 0) * 257 + d] = a.x;
            krT[(kg + 1) * 257 + d] = a.y;
            krT[(kg + 2) * 257 + d] = a.z;
            krT[(kg + 3) * 257 + d] = a.w;
        }
        if (tid < 64) qid_s[tid] = qid[h * Cd + cb * 64 + tid];
    }
    __syncthreads();

    float acc[4][16];
#pragma unroll
    for (int i = 0; i < 4; i++)
#pragma unroll
        for (int j = 0; j < 16; j++) acc[i][j] = 0.f;

#pragma unroll 4
    for (int kk = 0; kk < 64; kk++) {
        float ra[4], rb[16];
#pragma unroll
        for (int i = 0; i < 4; i++) ra[i] = qrT[kk * 65 + i * 16 + ty];
#pragma unroll
        for (int j = 0; j < 16; j++) rb[j] = krT[kk * 257 + j * 16 + tx];
#pragma unroll
        for (int i = 0; i < 4; i++)
#pragma unroll
            for (int j = 0; j < 16; j++) acc[i][j] += ra[i] * rb[j];
    }

    const float* mrow = mask + ((size_t)h * Cd + cb * 64) * Cd;
    float rs[4] = {0.f, 0.f, 0.f, 0.f};
#pragma unroll
    for (int i = 0; i < 4; i++) {
        int c = i * 16 + ty;
#pragma unroll
        for (int j = 0; j < 16; j++) {
            int d = j * 16 + tx;
            acc[i][j] *= mrow[c * Cd + d];
            rs[i] += fabsf(acc[i][j]);
        }
    }
#pragma unroll
    for (int o = 1; o < 16; o <<= 1)
#pragma unroll
        for (int i = 0; i < 4; i++) rs[i] += __shfl_xor_sync(0xffffffff, rs[i], o);
    if (tx == 0)
#pragma unroll
        for (int i = 0; i < 4; i++) iscale_s[i * 16 + ty] = fmaxf(rs[i], 1.0f);
#pragma unroll
    for (int i = 0; i < 4; i++)
#pragma unroll
        for (int j = 0; j < 16; j++)
            qk_s[(i * 16 + ty) * 257 + j * 16 + tx] = acc[i][j];
    __syncthreads();

    float acc2[4][8];
#pragma unroll
    for (int i = 0; i < 4; i++)
#pragma unroll
        for (int j = 0; j < 8; j++) acc2[i][j] = 0.f;

    for (int dc = 0; dc < 4; dc++) {
        {
            int col = (tid % 32) * 4, r = tid / 32;
#pragma unroll
            for (int p = 0; p < 8; p++)
                *(float4*)&v_s[(r + p * 8) * 128 + col] =
                    *(const float4*)&v[(row0 + dc * 64 + r + p * 8) * E2d + h * HDd + col];
        }
        __syncthreads();
#pragma unroll 4
        for (int dd = 0; dd < 64; dd++) {
            int d = dc * 64 + dd;
            float ra[4], rb[8];
#pragma unroll
            for (int i = 0; i < 4; i++) ra[i] = qk_s[(i * 16 + ty) * 257 + d];
#pragma unroll
            for (int j = 0; j < 8; j++) rb[j] = v_s[dd * 128 + j * 16 + tx];
#pragma unroll
            for (int i = 0; i < 4; i++)
#pragma unroll
                for (int j = 0; j < 8; j++) acc2[i][j] += ra[i] * rb[j];
        }
        __syncthreads();
    }

    {
        const float* sp = state + ((size_t)((b * NCd + n) * Hd + h)) * (KDd * HDd);
        int col = (tid % 32) * 4, r = tid / 32;
#pragma unroll
        for (int p = 0; p < 8; p++)
            *(float4*)&v_s[(r + p * 8) * 128 + col] =
                *(const float4*)&sp[(r + p * 8) * 128 + col];
    }
    __syncthreads();
    float acc3[4][8];
#pragma unroll
    for (int i = 0; i < 4; i++)
#pragma unroll
        for (int j = 0; j < 8; j++) acc3[i][j] = 0.f;
#pragma unroll 4
    for (int kk = 0; kk < 64; kk++) {
        float ra[4], rb[8];
#pragma unroll
        for (int i = 0; i < 4; i++) ra[i] = qrT[kk * 65 + i * 16 + ty];
#pragma unroll
        for (int j = 0; j < 8; j++) rb[j] = v_s[kk * 128 + j * 16 + tx];
#pragma unroll
        for (int i = 0; i < 4; i++)
#pragma unroll
            for (int j = 0; j < 8; j++) acc3[i][j] += ra[i] * rb[j];
    }

    float csc = cs[(b * NCd + n) * Hd + h];

#pragma unroll
    for (int i = 0; i < 4; i++) {
        int c = i * 16 + ty;
        float qd = qid_s[c];
        float alls = fmaxf(iscale_s[c], csc);
        float inv = 1.0f / alls;
        float val[8];
        float ss = 0.f;
#pragma unroll
        for (int j = 0; j < 8; j++) {
            val[j] = (acc2[i][j] + qd * acc3[i][j]) * inv;
            ss += val[j] * val[j];
        }
#pragma unroll
        for (int o = 1; o < 16; o <<= 1) ss += __shfl_xor_sync(0xffffffff, ss, o);
        float rnorm = rsqrtf(ss * (1.0f / 128.0f) + 1e-6f);
        long row = row0 + cb * 64 + c;
#pragma unroll
        for (int j = 0; j < 8; j++) {
            int e = j * 16 + tx;
            float gv = g[row * E2d + h * HDd + e];
            float sig = 1.0f / (1.0f + expf(-gv));
            act[row * E2d + h * HDd + e] = val[j] * rnorm * gv * sig;
        }
    }
}

// ---------------- host launch ----------------
extern "C" void kernel_launch(void* const* d_in, const int* in_sizes, int n_in,
                              void* d_out, int out_size)
{
    const float* x    = (const float*)d_in[0];
    const float* sinp = (const float*)d_in[1];
    const float* cosp = (const float*)d_in[2];
    const float* mask = (const float*)d_in[3];
    const float* cdec = (const float*)d_in[4];
    const float* qid  = (const float*)d_in[5];
    const float* vid  = (const float*)d_in[6];
    const float* Wq   = (const float*)d_in[7];
    const float* Wk   = (const float*)d_in[8];
    const float* Wv   = (const float*)d_in[9];
    const float* Wg   = (const float*)d_in[10];
    const float* Wo   = (const float*)d_in[11];
    float* out = (float*)d_out;

    float *p_q, *p_k, *p_v, *p_g, *p_act, *p_kv, *p_state, *p_cs, *p_wt;
    cudaGetSymbolAddress((void**)&p_q, g_q);
    cudaGetSymbolAddress((void**)&p_k, g_k);
    cudaGetSymbolAddress((void**)&p_v, g_v);
    cudaGetSymbolAddress((void**)&p_g, g_g);
    cudaGetSymbolAddress((void**)&p_act, g_act);
    cudaGetSymbolAddress((void**)&p_kv, g_kv);
    cudaGetSymbolAddress((void**)&p_state, g_state);
    cudaGetSymbolAddress((void**)&p_cs, g_cscale);
    cudaGetSymbolAddress((void**)&p_wt, g_wt);

    float* wtq = p_wt;                 // [512,512]
    float* wtk = p_wt + 262144;        // [512,512]
    float* wtv = p_wt + 524288;        // [1024,512]
    float* wtg = p_wt + 1048576;       // [1024,512]
    float* wto = p_wt + 1572864;       // [512,1024]

    const int smem_attn = (64 * 65 + 64 * 257 + 64 * 257 + 64 * 128 + 128) * 4;
    cudaFuncSetAttribute(attn_kernel, cudaFuncAttributeMaxDynamicSharedMemorySize, smem_attn);

    // weight transposes (K-major B operand)
    transpose_kernel<<<dim3(16, 16), dim3(32, 8)>>>(Wq, wtq, Ed, Ed);
    transpose_kernel<<<dim3(16, 16), dim3(32, 8)>>>(Wk, wtk, Ed, Ed);
    transpose_kernel<<<dim3(32, 16), dim3(32, 8)>>>(Wv, wtv, Ed, E2d);
    transpose_kernel<<<dim3(32, 16), dim3(32, 8)>>>(Wg, wtg, Ed, E2d);
    transpose_kernel<<<dim3(16, 32), dim3(32, 8)>>>(Wo, wto, E2d, Ed);

    // projections on tensor cores (tf32 mma.sync)
    mma_gemm<<<dim3(4, 256), 256>>>(x, wtq, p_q, Mtot, Ed, Ed, 1.0f);
    mma_gemm<<<dim3(4, 256), 256>>>(x, wtk, p_k, Mtot, Ed, Ed, 0.125f);
    mma_gemm<<<dim3(8, 256), 256>>>(x, wtv, p_v, Mtot, E2d, Ed, 1.0f);
    mma_gemm<<<dim3(8, 256), 256>>>(x, wtg, p_g, Mtot, E2d, Ed, 1.0f);

    // rotary on q and k
    int rot_blocks = (Mtot * Ed / 2) / 256;
    rotary_kernel<<<rot_blocks, 256>>>(p_q, sinp, cosp);
    rotary_kernel<<<rot_blocks, 256>>>(p_k, sinp, cosp);

    // per-chunk kv, scan, cross scale
    kv_kernel<<<Bz * NCd * Hd, 256>>>(p_k, p_v, vid, p_kv);
    scan_kernel<<<(Bz * Hd * KDd * HDd) / 256, 256>>>(p_kv, cdec, p_state);
    cscale_kernel<<<Bz * NCd * Hd, 128>>>(p_state, p_cs);

    // fused attention + combine + rms + silu
    attn_kernel<<<Bz * NCd * Hd * 4, 256, smem_attn>>>(
        p_q, p_k, p_v, p_g, p_state, p_cs, mask, qid, p_act);

    // output projection
    mma_gemm<<<dim3(4, 256), 256>>>(p_act, wto, out, Mtot, Ed, E2d, 1.0f);
}

// round 4
// speedup vs baseline: 2.0159x; 1.1459x over previous
#include <cuda_runtime.h>
#include <math.h>
#include <stdint.h>

// Dims (fixed for this problem)
#define Bz    4
#define Tl    8192
#define Ed    512
#define Hd    8
#define KDd   64
#define HDd   128
#define Cd    256
#define NCd   32
#define E2d   1024
#define Mtot  32768   // B*T

// ---------------- scratch (device globals; no runtime alloc) ----------------
__device__ float g_q[(size_t)Mtot * Ed];
__device__ float g_k[(size_t)Mtot * Ed];
__device__ float g_v[(size_t)Mtot * E2d];
__device__ float g_g[(size_t)Mtot * E2d];
__device__ float g_act[(size_t)Mtot * E2d];
__device__ float g_xr[(size_t)Mtot * Ed];     // tf32-rounded x
__device__ float g_kv[(size_t)Bz * NCd * Hd * KDd * HDd];
__device__ float g_state[(size_t)Bz * NCd * Hd * KDd * HDd];
__device__ float g_cscale[Bz * NCd * Hd];
__device__ float g_wt[2097152];   // transposed+rounded weights

__device__ __forceinline__ uint32_t smem_u32(const void* p) {
    uint32_t a;
    asm("{ .reg .u64 t; cvta.to.shared.u64 t, %1; cvt.u32.u64 %0, t; }"
        : "=r"(a) : "l"(p));
    return a;
}
__device__ __forceinline__ float to_tf32(float x) {
    uint32_t r;
    asm("cvt.rna.tf32.f32 %0, %1;" : "=r"(r) : "f"(x));
    return __uint_as_float(r);
}

#define LDSM4(r0, r1, r2, r3, a)                                               \
    asm volatile("ldmatrix.sync.aligned.m8n8.x4.shared.b16 {%0,%1,%2,%3}, [%4];" \
                 : "=r"(r0), "=r"(r1), "=r"(r2), "=r"(r3) : "r"(a))

#define MMA_TF32(c, a, b0, b1)                                                 \
    asm volatile("mma.sync.aligned.m16n8k8.row.col.f32.tf32.tf32.f32 "         \
                 "{%0,%1,%2,%3},{%4,%5,%6,%7},{%8,%9},{%0,%1,%2,%3};"          \
                 : "+f"((c)[0]), "+f"((c)[1]), "+f"((c)[2]), "+f"((c)[3])      \
                 : "r"((a)[0]), "r"((a)[1]), "r"((a)[2]), "r"((a)[3]),         \
                   "r"(b0), "r"(b1))

#define CP_ASYNC16(dst, src)                                                   \
    asm volatile("cp.async.cg.shared.global [%0], [%1], 16;"                   \
                 :: "r"(dst), "l"(src))
#define CP_COMMIT asm volatile("cp.async.commit_group;" ::: "memory")
#define CP_WAIT(n) asm volatile("cp.async.wait_group %0;" :: "n"(n) : "memory")

// ---------------- tf32 pre-round of x ----------------
__global__ void round_kernel(const float* __restrict__ in, float* __restrict__ out)
{
    int i = blockIdx.x * 256 + threadIdx.x;
    float4 v = ((const float4*)in)[i];
    v.x = to_tf32(v.x); v.y = to_tf32(v.y); v.z = to_tf32(v.z); v.w = to_tf32(v.w);
    ((float4*)out)[i] = v;
}

// ---------------- weight transpose (+scale+round): Wt[N,K] = tf32(W[K,N]^T * s) ----
__global__ void transpose_kernel(const float* __restrict__ W, float* __restrict__ Wt,
                                 int K, int N, float scale)
{
    __shared__ float t[32][33];
    int n0 = blockIdx.x * 32, k0 = blockIdx.y * 32;
    int tx = threadIdx.x, ty = threadIdx.y;  // 32 x 8
#pragma unroll
    for (int i = 0; i < 4; i++)
        t[ty + i * 8][tx] = W[(size_t)(k0 + ty + i * 8) * N + n0 + tx];
    __syncthreads();
#pragma unroll
    for (int i = 0; i < 4; i++)
        Wt[(size_t)(n0 + ty + i * 8) * K + k0 + tx] = to_tf32(t[tx][ty + i * 8] * scale);
}

// ---------------- pipelined tf32 tensor-core GEMM: C = A[M,K] @ Bt[N,K]^T ----------
// CTA tile 128x128, BK=32, 3-stage cp.async pipeline, 8 warps (each 64x32).
#define STAGES 3
#define STG_BYTES 16384
#define GEMM_SMEM (STAGES * 2 * STG_BYTES)
__global__ __launch_bounds__(256) void mma_gemm(
    const float* __restrict__ A, const float* __restrict__ Bt,
    float* __restrict__ C, int M, int N, int K)
{
    extern __shared__ float smemf[];
    uint32_t sbase = smem_u32(smemf);
    const uint32_t BOFF = STAGES * STG_BYTES;

    int tid = threadIdx.x;
    int lane = tid & 31;
    int w = tid >> 5;
    int wm = w & 1;        // 64-row half
    int wn = w >> 1;       // 32-col quarter
    int rowBlk = blockIdx.y * 128, colBlk = blockIdx.x * 128;

    float acc[4][4][4];
#pragma unroll
    for (int mi = 0; mi < 4; mi++)
#pragma unroll
        for (int ni = 0; ni < 4; ni++)
#pragma unroll
            for (int r = 0; r < 4; r++) acc[mi][ni][r] = 0.f;

    // per-thread copy slots
    int ldrow = tid >> 3;          // 0..31
    int kq = (tid & 7) * 4;        // float offset in 32-float row
    const int L = K >> 5;

    // ldmatrix base offsets within a stage
    int rowA0 = wm * 64 + (lane & 15);
    uint32_t offA = rowA0 * 128 + (((lane >> 4) * 16) ^ ((rowA0 & 7) << 4));
    int nB0 = wn * 32 + (lane & 7) + ((lane & 16) ? 8 : 0);
    uint32_t offB = nB0 * 128 + ((((lane >> 3) & 1) * 16) ^ ((nB0 & 7) << 4));

#define PREFETCH(kt, st) do {                                                  \
    int _k0 = (kt) * 32;                                                       \
    uint32_t _b = sbase + (st) * STG_BYTES;                                    \
    _Pragma("unroll")                                                          \
    for (int p = 0; p < 4; p++) {                                              \
        int row = p * 32 + ldrow;                                              \
        uint32_t sw = row * 128 + (((uint32_t)(kq * 4)) ^ ((row & 7) << 4));   \
        CP_ASYNC16(_b + sw, &A[(size_t)(rowBlk + row) * K + _k0 + kq]);        \
        CP_ASYNC16(_b + BOFF + sw, &Bt[(size_t)(colBlk + row) * K + _k0 + kq]);\
    }                                                                          \
    CP_COMMIT;                                                                 \
} while (0)

    PREFETCH(0, 0);
    PREFETCH(1, 1);

    for (int kt = 0; kt < L; kt++) {
        CP_WAIT(STAGES - 2);
        __syncthreads();
        int nf = kt + STAGES - 1;
        if (nf < L) PREFETCH(nf, nf % STAGES);

        int st = kt % STAGES;
        uint32_t baA = sbase + st * STG_BYTES + offA;
        uint32_t baB = sbase + st * STG_BYTES + BOFF + offB;
#pragma unroll
        for (int s = 0; s < 4; s++) {
            uint32_t af[4][4];
#pragma unroll
            for (int mi = 0; mi < 4; mi++)
                LDSM4(af[mi][0], af[mi][1], af[mi][2], af[mi][3],
                      (baA + mi * 2048) ^ (uint32_t)(s * 32));
            uint32_t bf[8];
            LDSM4(bf[0], bf[1], bf[2], bf[3], baB ^ (uint32_t)(s * 32));
            LDSM4(bf[4], bf[5], bf[6], bf[7], (baB + 2048) ^ (uint32_t)(s * 32));
#pragma unroll
            for (int mi = 0; mi < 4; mi++)
#pragma unroll
                for (int ni = 0; ni < 4; ni++)
                    MMA_TF32(acc[mi][ni], af[mi], bf[ni * 2], bf[ni * 2 + 1]);
        }
        __syncthreads();
    }

    // epilogue
    int r0 = lane >> 2, cp = (lane & 3) * 2;
#pragma unroll
    for (int mi = 0; mi < 4; mi++) {
#pragma unroll
        for (int ni = 0; ni < 4; ni++) {
            size_t row = (size_t)(rowBlk + wm * 64 + mi * 16 + r0);
            int col = colBlk + wn * 32 + ni * 8 + cp;
            float2 o0 = {acc[mi][ni][0], acc[mi][ni][1]};
            float2 o1 = {acc[mi][ni][2], acc[mi][ni][3]};
            *(float2*)&C[row * N + col] = o0;
            *(float2*)&C[(row + 8) * N + col] = o1;
        }
    }
#undef PREFETCH
}

// ---------------- rotary (theta shift) in place ----------------
__global__ void rotary_kernel(float* __restrict__ q,
                              const float* __restrict__ sinp,
                              const float* __restrict__ cosp)
{
    long p = (long)blockIdx.x * 256 + threadIdx.x;
    long base = p * 2;
    int e = (int)(base % Ed);
    long row = base / Ed;
    int t = (int)(row % Tl);
    int d = e % KDd;
    float s0 = sinp[t * KDd + d],     c0 = cosp[t * KDd + d];
    float s1 = sinp[t * KDd + d + 1], c1 = cosp[t * KDd + d + 1];
    float q0 = q[base], q1 = q[base + 1];
    q[base]     = q0 * c0 - q1 * s0;
    q[base + 1] = q1 * c1 + q0 * s1;
}

// ---------------- kv per chunk: kv[k,e] = sum_c kr[c,k]*v[c,e]*vid[h,c] ----------------
__global__ __launch_bounds__(256) void kv_kernel(const float* __restrict__ k,
                                                 const float* __restrict__ v,
                                                 const float* __restrict__ vid,
                                                 float* __restrict__ kv)
{
    __shared__ float kr_s[32 * 64];
    __shared__ float v_s[32 * 128];
    __shared__ float vid_s[32];
    int bx = blockIdx.x;
    int h = bx % Hd;
    int n = (bx / Hd) % NCd;
    int b = bx / (Hd * NCd);
    int tid = threadIdx.x;
    int tx = tid % 32, ty = tid / 32;
    float acc[8][4];
#pragma unroll
    for (int i = 0; i < 8; i++)
#pragma unroll
        for (int j = 0; j < 4; j++) acc[i][j] = 0.f;

    long row0 = (long)b * Tl + n * Cd;
    for (int c0 = 0; c0 < Cd; c0 += 32) {
        {
            int col = (tid % 16) * 4, r = tid / 16;
#pragma unroll
            for (int i = 0; i < 2; i++)
                *(float4*)&kr_s[(r + i * 16) * 64 + col] =
                    *(const float4*)&k[(row0 + c0 + r + i * 16) * Ed + h * KDd + col];
            int col2 = (tid % 32) * 4, r2 = tid / 32;
#pragma unroll
            for (int i = 0; i < 4; i++)
                *(float4*)&v_s[(r2 + i * 8) * 128 + col2] =
                    *(const float4*)&v[(row0 + c0 + r2 + i * 8) * E2d + h * HDd + col2];
            if (tid < 32) vid_s[tid] = vid[h * Cd + c0 + tid];
        }
        __syncthreads();
#pragma unroll 4
        for (int c = 0; c < 32; c++) {
            float vv = vid_s[c];
            float4 v4 = *(float4*)&v_s[c * 128 + tx * 4];
            float rb[4] = {v4.x * vv, v4.y * vv, v4.z * vv, v4.w * vv};
#pragma unroll
            for (int i = 0; i < 8; i++) {
                float ka = kr_s[c * 64 + ty * 8 + i];
#pragma unroll
                for (int j = 0; j < 4; j++) acc[i][j] += ka * rb[j];
            }
        }
        __syncthreads();
    }
    float* outp = kv + (size_t)bx * (KDd * HDd);
#pragma unroll
    for (int i = 0; i < 8; i++) {
        float4 o = {acc[i][0], acc[i][1], acc[i][2], acc[i][3]};
        *(float4*)&outp[(ty * 8 + i) * 128 + tx * 4] = o;
    }
}

// ---------------- scan: per-element recurrence (raw state) ----------------
__global__ void scan_kernel(const float* __restrict__ kv,
                            const float* __restrict__ cd,
                            float* __restrict__ state)
{
    int idx = blockIdx.x * 256 + threadIdx.x;
    int eidx = idx % (KDd * HDd);
    int bh = idx / (KDd * HDd);
    int h = bh % Hd, b = bh / Hd;
    float c = cd[h];
    float s = 0.f;
    for (int n = 0; n < NCd; n++) {
        size_t off = ((size_t)((b * NCd + n) * Hd + h)) * (KDd * HDd) + eidx;
        state[off] = s;
        s = s * c + kv[off];
    }
}

// ---------------- cross_scale: clip(max_e sum_k |state|, 1) ----------------
__global__ void cscale_kernel(const float* __restrict__ state, float* __restrict__ cs)
{
    int bx = blockIdx.x;
    int e = threadIdx.x;
    const float* sp = state + (size_t)bx * (KDd * HDd);
    float s = 0.f;
#pragma unroll 8
    for (int k2 = 0; k2 < KDd; k2++) s += fabsf(sp[k2 * HDd + e]);
#pragma unroll
    for (int o = 16; o > 0; o >>= 1) s = fmaxf(s, __shfl_xor_sync(0xffffffff, s, o));
    __shared__ float wmax[4];
    if ((e & 31) == 0) wmax[e >> 5] = s;
    __syncthreads();
    if (e == 0) {
        float m = fmaxf(fmaxf(wmax[0], wmax[1]), fmaxf(wmax[2], wmax[3]));
        cs[bx] = fmaxf(m, 1.0f);
    }
}

// ---------------- fused attention per (b,n,h,c-slab of 64 rows) ----------------
__global__ __launch_bounds__(256) void attn_kernel(
    const float* __restrict__ q, const float* __restrict__ k,
    const float* __restrict__ v, const float* __restrict__ g,
    const float* __restrict__ state, const float* __restrict__ cs,
    const float* __restrict__ mask, const float* __restrict__ qid,
    float* __restrict__ act)
{
    extern __shared__ float sm[];
    float* qrT      = sm;
    float* krT      = qrT + 64 * 65;
    float* qk_s     = krT + 64 * 257;
    float* v_s      = qk_s + 64 * 257;
    float* iscale_s = v_s + 64 * 128;
    float* qid_s    = iscale_s + 64;

    int bx = blockIdx.x;
    int cb = bx % 4;
    int h  = (bx / 4) % Hd;
    int n  = (bx / (4 * Hd)) % NCd;
    int b  = bx / (4 * Hd * NCd);
    int tid = threadIdx.x;
    int tx = tid % 16, ty = tid / 16;
    long row0 = (long)b * Tl + n * Cd;

    {
        int kg = (tid % 16) * 4;
        int cr = tid / 16;
#pragma unroll
        for (int p = 0; p < 4; p++) {
            int c = cr + p * 16;
            float4 a = *(const float4*)&q[(row0 + cb * 64 + c) * Ed + h * KDd + kg];
            qrT[(kg + 0) * 65 + c] = a.x;
            qrT[(kg + 1) * 65 + c] = a.y;
            qrT[(kg + 2) * 65 + c] = a.z;
            qrT[(kg + 3) * 65 + c] = a.w;
        }
#pragma unroll
        for (int p = 0; p < 16; p++) {
            int d = cr + p * 16;
            float4 a = *(const float4*)&k[(row0 + d) * Ed + h * KDd + kg];
            krT[(kg + 0) * 257 + d] = a.x;
            krT[(kg + 1) * 257 + d] = a.y;
            krT[(kg + 2) * 257 + d] = a.z;
            krT[(kg + 3) * 257 + d] = a.w;
        }
        if (tid < 64) qid_s[tid] = qid[h * Cd + cb * 64 + tid];
    }
    __syncthreads();

    float acc[4][16];
#pragma unroll
    for (int i = 0; i < 4; i++)
#pragma unroll
        for (int j = 0; j < 16; j++) acc[i][j] = 0.f;

#pragma unroll 4
    for (int kk = 0; kk < 64; kk++) {
        float ra[4], rb[16];
#pragma unroll
        for (int i = 0; i < 4; i++) ra[i] = qrT[kk * 65 + i * 16 + ty];
#pragma unroll
        for (int j = 0; j < 16; j++) rb[j] = krT[kk * 257 + j * 16 + tx];
#pragma unroll
        for (int i = 0; i < 4; i++)
#pragma unroll
            for (int j = 0; j < 16; j++) acc[i][j] += ra[i] * rb[j];
    }

    const float* mrow = mask + ((size_t)h * Cd + cb * 64) * Cd;
    float rs[4] = {0.f, 0.f, 0.f, 0.f};
#pragma unroll
    for (int i = 0; i < 4; i++) {
        int c = i * 16 + ty;
#pragma unroll
        for (int j = 0; j < 16; j++) {
            int d = j * 16 + tx;
            acc[i][j] *= mrow[c * Cd + d];
            rs[i] += fabsf(acc[i][j]);
        }
    }
#pragma unroll
    for (int o = 1; o < 16; o <<= 1)
#pragma unroll
        for (int i = 0; i < 4; i++) rs[i] += __shfl_xor_sync(0xffffffff, rs[i], o);
    if (tx == 0)
#pragma unroll
        for (int i = 0; i < 4; i++) iscale_s[i * 16 + ty] = fmaxf(rs[i], 1.0f);
#pragma unroll
    for (int i = 0; i < 4; i++)
#pragma unroll
        for (int j = 0; j < 16; j++)
            qk_s[(i * 16 + ty) * 257 + j * 16 + tx] = acc[i][j];
    __syncthreads();

    float acc2[4][8];
#pragma unroll
    for (int i = 0; i < 4; i++)
#pragma unroll
        for (int j = 0; j < 8; j++) acc2[i][j] = 0.f;

    for (int dc = 0; dc < 4; dc++) {
        {
            int col = (tid % 32) * 4, r = tid / 32;
#pragma unroll
            for (int p = 0; p < 8; p++)
                *(float4*)&v_s[(r + p * 8) * 128 + col] =
                    *(const float4*)&v[(row0 + dc * 64 + r + p * 8) * E2d + h * HDd + col];
        }
        __syncthreads();
#pragma unroll 4
        for (int dd = 0; dd < 64; dd++) {
            int d = dc * 64 + dd;
            float ra[4], rb[8];
#pragma unroll
            for (int i = 0; i < 4; i++) ra[i] = qk_s[(i * 16 + ty) * 257 + d];
#pragma unroll
            for (int j = 0; j < 8; j++) rb[j] = v_s[dd * 128 + j * 16 + tx];
#pragma unroll
            for (int i = 0; i < 4; i++)
#pragma unroll
                for (int j = 0; j < 8; j++) acc2[i][j] += ra[i] * rb[j];
        }
        __syncthreads();
    }

    {
        const float* sp = state + ((size_t)((b * NCd + n) * Hd + h)) * (KDd * HDd);
        int col = (tid % 32) * 4, r = tid / 32;
#pragma unroll
        for (int p = 0; p < 8; p++)
            *(float4*)&v_s[(r + p * 8) * 128 + col] =
                *(const float4*)&sp[(r + p * 8) * 128 + col];
    }
    __syncthreads();
    float acc3[4][8];
#pragma unroll
    for (int i = 0; i < 4; i++)
#pragma unroll
        for (int j = 0; j < 8; j++) acc3[i][j] = 0.f;
#pragma unroll 4
    for (int kk = 0; kk < 64; kk++) {
        float ra[4], rb[8];
#pragma unroll
        for (int i = 0; i < 4; i++) ra[i] = qrT[kk * 65 + i * 16 + ty];
#pragma unroll
        for (int j = 0; j < 8; j++) rb[j] = v_s[kk * 128 + j * 16 + tx];
#pragma unroll
        for (int i = 0; i < 4; i++)
#pragma unroll
            for (int j = 0; j < 8; j++) acc3[i][j] += ra[i] * rb[j];
    }

    float csc = cs[(b * NCd + n) * Hd + h];

#pragma unroll
    for (int i = 0; i < 4; i++) {
        int c = i * 16 + ty;
        float qd = qid_s[c];
        float alls = fmaxf(iscale_s[c], csc);
        float inv = 1.0f / alls;
        float val[8];
        float ss = 0.f;
#pragma unroll
        for (int j = 0; j < 8; j++) {
            val[j] = (acc2[i][j] + qd * acc3[i][j]) * inv;
            ss += val[j] * val[j];
        }
#pragma unroll
        for (int o = 1; o < 16; o <<= 1) ss += __shfl_xor_sync(0xffffffff, ss, o);
        float rnorm = rsqrtf(ss * (1.0f / 128.0f) + 1e-6f);
        long row = row0 + cb * 64 + c;
#pragma unroll
        for (int j = 0; j < 8; j++) {
            int e = j * 16 + tx;
            float gv = g[row * E2d + h * HDd + e];
            float sig = 1.0f / (1.0f + expf(-gv));
            act[row * E2d + h * HDd + e] = to_tf32(val[j] * rnorm * gv * sig);
        }
    }
}

// ---------------- host launch ----------------
extern "C" void kernel_launch(void* const* d_in, const int* in_sizes, int n_in,
                              void* d_out, int out_size)
{
    const float* x    = (const float*)d_in[0];
    const float* sinp = (const float*)d_in[1];
    const float* cosp = (const float*)d_in[2];
    const float* mask = (const float*)d_in[3];
    const float* cdec = (const float*)d_in[4];
    const float* qid  = (const float*)d_in[5];
    const float* vid  = (const float*)d_in[6];
    const float* Wq   = (const float*)d_in[7];
    const float* Wk   = (const float*)d_in[8];
    const float* Wv   = (const float*)d_in[9];
    const float* Wg   = (const float*)d_in[10];
    const float* Wo   = (const float*)d_in[11];
    float* out = (float*)d_out;

    float *p_q, *p_k, *p_v, *p_g, *p_act, *p_xr, *p_kv, *p_state, *p_cs, *p_wt;
    cudaGetSymbolAddress((void**)&p_q, g_q);
    cudaGetSymbolAddress((void**)&p_k, g_k);
    cudaGetSymbolAddress((void**)&p_v, g_v);
    cudaGetSymbolAddress((void**)&p_g, g_g);
    cudaGetSymbolAddress((void**)&p_act, g_act);
    cudaGetSymbolAddress((void**)&p_xr, g_xr);
    cudaGetSymbolAddress((void**)&p_kv, g_kv);
    cudaGetSymbolAddress((void**)&p_state, g_state);
    cudaGetSymbolAddress((void**)&p_cs, g_cscale);
    cudaGetSymbolAddress((void**)&p_wt, g_wt);

    float* wtq = p_wt;                 // [512,512]
    float* wtk = p_wt + 262144;        // [512,512]
    float* wtv = p_wt + 524288;        // [1024,512]
    float* wtg = p_wt + 1048576;       // [1024,512]
    float* wto = p_wt + 1572864;       // [512,1024]

    const int smem_attn = (64 * 65 + 64 * 257 + 64 * 257 + 64 * 128 + 128) * 4;
    cudaFuncSetAttribute(attn_kernel, cudaFuncAttributeMaxDynamicSharedMemorySize, smem_attn);
    cudaFuncSetAttribute(mma_gemm, cudaFuncAttributeMaxDynamicSharedMemorySize, GEMM_SMEM);

    // pre-round x; transpose+round weights (fold 0.125 into Wk)
    round_kernel<<<(Mtot * Ed / 4) / 256, 256>>>(x, p_xr);
    transpose_kernel<<<dim3(16, 16), dim3(32, 8)>>>(Wq, wtq, Ed, Ed, 1.0f);
    transpose_kernel<<<dim3(16, 16), dim3(32, 8)>>>(Wk, wtk, Ed, Ed, 0.125f);
    transpose_kernel<<<dim3(32, 16), dim3(32, 8)>>>(Wv, wtv, Ed, E2d, 1.0f);
    transpose_kernel<<<dim3(32, 16), dim3(32, 8)>>>(Wg, wtg, Ed, E2d, 1.0f);
    transpose_kernel<<<dim3(16, 32), dim3(32, 8)>>>(Wo, wto, E2d, Ed, 1.0f);

    // projections on tensor cores (pipelined tf32 mma.sync)
    mma_gemm<<<dim3(4, 256), 256, GEMM_SMEM>>>(p_xr, wtq, p_q, Mtot, Ed, Ed);
    mma_gemm<<<dim3(4, 256), 256, GEMM_SMEM>>>(p_xr, wtk, p_k, Mtot, Ed, Ed);
    mma_gemm<<<dim3(8, 256), 256, GEMM_SMEM>>>(p_xr, wtv, p_v, Mtot, E2d, Ed);
    mma_gemm<<<dim3(8, 256), 256, GEMM_SMEM>>>(p_xr, wtg, p_g, Mtot, E2d, Ed);

    // rotary on q and k
    int rot_blocks = (Mtot * Ed / 2) / 256;
    rotary_kernel<<<rot_blocks, 256>>>(p_q, sinp, cosp);
    rotary_kernel<<<rot_blocks, 256>>>(p_k, sinp, cosp);

    // per-chunk kv, scan, cross scale
    kv_kernel<<<Bz * NCd * Hd, 256>>>(p_k, p_v, vid, p_kv);
    scan_kernel<<<(Bz * Hd * KDd * HDd) / 256, 256>>>(p_kv, cdec, p_state);
    cscale_kernel<<<Bz * NCd * Hd, 128>>>(p_state, p_cs);

    // fused attention + combine + rms + silu (act written tf32-rounded)
    attn_kernel<<<Bz * NCd * Hd * 4, 256, smem_attn>>>(
        p_q, p_k, p_v, p_g, p_state, p_cs, mask, qid, p_act);

    // output projection
    mma_gemm<<<dim3(4, 256), 256, GEMM_SMEM>>>(p_act, wto, out, Mtot, Ed, E2d);
}

// round 5
// speedup vs baseline: 3.5932x; 1.7824x over previous
#include <cuda_runtime.h>
#include <math.h>
#include <stdint.h>

// Dims (fixed for this problem)
#define Bz    4
#define Tl    8192
#define Ed    512
#define Hd    8
#define KDd   64
#define HDd   128
#define Cd    256
#define NCd   32
#define E2d   1024
#define Mtot  32768   // B*T

// ---------------- scratch (device globals; no runtime alloc) ----------------
__device__ float g_q[(size_t)Mtot * Ed];
__device__ float g_k[(size_t)Mtot * Ed];
__device__ float g_v[(size_t)Mtot * E2d];
__device__ float g_g[(size_t)Mtot * E2d];
__device__ float g_act[(size_t)Mtot * E2d];
__device__ float g_xr[(size_t)Mtot * Ed];     // tf32-rounded x
__device__ float g_kv[(size_t)Bz * NCd * Hd * KDd * HDd];
__device__ float g_state[(size_t)Bz * NCd * Hd * KDd * HDd];
__device__ float g_cscale[Bz * NCd * Hd];
__device__ float g_wt[2097152];   // transposed+rounded weights

__device__ __forceinline__ uint32_t smem_u32(const void* p) {
    uint32_t a;
    asm("{ .reg .u64 t; cvta.to.shared.u64 t, %1; cvt.u32.u64 %0, t; }"
        : "=r"(a) : "l"(p));
    return a;
}
__device__ __forceinline__ float to_tf32(float x) {
    uint32_t r;
    asm("cvt.rna.tf32.f32 %0, %1;" : "=r"(r) : "f"(x));
    return __uint_as_float(r);
}

#define LDSM4(r0, r1, r2, r3, a)                                               \
    asm volatile("ldmatrix.sync.aligned.m8n8.x4.shared.b16 {%0,%1,%2,%3}, [%4];" \
                 : "=r"(r0), "=r"(r1), "=r"(r2), "=r"(r3) : "r"(a))

#define MMA_TF32(c, a, b0, b1)                                                 \
    asm volatile("mma.sync.aligned.m16n8k8.row.col.f32.tf32.tf32.f32 "         \
                 "{%0,%1,%2,%3},{%4,%5,%6,%7},{%8,%9},{%0,%1,%2,%3};"          \
                 : "+f"((c)[0]), "+f"((c)[1]), "+f"((c)[2]), "+f"((c)[3])      \
                 : "r"((a)[0]), "r"((a)[1]), "r"((a)[2]), "r"((a)[3]),         \
                   "r"(b0), "r"(b1))

#define CP_ASYNC16(dst, src)                                                   \
    asm volatile("cp.async.cg.shared.global [%0], [%1], 16;"                   \
                 :: "r"(dst), "l"(src))
#define CP_COMMIT asm volatile("cp.async.commit_group;" ::: "memory")
#define CP_WAIT(n) asm volatile("cp.async.wait_group %0;" :: "n"(n) : "memory")

// ---------------- tf32 pre-round of x ----------------
__global__ void round_kernel(const float* __restrict__ in, float* __restrict__ out)
{
    int i = blockIdx.x * 256 + threadIdx.x;
    float4 v = ((const float4*)in)[i];
    v.x = to_tf32(v.x); v.y = to_tf32(v.y); v.z = to_tf32(v.z); v.w = to_tf32(v.w);
    ((float4*)out)[i] = v;
}

// ---------------- weight transpose (+scale+round): Wt[N,K] = tf32(W[K,N]^T * s) ----
__global__ void transpose_kernel(const float* __restrict__ W, float* __restrict__ Wt,
                                 int K, int N, float scale)
{
    __shared__ float t[32][33];
    int n0 = blockIdx.x * 32, k0 = blockIdx.y * 32;
    int tx = threadIdx.x, ty = threadIdx.y;  // 32 x 8
#pragma unroll
    for (int i = 0; i < 4; i++)
        t[ty + i * 8][tx] = W[(size_t)(k0 + ty + i * 8) * N + n0 + tx];
    __syncthreads();
#pragma unroll
    for (int i = 0; i < 4; i++)
        Wt[(size_t)(n0 + ty + i * 8) * K + k0 + tx] = to_tf32(t[tx][ty + i * 8] * scale);
}

// ---------------- pipelined tf32 tensor-core GEMM: C = A[M,K] @ Bt[N,K]^T ----------
#define STAGES 3
#define STG_BYTES 16384
#define GEMM_SMEM (STAGES * 2 * STG_BYTES)
__global__ __launch_bounds__(256) void mma_gemm(
    const float* __restrict__ A, const float* __restrict__ Bt,
    float* __restrict__ C, int M, int N, int K)
{
    extern __shared__ float smemf[];
    uint32_t sbase = smem_u32(smemf);
    const uint32_t BOFF = STAGES * STG_BYTES;

    int tid = threadIdx.x;
    int lane = tid & 31;
    int w = tid >> 5;
    int wm = w & 1;
    int wn = w >> 1;
    int rowBlk = blockIdx.y * 128, colBlk = blockIdx.x * 128;

    float acc[4][4][4];
#pragma unroll
    for (int mi = 0; mi < 4; mi++)
#pragma unroll
        for (int ni = 0; ni < 4; ni++)
#pragma unroll
            for (int r = 0; r < 4; r++) acc[mi][ni][r] = 0.f;

    int ldrow = tid >> 3;
    int kq = (tid & 7) * 4;
    const int L = K >> 5;

    int rowA0 = wm * 64 + (lane & 15);
    uint32_t offA = rowA0 * 128 + (((lane >> 4) * 16) ^ ((rowA0 & 7) << 4));
    int nB0 = wn * 32 + (lane & 7) + ((lane & 16) ? 8 : 0);
    uint32_t offB = nB0 * 128 + ((((lane >> 3) & 1) * 16) ^ ((nB0 & 7) << 4));

#define PREFETCH(kt, st) do {                                                  \
    int _k0 = (kt) * 32;                                                       \
    uint32_t _b = sbase + (st) * STG_BYTES;                                    \
    _Pragma("unroll")                                                          \
    for (int p = 0; p < 4; p++) {                                              \
        int row = p * 32 + ldrow;                                              \
        uint32_t sw = row * 128 + (((uint32_t)(kq * 4)) ^ ((row & 7) << 4));   \
        CP_ASYNC16(_b + sw, &A[(size_t)(rowBlk + row) * K + _k0 + kq]);        \
        CP_ASYNC16(_b + BOFF + sw, &Bt[(size_t)(colBlk + row) * K + _k0 + kq]);\
    }                                                                          \
    CP_COMMIT;                                                                 \
} while (0)

    PREFETCH(0, 0);
    PREFETCH(1, 1);

    for (int kt = 0; kt < L; kt++) {
        CP_WAIT(STAGES - 2);
        __syncthreads();
        int nf = kt + STAGES - 1;
        if (nf < L) PREFETCH(nf, nf % STAGES);

        int st = kt % STAGES;
        uint32_t baA = sbase + st * STG_BYTES + offA;
        uint32_t baB = sbase + st * STG_BYTES + BOFF + offB;
#pragma unroll
        for (int s = 0; s < 4; s++) {
            uint32_t af[4][4];
#pragma unroll
            for (int mi = 0; mi < 4; mi++)
                LDSM4(af[mi][0], af[mi][1], af[mi][2], af[mi][3],
                      (baA + mi * 2048) ^ (uint32_t)(s * 32));
            uint32_t bf[8];
            LDSM4(bf[0], bf[1], bf[2], bf[3], baB ^ (uint32_t)(s * 32));
            LDSM4(bf[4], bf[5], bf[6], bf[7], (baB + 2048) ^ (uint32_t)(s * 32));
#pragma unroll
            for (int mi = 0; mi < 4; mi++)
#pragma unroll
                for (int ni = 0; ni < 4; ni++)
                    MMA_TF32(acc[mi][ni], af[mi], bf[ni * 2], bf[ni * 2 + 1]);
        }
        __syncthreads();
    }

    int r0 = lane >> 2, cp = (lane & 3) * 2;
#pragma unroll
    for (int mi = 0; mi < 4; mi++) {
#pragma unroll
        for (int ni = 0; ni < 4; ni++) {
            size_t row = (size_t)(rowBlk + wm * 64 + mi * 16 + r0);
            int col = colBlk + wn * 32 + ni * 8 + cp;
            float2 o0 = {acc[mi][ni][0], acc[mi][ni][1]};
            float2 o1 = {acc[mi][ni][2], acc[mi][ni][3]};
            *(float2*)&C[row * N + col] = o0;
            *(float2*)&C[(row + 8) * N + col] = o1;
        }
    }
#undef PREFETCH
}

// ---------------- rotary (theta shift) in place ----------------
__global__ void rotary_kernel(float* __restrict__ q,
                              const float* __restrict__ sinp,
                              const float* __restrict__ cosp)
{
    long p = (long)blockIdx.x * 256 + threadIdx.x;
    long base = p * 2;
    int e = (int)(base % Ed);
    long row = base / Ed;
    int t = (int)(row % Tl);
    int d = e % KDd;
    float s0 = sinp[t * KDd + d],     c0 = cosp[t * KDd + d];
    float s1 = sinp[t * KDd + d + 1], c1 = cosp[t * KDd + d + 1];
    float q0 = q[base], q1 = q[base + 1];
    q[base]     = q0 * c0 - q1 * s0;
    q[base + 1] = q1 * c1 + q0 * s1;
}

// ---------------- kv per chunk ----------------
__global__ __launch_bounds__(256) void kv_kernel(const float* __restrict__ k,
                                                 const float* __restrict__ v,
                                                 const float* __restrict__ vid,
                                                 float* __restrict__ kv)
{
    __shared__ float kr_s[32 * 64];
    __shared__ float v_s[32 * 128];
    __shared__ float vid_s[32];
    int bx = blockIdx.x;
    int h = bx % Hd;
    int n = (bx / Hd) % NCd;
    int b = bx / (Hd * NCd);
    int tid = threadIdx.x;
    int tx = tid % 32, ty = tid / 32;
    float acc[8][4];
#pragma unroll
    for (int i = 0; i < 8; i++)
#pragma unroll
        for (int j = 0; j < 4; j++) acc[i][j] = 0.f;

    long row0 = (long)b * Tl + n * Cd;
    for (int c0 = 0; c0 < Cd; c0 += 32) {
        {
            int col = (tid % 16) * 4, r = tid / 16;
#pragma unroll
            for (int i = 0; i < 2; i++)
                *(float4*)&kr_s[(r + i * 16) * 64 + col] =
                    *(const float4*)&k[(row0 + c0 + r + i * 16) * Ed + h * KDd + col];
            int col2 = (tid % 32) * 4, r2 = tid / 32;
#pragma unroll
            for (int i = 0; i < 4; i++)
                *(float4*)&v_s[(r2 + i * 8) * 128 + col2] =
                    *(const float4*)&v[(row0 + c0 + r2 + i * 8) * E2d + h * HDd + col2];
            if (tid < 32) vid_s[tid] = vid[h * Cd + c0 + tid];
        }
        __syncthreads();
#pragma unroll 4
        for (int c = 0; c < 32; c++) {
            float vv = vid_s[c];
            float4 v4 = *(float4*)&v_s[c * 128 + tx * 4];
            float rb[4] = {v4.x * vv, v4.y * vv, v4.z * vv, v4.w * vv};
#pragma unroll
            for (int i = 0; i < 8; i++) {
                float ka = kr_s[c * 64 + ty * 8 + i];
#pragma unroll
                for (int j = 0; j < 4; j++) acc[i][j] += ka * rb[j];
            }
        }
        __syncthreads();
    }
    float* outp = kv + (size_t)bx * (KDd * HDd);
#pragma unroll
    for (int i = 0; i < 8; i++) {
        float4 o = {acc[i][0], acc[i][1], acc[i][2], acc[i][3]};
        *(float4*)&outp[(ty * 8 + i) * 128 + tx * 4] = o;
    }
}

// ---------------- scan ----------------
__global__ void scan_kernel(const float* __restrict__ kv,
                            const float* __restrict__ cd,
                            float* __restrict__ state)
{
    int idx = blockIdx.x * 256 + threadIdx.x;
    int eidx = idx % (KDd * HDd);
    int bh = idx / (KDd * HDd);
    int h = bh % Hd, b = bh / Hd;
    float c = cd[h];
    float s = 0.f;
    for (int n = 0; n < NCd; n++) {
        size_t off = ((size_t)((b * NCd + n) * Hd + h)) * (KDd * HDd) + eidx;
        state[off] = s;
        s = s * c + kv[off];
    }
}

// ---------------- cross_scale ----------------
__global__ void cscale_kernel(const float* __restrict__ state, float* __restrict__ cs)
{
    int bx = blockIdx.x;
    int e = threadIdx.x;
    const float* sp = state + (size_t)bx * (KDd * HDd);
    float s = 0.f;
#pragma unroll 8
    for (int k2 = 0; k2 < KDd; k2++) s += fabsf(sp[k2 * HDd + e]);
#pragma unroll
    for (int o = 16; o > 0; o >>= 1) s = fmaxf(s, __shfl_xor_sync(0xffffffff, s, o));
    __shared__ float wmax[4];
    if ((e & 31) == 0) wmax[e >> 5] = s;
    __syncthreads();
    if (e == 0) {
        float m = fmaxf(fmaxf(wmax[0], wmax[1]), fmaxf(wmax[2], wmax[3]));
        cs[bx] = fmaxf(m, 1.0f);
    }
}

// ---------------- tensor-core fused attention per (b,n,h,64-row slab) --------
// mma.sync tf32 for qk, qk@V (chunked over d), qr@state. Direct LDS fragment
// gathers; pads chosen for conflict-free access (68 for K-dim-64, 136 for 128-wide).
#define LDA 68
#define LDV 136
#define ATTN_SMEM ((3 * 64 * LDA + 64 * LDV + 128 + 128 + 64) * 4)
__global__ __launch_bounds__(256) void attn_kernel(
    const float* __restrict__ q, const float* __restrict__ k,
    const float* __restrict__ v, const float* __restrict__ g,
    const float* __restrict__ state, const float* __restrict__ cs,
    const float* __restrict__ mask, const float* __restrict__ qid,
    float* __restrict__ act)
{
    extern __shared__ float sm[];
    float* qr_s  = sm;                    // 64*68
    float* kr_s  = qr_s + 64 * LDA;       // 64*68
    float* qk_s  = kr_s + 64 * LDA;       // 64*68
    float* v_s   = qk_s + 64 * LDA;       // 64*136
    float* ipart = v_s + 64 * LDV;        // 2*64
    float* rpart = ipart + 128;           // 2*64
    float* qid_s = rpart + 128;           // 64

    int bx = blockIdx.x;
    int cb = bx % 4;
    int h  = (bx / 4) % Hd;
    int n  = (bx / (4 * Hd)) % NCd;
    int b  = bx / (4 * Hd * NCd);
    int tid = threadIdx.x;
    int lane = tid & 31;
    int w = tid >> 5;
    int wm = w >> 1;        // 0..3 -> 16-row group
    int wn = w & 1;         // 0..1 -> column half
    long row0 = (long)b * Tl + n * Cd;

    // load qr slab [64 x 64] row-major, tf32-rounded
    {
        int kg = (tid & 15) * 4;
        int cr = tid >> 4;
#pragma unroll
        for (int p = 0; p < 4; p++) {
            int row = cr + p * 16;
            float4 a = *(const float4*)&q[(row0 + cb * 64 + row) * Ed + h * KDd + kg];
            qr_s[row * LDA + kg + 0] = to_tf32(a.x);
            qr_s[row * LDA + kg + 1] = to_tf32(a.y);
            qr_s[row * LDA + kg + 2] = to_tf32(a.z);
            qr_s[row * LDA + kg + 3] = to_tf32(a.w);
        }
        if (tid < 64) qid_s[tid] = qid[h * Cd + cb * 64 + tid];
    }

    const float* mrow = mask + ((size_t)h * Cd + cb * 64) * Cd;
    int qrow = (lane >> 2);       // 0..7
    int qcol = (lane & 3);        // 0..3
    int clr = wm * 16 + qrow;     // local row (lo); +8 for hi

    float rs_lo = 0.f, rs_hi = 0.f;
    float acc2[8][4];
#pragma unroll
    for (int ni = 0; ni < 8; ni++)
#pragma unroll
        for (int j = 0; j < 4; j++) acc2[ni][j] = 0.f;

    for (int dc = 0; dc < 4; dc++) {
        __syncthreads();   // protect prior-iteration consumers of kr/v/qk
        // load kr chunk [64 x 64] and v chunk [64 x 128]
        {
            int kg = (tid & 15) * 4;
            int cr = tid >> 4;
#pragma unroll
            for (int p = 0; p < 4; p++) {
                int row = cr + p * 16;
                float4 a = *(const float4*)&k[(row0 + dc * 64 + row) * Ed + h * KDd + kg];
                kr_s[row * LDA + kg + 0] = to_tf32(a.x);
                kr_s[row * LDA + kg + 1] = to_tf32(a.y);
                kr_s[row * LDA + kg + 2] = to_tf32(a.z);
                kr_s[row * LDA + kg + 3] = to_tf32(a.w);
            }
            int col = (tid & 31) * 4;
            int r = tid >> 5;
#pragma unroll
            for (int p = 0; p < 8; p++) {
                int row = r + p * 8;
                float4 a = *(const float4*)&v[(row0 + dc * 64 + row) * E2d + h * HDd + col];
                v_s[row * LDV + col + 0] = to_tf32(a.x);
                v_s[row * LDV + col + 1] = to_tf32(a.y);
                v_s[row * LDV + col + 2] = to_tf32(a.z);
                v_s[row * LDV + col + 3] = to_tf32(a.w);
            }
        }
        __syncthreads();

        // qk chunk: [16 rows x 32 cols] per warp, K=64
        float acc1[4][4];
#pragma unroll
        for (int ni = 0; ni < 4; ni++)
#pragma unroll
            for (int j = 0; j < 4; j++) acc1[ni][j] = 0.f;
#pragma unroll
        for (int ks = 0; ks < 8; ks++) {
            uint32_t a[4];
            int ar = wm * 16 + qrow, ac = ks * 8 + qcol;
            a[0] = __float_as_uint(qr_s[ar * LDA + ac]);
            a[1] = __float_as_uint(qr_s[(ar + 8) * LDA + ac]);
            a[2] = __float_as_uint(qr_s[ar * LDA + ac + 4]);
            a[3] = __float_as_uint(qr_s[(ar + 8) * LDA + ac + 4]);
#pragma unroll
            for (int ni = 0; ni < 4; ni++) {
                int br = wn * 32 + ni * 8 + qrow;
                uint32_t b0 = __float_as_uint(kr_s[br * LDA + ks * 8 + qcol]);
                uint32_t b1 = __float_as_uint(kr_s[br * LDA + ks * 8 + qcol + 4]);
                MMA_TF32(acc1[ni], a, b0, b1);
            }
        }

        // mask, abs row-sum, stage masked qk (tf32) to smem
#pragma unroll
        for (int ni = 0; ni < 4; ni++) {
            int dl = wn * 32 + ni * 8 + 2 * qcol;
            int d = dc * 64 + dl;
            float2 mlo = *(const float2*)&mrow[(size_t)clr * Cd + d];
            float2 mhi = *(const float2*)&mrow[(size_t)(clr + 8) * Cd + d];
            acc1[ni][0] *= mlo.x; acc1[ni][1] *= mlo.y;
            acc1[ni][2] *= mhi.x; acc1[ni][3] *= mhi.y;
            rs_lo += fabsf(acc1[ni][0]) + fabsf(acc1[ni][1]);
            rs_hi += fabsf(acc1[ni][2]) + fabsf(acc1[ni][3]);
            float2 s0 = {to_tf32(acc1[ni][0]), to_tf32(acc1[ni][1])};
            float2 s1 = {to_tf32(acc1[ni][2]), to_tf32(acc1[ni][3])};
            *(float2*)&qk_s[clr * LDA + dl] = s0;
            *(float2*)&qk_s[(clr + 8) * LDA + dl] = s1;
        }
        __syncthreads();

        // PV: acc2 += qk_chunk[16x64] @ V_chunk[64x128-half]
#pragma unroll
        for (int ks = 0; ks < 8; ks++) {
            uint32_t a[4];
            int ar = wm * 16 + qrow, ac = ks * 8 + qcol;
            a[0] = __float_as_uint(qk_s[ar * LDA + ac]);
            a[1] = __float_as_uint(qk_s[(ar + 8) * LDA + ac]);
            a[2] = __float_as_uint(qk_s[ar * LDA + ac + 4]);
            a[3] = __float_as_uint(qk_s[(ar + 8) * LDA + ac + 4]);
#pragma unroll
            for (int ni = 0; ni < 8; ni++) {
                int bn = wn * 64 + ni * 8 + qrow;
                uint32_t b0 = __float_as_uint(v_s[(ks * 8 + qcol) * LDV + bn]);
                uint32_t b1 = __float_as_uint(v_s[(ks * 8 + qcol + 4) * LDV + bn]);
                MMA_TF32(acc2[ni], a, b0, b1);
            }
        }
    }

    // cross: load state [64 x 128] into v_s, then qr @ state
    __syncthreads();
    {
        const float* sp = state + ((size_t)((b * NCd + n) * Hd + h)) * (KDd * HDd);
        int col = (tid & 31) * 4;
        int r = tid >> 5;
#pragma unroll
        for (int p = 0; p < 8; p++) {
            int row = r + p * 8;
            float4 a = *(const float4*)&sp[row * HDd + col];
            v_s[row * LDV + col + 0] = to_tf32(a.x);
            v_s[row * LDV + col + 1] = to_tf32(a.y);
            v_s[row * LDV + col + 2] = to_tf32(a.z);
            v_s[row * LDV + col + 3] = to_tf32(a.w);
        }
    }
    __syncthreads();

    float acc3[8][4];
#pragma unroll
    for (int ni = 0; ni < 8; ni++)
#pragma unroll
        for (int j = 0; j < 4; j++) acc3[ni][j] = 0.f;
#pragma unroll
    for (int ks = 0; ks < 8; ks++) {
        uint32_t a[4];
        int ar = wm * 16 + qrow, ac = ks * 8 + qcol;
        a[0] = __float_as_uint(qr_s[ar * LDA + ac]);
        a[1] = __float_as_uint(qr_s[(ar + 8) * LDA + ac]);
        a[2] = __float_as_uint(qr_s[ar * LDA + ac + 4]);
        a[3] = __float_as_uint(qr_s[(ar + 8) * LDA + ac + 4]);
#pragma unroll
        for (int ni = 0; ni < 8; ni++) {
            int bn = wn * 64 + ni * 8 + qrow;
            uint32_t b0 = __float_as_uint(v_s[(ks * 8 + qcol) * LDV + bn]);
            uint32_t b1 = __float_as_uint(v_s[(ks * 8 + qcol + 4) * LDV + bn]);
            MMA_TF32(acc3[ni], a, b0, b1);
        }
    }

    // combine row-sums across quad + column halves
    rs_lo += __shfl_xor_sync(0xffffffff, rs_lo, 1);
    rs_lo += __shfl_xor_sync(0xffffffff, rs_lo, 2);
    rs_hi += __shfl_xor_sync(0xffffffff, rs_hi, 1);
    rs_hi += __shfl_xor_sync(0xffffffff, rs_hi, 2);
    if ((lane & 3) == 0) {
        ipart[wn * 64 + clr] = rs_lo;
        ipart[wn * 64 + clr + 8] = rs_hi;
    }
    __syncthreads();

    float csc = cs[(b * NCd + n) * Hd + h];
    float is_lo = fmaxf(1.f, ipart[clr] + ipart[64 + clr]);
    float is_hi = fmaxf(1.f, ipart[clr + 8] + ipart[64 + clr + 8]);
    float inv_lo = 1.f / fmaxf(is_lo, csc);
    float inv_hi = 1.f / fmaxf(is_hi, csc);
    float qd_lo = qid_s[clr], qd_hi = qid_s[clr + 8];

    float ss_lo = 0.f, ss_hi = 0.f;
#pragma unroll
    for (int ni = 0; ni < 8; ni++) {
        acc2[ni][0] = (acc2[ni][0] + qd_lo * acc3[ni][0]) * inv_lo;
        acc2[ni][1] = (acc2[ni][1] + qd_lo * acc3[ni][1]) * inv_lo;
        acc2[ni][2] = (acc2[ni][2] + qd_hi * acc3[ni][2]) * inv_hi;
        acc2[ni][3] = (acc2[ni][3] + qd_hi * acc3[ni][3]) * inv_hi;
        ss_lo += acc2[ni][0] * acc2[ni][0] + acc2[ni][1] * acc2[ni][1];
        ss_hi += acc2[ni][2] * acc2[ni][2] + acc2[ni][3] * acc2[ni][3];
    }
    ss_lo += __shfl_xor_sync(0xffffffff, ss_lo, 1);
    ss_lo += __shfl_xor_sync(0xffffffff, ss_lo, 2);
    ss_hi += __shfl_xor_sync(0xffffffff, ss_hi, 1);
    ss_hi += __shfl_xor_sync(0xffffffff, ss_hi, 2);
    if ((lane & 3) == 0) {
        rpart[wn * 64 + clr] = ss_lo;
        rpart[wn * 64 + clr + 8] = ss_hi;
    }
    __syncthreads();

    float rn_lo = rsqrtf((rpart[clr] + rpart[64 + clr]) * (1.f / 128.f) + 1e-6f);
    float rn_hi = rsqrtf((rpart[clr + 8] + rpart[64 + clr + 8]) * (1.f / 128.f) + 1e-6f);

    long grow_lo = row0 + cb * 64 + clr;
    long grow_hi = grow_lo + 8;
#pragma unroll
    for (int ni = 0; ni < 8; ni++) {
        int e = wn * 64 + ni * 8 + 2 * qcol;
        float2 gl = *(const float2*)&g[grow_lo * E2d + h * HDd + e];
        float2 gh = *(const float2*)&g[grow_hi * E2d + h * HDd + e];
        float o0 = acc2[ni][0] * rn_lo * gl.x / (1.f + expf(-gl.x));
        float o1 = acc2[ni][1] * rn_lo * gl.y / (1.f + expf(-gl.y));
        float o2 = acc2[ni][2] * rn_hi * gh.x / (1.f + expf(-gh.x));
        float o3 = acc2[ni][3] * rn_hi * gh.y / (1.f + expf(-gh.y));
        float2 w0 = {to_tf32(o0), to_tf32(o1)};
        float2 w1 = {to_tf32(o2), to_tf32(o3)};
        *(float2*)&act[grow_lo * E2d + h * HDd + e] = w0;
        *(float2*)&act[grow_hi * E2d + h * HDd + e] = w1;
    }
}

// ---------------- host launch ----------------
extern "C" void kernel_launch(void* const* d_in, const int* in_sizes, int n_in,
                              void* d_out, int out_size)
{
    const float* x    = (const float*)d_in[0];
    const float* sinp = (const float*)d_in[1];
    const float* cosp = (const float*)d_in[2];
    const float* mask = (const float*)d_in[3];
    const float* cdec = (const float*)d_in[4];
    const float* qid  = (const float*)d_in[5];
    const float* vid  = (const float*)d_in[6];
    const float* Wq   = (const float*)d_in[7];
    const float* Wk   = (const float*)d_in[8];
    const float* Wv   = (const float*)d_in[9];
    const float* Wg   = (const float*)d_in[10];
    const float* Wo   = (const float*)d_in[11];
    float* out = (float*)d_out;

    float *p_q, *p_k, *p_v, *p_g, *p_act, *p_xr, *p_kv, *p_state, *p_cs, *p_wt;
    cudaGetSymbolAddress((void**)&p_q, g_q);
    cudaGetSymbolAddress((void**)&p_k, g_k);
    cudaGetSymbolAddress((void**)&p_v, g_v);
    cudaGetSymbolAddress((void**)&p_g, g_g);
    cudaGetSymbolAddress((void**)&p_act, g_act);
    cudaGetSymbolAddress((void**)&p_xr, g_xr);
    cudaGetSymbolAddress((void**)&p_kv, g_kv);
    cudaGetSymbolAddress((void**)&p_state, g_state);
    cudaGetSymbolAddress((void**)&p_cs, g_cscale);
    cudaGetSymbolAddress((void**)&p_wt, g_wt);

    float* wtq = p_wt;
    float* wtk = p_wt + 262144;
    float* wtv = p_wt + 524288;
    float* wtg = p_wt + 1048576;
    float* wto = p_wt + 1572864;

    cudaFuncSetAttribute(attn_kernel, cudaFuncAttributeMaxDynamicSharedMemorySize, ATTN_SMEM);
    cudaFuncSetAttribute(mma_gemm, cudaFuncAttributeMaxDynamicSharedMemorySize, GEMM_SMEM);

    // pre-round x; transpose+round weights (fold 0.125 into Wk)
    round_kernel<<<(Mtot * Ed / 4) / 256, 256>>>(x, p_xr);
    transpose_kernel<<<dim3(16, 16), dim3(32, 8)>>>(Wq, wtq, Ed, Ed, 1.0f);
    transpose_kernel<<<dim3(16, 16), dim3(32, 8)>>>(Wk, wtk, Ed, Ed, 0.125f);
    transpose_kernel<<<dim3(32, 16), dim3(32, 8)>>>(Wv, wtv, Ed, E2d, 1.0f);
    transpose_kernel<<<dim3(32, 16), dim3(32, 8)>>>(Wg, wtg, Ed, E2d, 1.0f);
    transpose_kernel<<<dim3(16, 32), dim3(32, 8)>>>(Wo, wto, E2d, Ed, 1.0f);

    // projections on tensor cores
    mma_gemm<<<dim3(4, 256), 256, GEMM_SMEM>>>(p_xr, wtq, p_q, Mtot, Ed, Ed);
    mma_gemm<<<dim3(4, 256), 256, GEMM_SMEM>>>(p_xr, wtk, p_k, Mtot, Ed, Ed);
    mma_gemm<<<dim3(8, 256), 256, GEMM_SMEM>>>(p_xr, wtv, p_v, Mtot, E2d, Ed);
    mma_gemm<<<dim3(8, 256), 256, GEMM_SMEM>>>(p_xr, wtg, p_g, Mtot, E2d, Ed);

    // rotary on q and k
    int rot_blocks = (Mtot * Ed / 2) / 256;
    rotary_kernel<<<rot_blocks, 256>>>(p_q, sinp, cosp);
    rotary_kernel<<<rot_blocks, 256>>>(p_k, sinp, cosp);

    // per-chunk kv, scan, cross scale
    kv_kernel<<<Bz * NCd * Hd, 256>>>(p_k, p_v, vid, p_kv);
    scan_kernel<<<(Bz * Hd * KDd * HDd) / 256, 256>>>(p_kv, cdec, p_state);
    cscale_kernel<<<Bz * NCd * Hd, 128>>>(p_state, p_cs);

    // tensor-core fused attention + combine + rms + silu
    attn_kernel<<<Bz * NCd * Hd * 4, 256, ATTN_SMEM>>>(
        p_q, p_k, p_v, p_g, p_state, p_cs, mask, qid, p_act);

    // output projection
    mma_gemm<<<dim3(4, 256), 256, GEMM_SMEM>>>(p_act, wto, out, Mtot, Ed, E2d);
}

// round 6
// speedup vs baseline: 4.9277x; 1.3714x over previous
#include <cuda_runtime.h>
#include <cuda_fp16.h>
#include <math.h>
#include <stdint.h>

// Dims (fixed for this problem)
#define Bz    4
#define Tl    8192
#define Ed    512
#define Hd    8
#define KDd   64
#define HDd   128
#define Cd    256
#define NCd   32
#define E2d   1024
#define Mtot  32768   // B*T

// ---------------- scratch (device globals; no runtime alloc) ----------------
__device__ float  g_q[(size_t)Mtot * Ed];
__device__ float  g_k[(size_t)Mtot * Ed];
__device__ float  g_v[(size_t)Mtot * E2d];
__device__ float  g_g[(size_t)Mtot * E2d];
__device__ __half g_act[(size_t)Mtot * E2d];
__device__ __half g_xh[(size_t)Mtot * Ed];    // fp16 x
__device__ float  g_kv[(size_t)Bz * NCd * Hd * KDd * HDd];
__device__ float  g_state[(size_t)Bz * NCd * Hd * KDd * HDd];
__device__ float  g_cscale[Bz * NCd * Hd];
__device__ __half g_wt[2097152];   // transposed fp16 weights

__device__ __forceinline__ uint32_t smem_u32(const void* p) {
    uint32_t a;
    asm("{ .reg .u64 t; cvta.to.shared.u64 t, %1; cvt.u32.u64 %0, t; }"
        : "=r"(a) : "l"(p));
    return a;
}
__device__ __forceinline__ float to_tf32(float x) {
    uint32_t r;
    asm("cvt.rna.tf32.f32 %0, %1;" : "=r"(r) : "f"(x));
    return __uint_as_float(r);
}

#define LDSM4(r0, r1, r2, r3, a)                                               \
    asm volatile("ldmatrix.sync.aligned.m8n8.x4.shared.b16 {%0,%1,%2,%3}, [%4];" \
                 : "=r"(r0), "=r"(r1), "=r"(r2), "=r"(r3) : "r"(a))

#define MMA_TF32(c, a, b0, b1)                                                 \
    asm volatile("mma.sync.aligned.m16n8k8.row.col.f32.tf32.tf32.f32 "         \
                 "{%0,%1,%2,%3},{%4,%5,%6,%7},{%8,%9},{%0,%1,%2,%3};"          \
                 : "+f"((c)[0]), "+f"((c)[1]), "+f"((c)[2]), "+f"((c)[3])      \
                 : "r"((a)[0]), "r"((a)[1]), "r"((a)[2]), "r"((a)[3]),         \
                   "r"(b0), "r"(b1))

#define MMA_F16(c, a, b0, b1)                                                  \
    asm volatile("mma.sync.aligned.m16n8k16.row.col.f32.f16.f16.f32 "          \
                 "{%0,%1,%2,%3},{%4,%5,%6,%7},{%8,%9},{%0,%1,%2,%3};"          \
                 : "+f"((c)[0]), "+f"((c)[1]), "+f"((c)[2]), "+f"((c)[3])      \
                 : "r"((a)[0]), "r"((a)[1]), "r"((a)[2]), "r"((a)[3]),         \
                   "r"(b0), "r"(b1))

#define CP_ASYNC16(dst, src)                                                   \
    asm volatile("cp.async.cg.shared.global [%0], [%1], 16;"                   \
                 :: "r"(dst), "l"(src))
#define CP_COMMIT asm volatile("cp.async.commit_group;" ::: "memory")
#define CP_WAIT(n) asm volatile("cp.async.wait_group %0;" :: "n"(n) : "memory")

// ---------------- x -> fp16 ----------------
__global__ void tohalf_kernel(const float* __restrict__ in, __half* __restrict__ out)
{
    int i = blockIdx.x * 256 + threadIdx.x;
    float4 v = ((const float4*)in)[i];
    __half2 h0 = __floats2half2_rn(v.x, v.y);
    __half2 h1 = __floats2half2_rn(v.z, v.w);
    ((__half2*)out)[i * 2]     = h0;
    ((__half2*)out)[i * 2 + 1] = h1;
}

// ---------------- weight transpose (+scale) to fp16: Wt[N,K] = h(W[K,N]^T * s) ----
__global__ void transpose_kernel(const float* __restrict__ W, __half* __restrict__ Wt,
                                 int K, int N, float scale)
{
    __shared__ float t[32][33];
    int n0 = blockIdx.x * 32, k0 = blockIdx.y * 32;
    int tx = threadIdx.x, ty = threadIdx.y;  // 32 x 8
#pragma unroll
    for (int i = 0; i < 4; i++)
        t[ty + i * 8][tx] = W[(size_t)(k0 + ty + i * 8) * N + n0 + tx];
    __syncthreads();
#pragma unroll
    for (int i = 0; i < 4; i++)
        Wt[(size_t)(n0 + ty + i * 8) * K + k0 + tx] = __float2half_rn(t[tx][ty + i * 8] * scale);
}

// ---------------- pipelined fp16 tensor-core GEMM: C = A[M,K] @ Bt[N,K]^T ----------
// CTA tile 128x128, BK=64 (128B rows of fp16), 3-stage cp.async, 8 warps.
// ROT: fuse rotary (theta shift) into the epilogue (q/k projections).
#define STAGES 3
#define STG_BYTES 16384
#define GEMM_SMEM (STAGES * 2 * STG_BYTES)
template <bool ROT>
__global__ __launch_bounds__(256) void mma_gemm(
    const __half* __restrict__ A, const __half* __restrict__ Bt,
    float* __restrict__ C, int M, int N, int K,
    const float* __restrict__ sinp, const float* __restrict__ cosp)
{
    extern __shared__ float smemf[];
    uint32_t sbase = smem_u32(smemf);
    const uint32_t BOFF = STAGES * STG_BYTES;

    int tid = threadIdx.x;
    int lane = tid & 31;
    int w = tid >> 5;
    int wm = w & 1;
    int wn = w >> 1;
    int rowBlk = blockIdx.y * 128, colBlk = blockIdx.x * 128;

    float acc[4][4][4];
#pragma unroll
    for (int mi = 0; mi < 4; mi++)
#pragma unroll
        for (int ni = 0; ni < 4; ni++)
#pragma unroll
            for (int r = 0; r < 4; r++) acc[mi][ni][r] = 0.f;

    int ldrow = tid >> 3;          // 0..31
    int kh = (tid & 7) * 8;        // half offset within 64-half row (16B chunks)
    const int L = K >> 6;          // BK = 64 halves

    int rowA0 = wm * 64 + (lane & 15);
    uint32_t offA = rowA0 * 128 + (((lane >> 4) * 16) ^ ((rowA0 & 7) << 4));
    int nB0 = wn * 32 + (lane & 7) + ((lane & 16) ? 8 : 0);
    uint32_t offB = nB0 * 128 + ((((lane >> 3) & 1) * 16) ^ ((nB0 & 7) << 4));

#define PREFETCH(kt, st) do {                                                  \
    int _k0 = (kt) * 64;                                                       \
    uint32_t _b = sbase + (st) * STG_BYTES;                                    \
    _Pragma("unroll")                                                          \
    for (int p = 0; p < 4; p++) {                                              \
        int row = p * 32 + ldrow;                                              \
        uint32_t sw = row * 128 + (((uint32_t)(kh * 2)) ^ ((row & 7) << 4));   \
        CP_ASYNC16(_b + sw, &A[(size_t)(rowBlk + row) * K + _k0 + kh]);        \
        CP_ASYNC16(_b + BOFF + sw, &Bt[(size_t)(colBlk + row) * K + _k0 + kh]);\
    }                                                                          \
    CP_COMMIT;                                                                 \
} while (0)

    PREFETCH(0, 0);
    PREFETCH(1, 1);

    for (int kt = 0; kt < L; kt++) {
        CP_WAIT(STAGES - 2);
        __syncthreads();
        int nf = kt + STAGES - 1;
        if (nf < L) PREFETCH(nf, nf % STAGES);

        int st = kt % STAGES;
        uint32_t baA = sbase + st * STG_BYTES + offA;
        uint32_t baB = sbase + st * STG_BYTES + BOFF + offB;
#pragma unroll
        for (int s = 0; s < 4; s++) {      // 4 x k16 steps, 32B each
            uint32_t af[4][4];
#pragma unroll
            for (int mi = 0; mi < 4; mi++)
                LDSM4(af[mi][0], af[mi][1], af[mi][2], af[mi][3],
                      (baA + mi * 2048) ^ (uint32_t)(s * 32));
            uint32_t bf[8];
            LDSM4(bf[0], bf[1], bf[2], bf[3], baB ^ (uint32_t)(s * 32));
            LDSM4(bf[4], bf[5], bf[6], bf[7], (baB + 2048) ^ (uint32_t)(s * 32));
#pragma unroll
            for (int mi = 0; mi < 4; mi++)
#pragma unroll
                for (int ni = 0; ni < 4; ni++)
                    MMA_F16(acc[mi][ni], af[mi], bf[ni * 2], bf[ni * 2 + 1]);
        }
        // no trailing barrier needed: next iteration's leading barrier orders
        // stage reuse (3-stage ring; prefetch target never overlaps live reads)
    }

    int r0 = lane >> 2, cp = (lane & 3) * 2;
#pragma unroll
    for (int mi = 0; mi < 4; mi++) {
#pragma unroll
        for (int ni = 0; ni < 4; ni++) {
            size_t row = (size_t)(rowBlk + wm * 64 + mi * 16 + r0);
            int col = colBlk + wn * 32 + ni * 8 + cp;
            float o0 = acc[mi][ni][0], o1 = acc[mi][ni][1];
            float o2 = acc[mi][ni][2], o3 = acc[mi][ni][3];
            if (ROT) {
                int t = (int)(row % Tl);      // row+8 stays in same batch
                int d = col & 63;             // even
                float2 sl = *(const float2*)&sinp[t * KDd + d];
                float2 cl = *(const float2*)&cosp[t * KDd + d];
                float2 sh = *(const float2*)&sinp[(t + 8) * KDd + d];
                float2 ch = *(const float2*)&cosp[(t + 8) * KDd + d];
                float n0 = o0 * cl.x - o1 * sl.x;
                float n1 = o1 * cl.y + o0 * sl.y;
                float n2 = o2 * ch.x - o3 * sh.x;
                float n3 = o3 * ch.y + o2 * sh.y;
                o0 = n0; o1 = n1; o2 = n2; o3 = n3;
            }
            float2 w0 = {o0, o1};
            float2 w1 = {o2, o3};
            *(float2*)&C[row * N + col] = w0;
            *(float2*)&C[(row + 8) * N + col] = w1;
        }
    }
#undef PREFETCH
}

// ---------------- kv per chunk: kv[k,e] = sum_c kr[c,k]*v[c,e]*vid[h,c] ----------------
__global__ __launch_bounds__(256) void kv_kernel(const float* __restrict__ k,
                                                 const float* __restrict__ v,
                                                 const float* __restrict__ vid,
                                                 float* __restrict__ kv)
{
    __shared__ float kr_s[32 * 64];
    __shared__ float v_s[32 * 128];
    __shared__ float vid_s[32];
    int bx = blockIdx.x;
    int h = bx % Hd;
    int n = (bx / Hd) % NCd;
    int b = bx / (Hd * NCd);
    int tid = threadIdx.x;
    int tx = tid % 32, ty = tid / 32;
    float acc[8][4];
#pragma unroll
    for (int i = 0; i < 8; i++)
#pragma unroll
        for (int j = 0; j < 4; j++) acc[i][j] = 0.f;

    long row0 = (long)b * Tl + n * Cd;
    for (int c0 = 0; c0 < Cd; c0 += 32) {
        {
            int col = (tid % 16) * 4, r = tid / 16;
#pragma unroll
            for (int i = 0; i < 2; i++)
                *(float4*)&kr_s[(r + i * 16) * 64 + col] =
                    *(const float4*)&k[(row0 + c0 + r + i * 16) * Ed + h * KDd + col];
            int col2 = (tid % 32) * 4, r2 = tid / 32;
#pragma unroll
            for (int i = 0; i < 4; i++)
                *(float4*)&v_s[(r2 + i * 8) * 128 + col2] =
                    *(const float4*)&v[(row0 + c0 + r2 + i * 8) * E2d + h * HDd + col2];
            if (tid < 32) vid_s[tid] = vid[h * Cd + c0 + tid];
        }
        __syncthreads();
#pragma unroll 4
        for (int c = 0; c < 32; c++) {
            float vv = vid_s[c];
            float4 v4 = *(float4*)&v_s[c * 128 + tx * 4];
            float rb[4] = {v4.x * vv, v4.y * vv, v4.z * vv, v4.w * vv};
#pragma unroll
            for (int i = 0; i < 8; i++) {
                float ka = kr_s[c * 64 + ty * 8 + i];
#pragma unroll
                for (int j = 0; j < 4; j++) acc[i][j] += ka * rb[j];
            }
        }
        __syncthreads();
    }
    float* outp = kv + (size_t)bx * (KDd * HDd);
#pragma unroll
    for (int i = 0; i < 8; i++) {
        float4 o = {acc[i][0], acc[i][1], acc[i][2], acc[i][3]};
        *(float4*)&outp[(ty * 8 + i) * 128 + tx * 4] = o;
    }
}

// ---------------- scan (float4 per thread) ----------------
__global__ void scan_kernel(const float4* __restrict__ kv,
                            const float* __restrict__ cd,
                            float4* __restrict__ state)
{
    int idx = blockIdx.x * 256 + threadIdx.x;   // over B*H*(KD*HD/4)
    const int EQ = KDd * HDd / 4;
    int e4 = idx % EQ;
    int bh = idx / EQ;
    int h = bh % Hd, b = bh / Hd;
    float c = cd[h];
    float4 s = {0.f, 0.f, 0.f, 0.f};
    for (int n = 0; n < NCd; n++) {
        size_t off = ((size_t)((b * NCd + n) * Hd + h)) * EQ + e4;
        state[off] = s;
        float4 kvv = kv[off];
        s.x = s.x * c + kvv.x;
        s.y = s.y * c + kvv.y;
        s.z = s.z * c + kvv.z;
        s.w = s.w * c + kvv.w;
    }
}

// ---------------- cross_scale ----------------
__global__ void cscale_kernel(const float* __restrict__ state, float* __restrict__ cs)
{
    int bx = blockIdx.x;
    int e = threadIdx.x;
    const float* sp = state + (size_t)bx * (KDd * HDd);
    float s = 0.f;
#pragma unroll 8
    for (int k2 = 0; k2 < KDd; k2++) s += fabsf(sp[k2 * HDd + e]);
#pragma unroll
    for (int o = 16; o > 0; o >>= 1) s = fmaxf(s, __shfl_xor_sync(0xffffffff, s, o));
    __shared__ float wmax[4];
    if ((e & 31) == 0) wmax[e >> 5] = s;
    __syncthreads();
    if (e == 0) {
        float m = fmaxf(fmaxf(wmax[0], wmax[1]), fmaxf(wmax[2], wmax[3]));
        cs[bx] = fmaxf(m, 1.0f);
    }
}

// ---------------- tensor-core fused attention per (b,n,h,64-row slab) --------
#define LDA 68
#define LDV 136
#define ATTN_SMEM ((3 * 64 * LDA + 64 * LDV + 128 + 128 + 64) * 4)
__global__ __launch_bounds__(256) void attn_kernel(
    const float* __restrict__ q, const float* __restrict__ k,
    const float* __restrict__ v, const float* __restrict__ g,
    const float* __restrict__ state, const float* __restrict__ cs,
    const float* __restrict__ mask, const float* __restrict__ qid,
    __half* __restrict__ act)
{
    extern __shared__ float sm[];
    float* qr_s  = sm;                    // 64*68
    float* kr_s  = qr_s + 64 * LDA;       // 64*68
    float* qk_s  = kr_s + 64 * LDA;       // 64*68
    float* v_s   = qk_s + 64 * LDA;       // 64*136
    float* ipart = v_s + 64 * LDV;        // 2*64
    float* rpart = ipart + 128;           // 2*64
    float* qid_s = rpart + 128;           // 64

    int bx = blockIdx.x;
    int cb = bx % 4;
    int h  = (bx / 4) % Hd;
    int n  = (bx / (4 * Hd)) % NCd;
    int b  = bx / (4 * Hd * NCd);
    int tid = threadIdx.x;
    int lane = tid & 31;
    int w = tid >> 5;
    int wm = w >> 1;
    int wn = w & 1;
    long row0 = (long)b * Tl + n * Cd;

    {
        int kg = (tid & 15) * 4;
        int cr = tid >> 4;
#pragma unroll
        for (int p = 0; p < 4; p++) {
            int row = cr + p * 16;
            float4 a = *(const float4*)&q[(row0 + cb * 64 + row) * Ed + h * KDd + kg];
            qr_s[row * LDA + kg + 0] = to_tf32(a.x);
            qr_s[row * LDA + kg + 1] = to_tf32(a.y);
            qr_s[row * LDA + kg + 2] = to_tf32(a.z);
            qr_s[row * LDA + kg + 3] = to_tf32(a.w);
        }
        if (tid < 64) qid_s[tid] = qid[h * Cd + cb * 64 + tid];
    }

    const float* mrow = mask + ((size_t)h * Cd + cb * 64) * Cd;
    int qrow = (lane >> 2);
    int qcol = (lane & 3);
    int clr = wm * 16 + qrow;

    float rs_lo = 0.f, rs_hi = 0.f;
    float acc2[8][4];
#pragma unroll
    for (int ni = 0; ni < 8; ni++)
#pragma unroll
        for (int j = 0; j < 4; j++) acc2[ni][j] = 0.f;

    for (int dc = 0; dc < 4; dc++) {
        __syncthreads();
        {
            int kg = (tid & 15) * 4;
            int cr = tid >> 4;
#pragma unroll
            for (int p = 0; p < 4; p++) {
                int row = cr + p * 16;
                float4 a = *(const float4*)&k[(row0 + dc * 64 + row) * Ed + h * KDd + kg];
                kr_s[row * LDA + kg + 0] = to_tf32(a.x);
                kr_s[row * LDA + kg + 1] = to_tf32(a.y);
                kr_s[row * LDA + kg + 2] = to_tf32(a.z);
                kr_s[row * LDA + kg + 3] = to_tf32(a.w);
            }
            int col = (tid & 31) * 4;
            int r = tid >> 5;
#pragma unroll
            for (int p = 0; p < 8; p++) {
                int row = r + p * 8;
                float4 a = *(const float4*)&v[(row0 + dc * 64 + row) * E2d + h * HDd + col];
                v_s[row * LDV + col + 0] = to_tf32(a.x);
                v_s[row * LDV + col + 1] = to_tf32(a.y);
                v_s[row * LDV + col + 2] = to_tf32(a.z);
                v_s[row * LDV + col + 3] = to_tf32(a.w);
            }
        }
        __syncthreads();

        float acc1[4][4];
#pragma unroll
        for (int ni = 0; ni < 4; ni++)
#pragma unroll
            for (int j = 0; j < 4; j++) acc1[ni][j] = 0.f;
#pragma unroll
        for (int ks = 0; ks < 8; ks++) {
            uint32_t a[4];
            int ar = wm * 16 + qrow, ac = ks * 8 + qcol;
            a[0] = __float_as_uint(qr_s[ar * LDA + ac]);
            a[1] = __float_as_uint(qr_s[(ar + 8) * LDA + ac]);
            a[2] = __float_as_uint(qr_s[ar * LDA + ac + 4]);
            a[3] = __float_as_uint(qr_s[(ar + 8) * LDA + ac + 4]);
#pragma unroll
            for (int ni = 0; ni < 4; ni++) {
                int br = wn * 32 + ni * 8 + qrow;
                uint32_t b0 = __float_as_uint(kr_s[br * LDA + ks * 8 + qcol]);
                uint32_t b1 = __float_as_uint(kr_s[br * LDA + ks * 8 + qcol + 4]);
                MMA_TF32(acc1[ni], a, b0, b1);
            }
        }

#pragma unroll
        for (int ni = 0; ni < 4; ni++) {
            int dl = wn * 32 + ni * 8 + 2 * qcol;
            int d = dc * 64 + dl;
            float2 mlo = *(const float2*)&mrow[(size_t)clr * Cd + d];
            float2 mhi = *(const float2*)&mrow[(size_t)(clr + 8) * Cd + d];
            acc1[ni][0] *= mlo.x; acc1[ni][1] *= mlo.y;
            acc1[ni][2] *= mhi.x; acc1[ni][3] *= mhi.y;
            rs_lo += fabsf(acc1[ni][0]) + fabsf(acc1[ni][1]);
            rs_hi += fabsf(acc1[ni][2]) + fabsf(acc1[ni][3]);
            float2 s0 = {to_tf32(acc1[ni][0]), to_tf32(acc1[ni][1])};
            float2 s1 = {to_tf32(acc1[ni][2]), to_tf32(acc1[ni][3])};
            *(float2*)&qk_s[clr * LDA + dl] = s0;
            *(float2*)&qk_s[(clr + 8) * LDA + dl] = s1;
        }
        __syncthreads();

#pragma unroll
        for (int ks = 0; ks < 8; ks++) {
            uint32_t a[4];
            int ar = wm * 16 + qrow, ac = ks * 8 + qcol;
            a[0] = __float_as_uint(qk_s[ar * LDA + ac]);
            a[1] = __float_as_uint(qk_s[(ar + 8) * LDA + ac]);
            a[2] = __float_as_uint(qk_s[ar * LDA + ac + 4]);
            a[3] = __float_as_uint(qk_s[(ar + 8) * LDA + ac + 4]);
#pragma unroll
            for (int ni = 0; ni < 8; ni++) {
                int bn = wn * 64 + ni * 8 + qrow;
                uint32_t b0 = __float_as_uint(v_s[(ks * 8 + qcol) * LDV + bn]);
                uint32_t b1 = __float_as_uint(v_s[(ks * 8 + qcol + 4) * LDV + bn]);
                MMA_TF32(acc2[ni], a, b0, b1);
            }
        }
    }

    __syncthreads();
    {
        const float* sp = state + ((size_t)((b * NCd + n) * Hd + h)) * (KDd * HDd);
        int col = (tid & 31) * 4;
        int r = tid >> 5;
#pragma unroll
        for (int p = 0; p < 8; p++) {
            int row = r + p * 8;
            float4 a = *(const float4*)&sp[row * HDd + col];
            v_s[row * LDV + col + 0] = to_tf32(a.x);
            v_s[row * LDV + col + 1] = to_tf32(a.y);
            v_s[row * LDV + col + 2] = to_tf32(a.z);
            v_s[row * LDV + col + 3] = to_tf32(a.w);
        }
    }
    __syncthreads();

    float acc3[8][4];
#pragma unroll
    for (int ni = 0; ni < 8; ni++)
#pragma unroll
        for (int j = 0; j < 4; j++) acc3[ni][j] = 0.f;
#pragma unroll
    for (int ks = 0; ks < 8; ks++) {
        uint32_t a[4];
        int ar = wm * 16 + qrow, ac = ks * 8 + qcol;
        a[0] = __float_as_uint(qr_s[ar * LDA + ac]);
        a[1] = __float_as_uint(qr_s[(ar + 8) * LDA + ac]);
        a[2] = __float_as_uint(qr_s[ar * LDA + ac + 4]);
        a[3] = __float_as_uint(qr_s[(ar + 8) * LDA + ac + 4]);
#pragma unroll
        for (int ni = 0; ni < 8; ni++) {
            int bn = wn * 64 + ni * 8 + qrow;
            uint32_t b0 = __float_as_uint(v_s[(ks * 8 + qcol) * LDV + bn]);
            uint32_t b1 = __float_as_uint(v_s[(ks * 8 + qcol + 4) * LDV + bn]);
            MMA_TF32(acc3[ni], a, b0, b1);
        }
    }

    rs_lo += __shfl_xor_sync(0xffffffff, rs_lo, 1);
    rs_lo += __shfl_xor_sync(0xffffffff, rs_lo, 2);
    rs_hi += __shfl_xor_sync(0xffffffff, rs_hi, 1);
    rs_hi += __shfl_xor_sync(0xffffffff, rs_hi, 2);
    if ((lane & 3) == 0) {
        ipart[wn * 64 + clr] = rs_lo;
        ipart[wn * 64 + clr + 8] = rs_hi;
    }
    __syncthreads();

    float csc = cs[(b * NCd + n) * Hd + h];
    float is_lo = fmaxf(1.f, ipart[clr] + ipart[64 + clr]);
    float is_hi = fmaxf(1.f, ipart[clr + 8] + ipart[64 + clr + 8]);
    float inv_lo = 1.f / fmaxf(is_lo, csc);
    float inv_hi = 1.f / fmaxf(is_hi, csc);
    float qd_lo = qid_s[clr], qd_hi = qid_s[clr + 8];

    float ss_lo = 0.f, ss_hi = 0.f;
#pragma unroll
    for (int ni = 0; ni < 8; ni++) {
        acc2[ni][0] = (acc2[ni][0] + qd_lo * acc3[ni][0]) * inv_lo;
        acc2[ni][1] = (acc2[ni][1] + qd_lo * acc3[ni][1]) * inv_lo;
        acc2[ni][2] = (acc2[ni][2] + qd_hi * acc3[ni][2]) * inv_hi;
        acc2[ni][3] = (acc2[ni][3] + qd_hi * acc3[ni][3]) * inv_hi;
        ss_lo += acc2[ni][0] * acc2[ni][0] + acc2[ni][1] * acc2[ni][1];
        ss_hi += acc2[ni][2] * acc2[ni][2] + acc2[ni][3] * acc2[ni][3];
    }
    ss_lo += __shfl_xor_sync(0xffffffff, ss_lo, 1);
    ss_lo += __shfl_xor_sync(0xffffffff, ss_lo, 2);
    ss_hi += __shfl_xor_sync(0xffffffff, ss_hi, 1);
    ss_hi += __shfl_xor_sync(0xffffffff, ss_hi, 2);
    if ((lane & 3) == 0) {
        rpart[wn * 64 + clr] = ss_lo;
        rpart[wn * 64 + clr + 8] = ss_hi;
    }
    __syncthreads();

    float rn_lo = rsqrtf((rpart[clr] + rpart[64 + clr]) * (1.f / 128.f) + 1e-6f);
    float rn_hi = rsqrtf((rpart[clr + 8] + rpart[64 + clr + 8]) * (1.f / 128.f) + 1e-6f);

    long grow_lo = row0 + cb * 64 + clr;
    long grow_hi = grow_lo + 8;
#pragma unroll
    for (int ni = 0; ni < 8; ni++) {
        int e = wn * 64 + ni * 8 + 2 * qcol;
        float2 gl = *(const float2*)&g[grow_lo * E2d + h * HDd + e];
        float2 gh = *(const float2*)&g[grow_hi * E2d + h * HDd + e];
        float o0 = acc2[ni][0] * rn_lo * gl.x / (1.f + expf(-gl.x));
        float o1 = acc2[ni][1] * rn_lo * gl.y / (1.f + expf(-gl.y));
        float o2 = acc2[ni][2] * rn_hi * gh.x / (1.f + expf(-gh.x));
        float o3 = acc2[ni][3] * rn_hi * gh.y / (1.f + expf(-gh.y));
        *(__half2*)&act[grow_lo * E2d + h * HDd + e] = __floats2half2_rn(o0, o1);
        *(__half2*)&act[grow_hi * E2d + h * HDd + e] = __floats2half2_rn(o2, o3);
    }
}

// ---------------- host launch ----------------
extern "C" void kernel_launch(void* const* d_in, const int* in_sizes, int n_in,
                              void* d_out, int out_size)
{
    const float* x    = (const float*)d_in[0];
    const float* sinp = (const float*)d_in[1];
    const float* cosp = (const float*)d_in[2];
    const float* mask = (const float*)d_in[3];
    const float* cdec = (const float*)d_in[4];
    const float* qid  = (const float*)d_in[5];
    const float* vid  = (const float*)d_in[6];
    const float* Wq   = (const float*)d_in[7];
    const float* Wk   = (const float*)d_in[8];
    const float* Wv   = (const float*)d_in[9];
    const float* Wg   = (const float*)d_in[10];
    const float* Wo   = (const float*)d_in[11];
    float* out = (float*)d_out;

    float *p_q, *p_k, *p_v, *p_g, *p_kv, *p_state, *p_cs;
    __half *p_xh, *p_act, *p_wt;
    cudaGetSymbolAddress((void**)&p_q, g_q);
    cudaGetSymbolAddress((void**)&p_k, g_k);
    cudaGetSymbolAddress((void**)&p_v, g_v);
    cudaGetSymbolAddress((void**)&p_g, g_g);
    cudaGetSymbolAddress((void**)&p_act, g_act);
    cudaGetSymbolAddress((void**)&p_xh, g_xh);
    cudaGetSymbolAddress((void**)&p_kv, g_kv);
    cudaGetSymbolAddress((void**)&p_state, g_state);
    cudaGetSymbolAddress((void**)&p_cs, g_cscale);
    cudaGetSymbolAddress((void**)&p_wt, g_wt);

    __half* wtq = p_wt;
    __half* wtk = p_wt + 262144;
    __half* wtv = p_wt + 524288;
    __half* wtg = p_wt + 1048576;
    __half* wto = p_wt + 1572864;

    cudaFuncSetAttribute(attn_kernel, cudaFuncAttributeMaxDynamicSharedMemorySize, ATTN_SMEM);
    cudaFuncSetAttribute(mma_gemm<true>, cudaFuncAttributeMaxDynamicSharedMemorySize, GEMM_SMEM);
    cudaFuncSetAttribute(mma_gemm<false>, cudaFuncAttributeMaxDynamicSharedMemorySize, GEMM_SMEM);

    // x -> fp16; weights transpose -> fp16 (0.125 folded into Wk)
    tohalf_kernel<<<(Mtot * Ed / 4) / 256, 256>>>(x, p_xh);
    transpose_kernel<<<dim3(16, 16), dim3(32, 8)>>>(Wq, wtq, Ed, Ed, 1.0f);
    transpose_kernel<<<dim3(16, 16), dim3(32, 8)>>>(Wk, wtk, Ed, Ed, 0.125f);
    transpose_kernel<<<dim3(32, 16), dim3(32, 8)>>>(Wv, wtv, Ed, E2d, 1.0f);
    transpose_kernel<<<dim3(32, 16), dim3(32, 8)>>>(Wg, wtg, Ed, E2d, 1.0f);
    transpose_kernel<<<dim3(16, 32), dim3(32, 8)>>>(Wo, wto, E2d, Ed, 1.0f);

    // projections (fp16 tensor cores); rotary fused into q/k epilogues
    mma_gemm<true><<<dim3(4, 256), 256, GEMM_SMEM>>>(p_xh, wtq, p_q, Mtot, Ed, Ed, sinp, cosp);
    mma_gemm<true><<<dim3(4, 256), 256, GEMM_SMEM>>>(p_xh, wtk, p_k, Mtot, Ed, Ed, sinp, cosp);
    mma_gemm<false><<<dim3(8, 256), 256, GEMM_SMEM>>>(p_xh, wtv, p_v, Mtot, E2d, Ed, nullptr, nullptr);
    mma_gemm<false><<<dim3(8, 256), 256, GEMM_SMEM>>>(p_xh, wtg, p_g, Mtot, E2d, Ed, nullptr, nullptr);

    // per-chunk kv, scan, cross scale
    kv_kernel<<<Bz * NCd * Hd, 256>>>(p_k, p_v, vid, p_kv);
    scan_kernel<<<(Bz * Hd * KDd * HDd / 4) / 256, 256>>>(
        (const float4*)p_kv, cdec, (float4*)p_state);
    cscale_kernel<<<Bz * NCd * Hd, 128>>>(p_state, p_cs);

    // tensor-core fused attention + combine + rms + silu (act written fp16)
    attn_kernel<<<Bz * NCd * Hd * 4, 256, ATTN_SMEM>>>(
        p_q, p_k, p_v, p_g, p_state, p_cs, mask, qid, p_act);

    // output projection (fp16 A from attention epilogue)
    mma_gemm<false><<<dim3(4, 256), 256, GEMM_SMEM>>>(p_act, wto, out, Mtot, Ed, E2d, nullptr, nullptr);
}

// round 7
// speedup vs baseline: 5.6665x; 1.1499x over previous
#include <cuda_runtime.h>
#include <cuda_fp16.h>
#include <math.h>
#include <stdint.h>

// Dims (fixed for this problem)
#define Bz    4
#define Tl    8192
#define Ed    512
#define Hd    8
#define KDd   64
#define HDd   128
#define Cd    256
#define NCd   32
#define E2d   1024
#define Mtot  32768   // B*T

// ---------------- scratch (device globals; no runtime alloc) ----------------
__device__ __half g_q[(size_t)Mtot * Ed];
__device__ __half g_k[(size_t)Mtot * Ed];
__device__ __half g_v[(size_t)Mtot * E2d];
__device__ __half g_g[(size_t)Mtot * E2d];
__device__ __half g_act[(size_t)Mtot * E2d];
__device__ __half g_xh[(size_t)Mtot * Ed];    // fp16 x
__device__ float  g_kv[(size_t)Bz * NCd * Hd * KDd * HDd];
__device__ float  g_state[(size_t)Bz * NCd * Hd * KDd * HDd];
__device__ float  g_cscale[Bz * NCd * Hd];
__device__ __half g_wt[2097152];   // transposed fp16 weights

__device__ __forceinline__ uint32_t smem_u32(const void* p) {
    uint32_t a;
    asm("{ .reg .u64 t; cvta.to.shared.u64 t, %1; cvt.u32.u64 %0, t; }"
        : "=r"(a) : "l"(p));
    return a;
}

#define LDSM4(r0, r1, r2, r3, a)                                               \
    asm volatile("ldmatrix.sync.aligned.m8n8.x4.shared.b16 {%0,%1,%2,%3}, [%4];" \
                 : "=r"(r0), "=r"(r1), "=r"(r2), "=r"(r3) : "r"(a))

#define LDSM4T(r0, r1, r2, r3, a)                                              \
    asm volatile("ldmatrix.sync.aligned.m8n8.x4.trans.shared.b16 {%0,%1,%2,%3}, [%4];" \
                 : "=r"(r0), "=r"(r1), "=r"(r2), "=r"(r3) : "r"(a))

#define MMA_F16(c, a, b0, b1)                                                  \
    asm volatile("mma.sync.aligned.m16n8k16.row.col.f32.f16.f16.f32 "          \
                 "{%0,%1,%2,%3},{%4,%5,%6,%7},{%8,%9},{%0,%1,%2,%3};"          \
                 : "+f"((c)[0]), "+f"((c)[1]), "+f"((c)[2]), "+f"((c)[3])      \
                 : "r"((a)[0]), "r"((a)[1]), "r"((a)[2]), "r"((a)[3]),         \
                   "r"(b0), "r"(b1))

#define CP_ASYNC16(dst, src)                                                   \
    asm volatile("cp.async.cg.shared.global [%0], [%1], 16;"                   \
                 :: "r"(dst), "l"(src))
#define CP_COMMIT asm volatile("cp.async.commit_group;" ::: "memory")
#define CP_WAIT(n) asm volatile("cp.async.wait_group %0;" :: "n"(n) : "memory")

// ---------------- x -> fp16 ----------------
__global__ void tohalf_kernel(const float* __restrict__ in, __half* __restrict__ out)
{
    int i = blockIdx.x * 256 + threadIdx.x;
    float4 v = ((const float4*)in)[i];
    ((__half2*)out)[i * 2]     = __floats2half2_rn(v.x, v.y);
    ((__half2*)out)[i * 2 + 1] = __floats2half2_rn(v.z, v.w);
}

// ---------------- weight transpose (+scale) to fp16 ----------------
__global__ void transpose_kernel(const float* __restrict__ W, __half* __restrict__ Wt,
                                 int K, int N, float scale)
{
    __shared__ float t[32][33];
    int n0 = blockIdx.x * 32, k0 = blockIdx.y * 32;
    int tx = threadIdx.x, ty = threadIdx.y;  // 32 x 8
#pragma unroll
    for (int i = 0; i < 4; i++)
        t[ty + i * 8][tx] = W[(size_t)(k0 + ty + i * 8) * N + n0 + tx];
    __syncthreads();
#pragma unroll
    for (int i = 0; i < 4; i++)
        Wt[(size_t)(n0 + ty + i * 8) * K + k0 + tx] = __float2half_rn(t[tx][ty + i * 8] * scale);
}

// ---------------- pipelined fp16 tensor-core GEMM ----------------
// CTA tile 128x128, BK=64, 3-stage cp.async, 8 warps. ROT fuses rotary.
// TOHALF: write C as fp16; else fp32.
#define STAGES 3
#define STG_BYTES 16384
#define GEMM_SMEM (STAGES * 2 * STG_BYTES)
template <bool ROT, bool TOHALF>
__global__ __launch_bounds__(256) void mma_gemm(
    const __half* __restrict__ A, const __half* __restrict__ Bt,
    void* __restrict__ Cv, int M, int N, int K,
    const float* __restrict__ sinp, const float* __restrict__ cosp)
{
    extern __shared__ float smemf[];
    uint32_t sbase = smem_u32(smemf);
    const uint32_t BOFF = STAGES * STG_BYTES;

    int tid = threadIdx.x;
    int lane = tid & 31;
    int w = tid >> 5;
    int wm = w & 1;
    int wn = w >> 1;
    int rowBlk = blockIdx.y * 128, colBlk = blockIdx.x * 128;

    float acc[4][4][4];
#pragma unroll
    for (int mi = 0; mi < 4; mi++)
#pragma unroll
        for (int ni = 0; ni < 4; ni++)
#pragma unroll
            for (int r = 0; r < 4; r++) acc[mi][ni][r] = 0.f;

    int ldrow = tid >> 3;
    int kh = (tid & 7) * 8;
    const int L = K >> 6;

    int rowA0 = wm * 64 + (lane & 15);
    uint32_t offA = rowA0 * 128 + (((lane >> 4) * 16) ^ ((rowA0 & 7) << 4));
    int nB0 = wn * 32 + (lane & 7) + ((lane & 16) ? 8 : 0);
    uint32_t offB = nB0 * 128 + ((((lane >> 3) & 1) * 16) ^ ((nB0 & 7) << 4));

#define PREFETCH(kt, st) do {                                                  \
    int _k0 = (kt) * 64;                                                       \
    uint32_t _b = sbase + (st) * STG_BYTES;                                    \
    _Pragma("unroll")                                                          \
    for (int p = 0; p < 4; p++) {                                              \
        int row = p * 32 + ldrow;                                              \
        uint32_t sw = row * 128 + (((uint32_t)(kh * 2)) ^ ((row & 7) << 4));   \
        CP_ASYNC16(_b + sw, &A[(size_t)(rowBlk + row) * K + _k0 + kh]);        \
        CP_ASYNC16(_b + BOFF + sw, &Bt[(size_t)(colBlk + row) * K + _k0 + kh]);\
    }                                                                          \
    CP_COMMIT;                                                                 \
} while (0)

    PREFETCH(0, 0);
    PREFETCH(1, 1);

    for (int kt = 0; kt < L; kt++) {
        CP_WAIT(STAGES - 2);
        __syncthreads();
        int nf = kt + STAGES - 1;
        if (nf < L) PREFETCH(nf, nf % STAGES);

        int st = kt % STAGES;
        uint32_t baA = sbase + st * STG_BYTES + offA;
        uint32_t baB = sbase + st * STG_BYTES + BOFF + offB;
#pragma unroll
        for (int s = 0; s < 4; s++) {
            uint32_t af[4][4];
#pragma unroll
            for (int mi = 0; mi < 4; mi++)
                LDSM4(af[mi][0], af[mi][1], af[mi][2], af[mi][3],
                      (baA + mi * 2048) ^ (uint32_t)(s * 32));
            uint32_t bf[8];
            LDSM4(bf[0], bf[1], bf[2], bf[3], baB ^ (uint32_t)(s * 32));
            LDSM4(bf[4], bf[5], bf[6], bf[7], (baB + 2048) ^ (uint32_t)(s * 32));
#pragma unroll
            for (int mi = 0; mi < 4; mi++)
#pragma unroll
                for (int ni = 0; ni < 4; ni++)
                    MMA_F16(acc[mi][ni], af[mi], bf[ni * 2], bf[ni * 2 + 1]);
        }
    }

    int r0 = lane >> 2, cp = (lane & 3) * 2;
#pragma unroll
    for (int mi = 0; mi < 4; mi++) {
#pragma unroll
        for (int ni = 0; ni < 4; ni++) {
            size_t row = (size_t)(rowBlk + wm * 64 + mi * 16 + r0);
            int col = colBlk + wn * 32 + ni * 8 + cp;
            float o0 = acc[mi][ni][0], o1 = acc[mi][ni][1];
            float o2 = acc[mi][ni][2], o3 = acc[mi][ni][3];
            if (ROT) {
                int t = (int)(row % Tl);
                int d = col & 63;
                float2 sl = *(const float2*)&sinp[t * KDd + d];
                float2 cl = *(const float2*)&cosp[t * KDd + d];
                float2 sh = *(const float2*)&sinp[(t + 8) * KDd + d];
                float2 ch = *(const float2*)&cosp[(t + 8) * KDd + d];
                float n0 = o0 * cl.x - o1 * sl.x;
                float n1 = o1 * cl.y + o0 * sl.y;
                float n2 = o2 * ch.x - o3 * sh.x;
                float n3 = o3 * ch.y + o2 * sh.y;
                o0 = n0; o1 = n1; o2 = n2; o3 = n3;
            }
            if (TOHALF) {
                __half* C = (__half*)Cv;
                *(__half2*)&C[row * N + col] = __floats2half2_rn(o0, o1);
                *(__half2*)&C[(row + 8) * N + col] = __floats2half2_rn(o2, o3);
            } else {
                float* C = (float*)Cv;
                float2 w0 = {o0, o1};
                float2 w1 = {o2, o3};
                *(float2*)&C[row * N + col] = w0;
                *(float2*)&C[(row + 8) * N + col] = w1;
            }
        }
    }
#undef PREFETCH
}

// ---------------- kv per chunk (fp16 tensor cores) ----------------
// kv[k][e] = sum_c kr[c][k] * (v[c][e] * vid[h][c]);  64x128x256 GEMM per block.
#define LDAh 72
#define LDVh 136
__global__ __launch_bounds__(256) void kv_kernel(const __half* __restrict__ k,
                                                 const __half* __restrict__ v,
                                                 const float* __restrict__ vid,
                                                 float* __restrict__ kv)
{
    __shared__ __half kr_s[64 * LDAh];
    __shared__ __half vv_s[64 * LDVh];
    int bx = blockIdx.x;
    int h = bx % Hd;
    int n = (bx / Hd) % NCd;
    int b = bx / (Hd * NCd);
    int tid = threadIdx.x;
    int lane = tid & 31;
    int w = tid >> 5;
    int wm3 = w & 3;        // k row group (16)
    int wn3 = w >> 2;       // e half (64)
    int qrow = lane >> 2, qcol = lane & 3;
    int j = lane >> 3, rr = lane & 7;
    uint32_t skr = smem_u32(kr_s), svv = smem_u32(vv_s);
    // A (= kr^T, col-major source) via ldmatrix.trans
    int arow_off = rr + ((j >> 1) << 3);       // c-row within chunk
    int acol = wm3 * 16 + ((j & 1) << 3);      // k-col
    // B (= v*vid, row-major rows=c) via ldmatrix.trans
    int brow_off = rr + ((j & 1) << 3);
    int bcol_off = (j >> 1) << 3;

    float acc[8][4];
#pragma unroll
    for (int ni = 0; ni < 8; ni++)
#pragma unroll
        for (int r = 0; r < 4; r++) acc[ni][r] = 0.f;

    long row0 = (long)b * Tl + n * Cd;
    for (int cc = 0; cc < 4; cc++) {
        __syncthreads();
        {
            int kg = (tid & 3) * 16, row = tid >> 2;
            const uint4* ks_ = (const uint4*)&k[(row0 + cc * 64 + row) * Ed + h * KDd + kg];
            *(uint4*)&kr_s[row * LDAh + kg] = ks_[0];
            *(uint4*)&kr_s[row * LDAh + kg + 8] = ks_[1];
            float vv = vid[h * Cd + cc * 64 + row];
            int ec = (tid & 3) * 32;
            const __half2* vp = (const __half2*)&v[(row0 + cc * 64 + row) * E2d + h * HDd + ec];
#pragma unroll
            for (int i = 0; i < 16; i++) {
                float2 f = __half22float2(vp[i]);
                *(__half2*)&vv_s[row * LDVh + ec + i * 2] = __floats2half2_rn(f.x * vv, f.y * vv);
            }
        }
        __syncthreads();
#pragma unroll
        for (int ks = 0; ks < 4; ks++) {
            uint32_t a[4];
            LDSM4T(a[0], a[1], a[2], a[3],
                   skr + (uint32_t)(((ks * 16 + arow_off) * LDAh + acol) * 2));
#pragma unroll
            for (int eb = 0; eb < 4; eb++) {
                uint32_t b0, b1, b2, b3;
                LDSM4T(b0, b1, b2, b3,
                       svv + (uint32_t)(((ks * 16 + brow_off) * LDVh + wn3 * 64 + eb * 16 + bcol_off) * 2));
                MMA_F16(acc[eb * 2], a, b0, b1);
                MMA_F16(acc[eb * 2 + 1], a, b2, b3);
            }
        }
    }

    float* outp = kv + (size_t)bx * (KDd * HDd);
    int r = wm3 * 16 + qrow;
#pragma unroll
    for (int ni = 0; ni < 8; ni++) {
        int e = wn3 * 64 + ni * 8 + 2 * qcol;
        float2 o0 = {acc[ni][0], acc[ni][1]};
        float2 o1 = {acc[ni][2], acc[ni][3]};
        *(float2*)&outp[r * HDd + e] = o0;
        *(float2*)&outp[(r + 8) * HDd + e] = o1;
    }
}

// ---------------- scan (float4 per thread) ----------------
__global__ void scan_kernel(const float4* __restrict__ kv,
                            const float* __restrict__ cd,
                            float4* __restrict__ state)
{
    int idx = blockIdx.x * 256 + threadIdx.x;
    const int EQ = KDd * HDd / 4;
    int e4 = idx % EQ;
    int bh = idx / EQ;
    int h = bh % Hd, b = bh / Hd;
    float c = cd[h];
    float4 s = {0.f, 0.f, 0.f, 0.f};
    for (int n = 0; n < NCd; n++) {
        size_t off = ((size_t)((b * NCd + n) * Hd + h)) * EQ + e4;
        state[off] = s;
        float4 kvv = kv[off];
        s.x = s.x * c + kvv.x;
        s.y = s.y * c + kvv.y;
        s.z = s.z * c + kvv.z;
        s.w = s.w * c + kvv.w;
    }
}

// ---------------- cross_scale ----------------
__global__ void cscale_kernel(const float* __restrict__ state, float* __restrict__ cs)
{
    int bx = blockIdx.x;
    int e = threadIdx.x;
    const float* sp = state + (size_t)bx * (KDd * HDd);
    float s = 0.f;
#pragma unroll 8
    for (int k2 = 0; k2 < KDd; k2++) s += fabsf(sp[k2 * HDd + e]);
#pragma unroll
    for (int o = 16; o > 0; o >>= 1) s = fmaxf(s, __shfl_xor_sync(0xffffffff, s, o));
    __shared__ float wmax[4];
    if ((e & 31) == 0) wmax[e >> 5] = s;
    __syncthreads();
    if (e == 0) {
        float m = fmaxf(fmaxf(wmax[0], wmax[1]), fmaxf(wmax[2], wmax[3]));
        cs[bx] = fmaxf(m, 1.0f);
    }
}

// ---------------- fp16 tensor-core fused attention per (b,n,h,64-row slab) ---
#define ATTN_SMEM ((3 * 64 * LDAh + 64 * LDVh) * 2 + (128 + 128 + 64) * 4)
__global__ __launch_bounds__(256) void attn_kernel(
    const __half* __restrict__ q, const __half* __restrict__ k,
    const __half* __restrict__ v, const __half* __restrict__ g,
    const float* __restrict__ state, const float* __restrict__ cs,
    const float* __restrict__ mask, const float* __restrict__ qid,
    __half* __restrict__ act)
{
    extern __shared__ char smraw[];
    __half* qr_s = (__half*)smraw;            // 64*72
    __half* kr_s = qr_s + 64 * LDAh;          // 64*72
    __half* qk_s = kr_s + 64 * LDAh;          // 64*72
    __half* v_s  = qk_s + 64 * LDAh;          // 64*136
    float* ipart = (float*)(v_s + 64 * LDVh); // 2*64
    float* rpart = ipart + 128;               // 2*64
    float* qid_s = rpart + 128;               // 64

    int bx = blockIdx.x;
    int cb = bx % 4;
    int h  = (bx / 4) % Hd;
    int n  = (bx / (4 * Hd)) % NCd;
    int b  = bx / (4 * Hd * NCd);
    int tid = threadIdx.x;
    int lane = tid & 31;
    int w = tid >> 5;
    int wm = w >> 1;        // 16-row group
    int wn = w & 1;         // col half
    int qrow = lane >> 2, qcol = lane & 3;
    int j = lane >> 3, rr = lane & 7;
    int clr = wm * 16 + qrow;
    uint32_t sv = smem_u32(v_s);
    int vrow_off = rr + ((j & 1) << 3);
    int vcol_off = (j >> 1) << 3;
    long row0 = (long)b * Tl + n * Cd;

    // stage qr [64 x 64] fp16
    {
        int kg = (tid & 3) * 16, row = tid >> 2;
        const uint4* src = (const uint4*)&q[(row0 + cb * 64 + row) * Ed + h * KDd + kg];
        *(uint4*)&qr_s[row * LDAh + kg] = src[0];
        *(uint4*)&qr_s[row * LDAh + kg + 8] = src[1];
        if (tid < 64) qid_s[tid] = qid[h * Cd + cb * 64 + tid];
    }

    const float* mrow = mask + ((size_t)h * Cd + cb * 64) * Cd;
    float rs_lo = 0.f, rs_hi = 0.f;
    float acc2[8][4];
#pragma unroll
    for (int ni = 0; ni < 8; ni++)
#pragma unroll
        for (int r = 0; r < 4; r++) acc2[ni][r] = 0.f;

    for (int dc = 0; dc < 4; dc++) {
        __syncthreads();
        {   // stage kr [64x64] + v [64x128] fp16
            int kg = (tid & 3) * 16, row = tid >> 2;
            const uint4* ks_ = (const uint4*)&k[(row0 + dc * 64 + row) * Ed + h * KDd + kg];
            *(uint4*)&kr_s[row * LDAh + kg] = ks_[0];
            *(uint4*)&kr_s[row * LDAh + kg + 8] = ks_[1];
            int ec = (tid & 3) * 32;
            const uint4* vp = (const uint4*)&v[(row0 + dc * 64 + row) * E2d + h * HDd + ec];
            *(uint4*)&v_s[row * LDVh + ec]      = vp[0];
            *(uint4*)&v_s[row * LDVh + ec + 8]  = vp[1];
            *(uint4*)&v_s[row * LDVh + ec + 16] = vp[2];
            *(uint4*)&v_s[row * LDVh + ec + 24] = vp[3];
        }
        __syncthreads();

        // qk = qr @ kr^T (warp: 16 rows x 32 keys, K=64)
        float acc1[4][4];
#pragma unroll
        for (int ni = 0; ni < 4; ni++)
#pragma unroll
            for (int r = 0; r < 4; r++) acc1[ni][r] = 0.f;
#pragma unroll
        for (int ks = 0; ks < 4; ks++) {
            int kk = ks * 16 + 2 * qcol;
            uint32_t a[4];
            a[0] = *(const uint32_t*)&qr_s[clr * LDAh + kk];
            a[1] = *(const uint32_t*)&qr_s[(clr + 8) * LDAh + kk];
            a[2] = *(const uint32_t*)&qr_s[clr * LDAh + kk + 8];
            a[3] = *(const uint32_t*)&qr_s[(clr + 8) * LDAh + kk + 8];
#pragma unroll
            for (int ni = 0; ni < 4; ni++) {
                int br = wn * 32 + ni * 8 + qrow;
                uint32_t b0 = *(const uint32_t*)&kr_s[br * LDAh + kk];
                uint32_t b1 = *(const uint32_t*)&kr_s[br * LDAh + kk + 8];
                MMA_F16(acc1[ni], a, b0, b1);
            }
        }

        // mask, |.| row-sum, stage masked qk as fp16
#pragma unroll
        for (int ni = 0; ni < 4; ni++) {
            int dl = wn * 32 + ni * 8 + 2 * qcol;
            int d = dc * 64 + dl;
            float2 mlo = *(const float2*)&mrow[(size_t)clr * Cd + d];
            float2 mhi = *(const float2*)&mrow[(size_t)(clr + 8) * Cd + d];
            acc1[ni][0] *= mlo.x; acc1[ni][1] *= mlo.y;
            acc1[ni][2] *= mhi.x; acc1[ni][3] *= mhi.y;
            rs_lo += fabsf(acc1[ni][0]) + fabsf(acc1[ni][1]);
            rs_hi += fabsf(acc1[ni][2]) + fabsf(acc1[ni][3]);
            *(__half2*)&qk_s[clr * LDAh + dl] = __floats2half2_rn(acc1[ni][0], acc1[ni][1]);
            *(__half2*)&qk_s[(clr + 8) * LDAh + dl] = __floats2half2_rn(acc1[ni][2], acc1[ni][3]);
        }
        __syncthreads();

        // PV: acc2 += qk[16x64] @ V[64 x 128-half]; B via ldmatrix.trans
#pragma unroll
        for (int ks = 0; ks < 4; ks++) {
            int kk = ks * 16 + 2 * qcol;
            uint32_t a[4];
            a[0] = *(const uint32_t*)&qk_s[clr * LDAh + kk];
            a[1] = *(const uint32_t*)&qk_s[(clr + 8) * LDAh + kk];
            a[2] = *(const uint32_t*)&qk_s[clr * LDAh + kk + 8];
            a[3] = *(const uint32_t*)&qk_s[(clr + 8) * LDAh + kk + 8];
#pragma unroll
            for (int eb = 0; eb < 4; eb++) {
                int e0 = wn * 64 + eb * 16;
                uint32_t b0, b1, b2, b3;
                LDSM4T(b0, b1, b2, b3,
                       sv + (uint32_t)(((ks * 16 + vrow_off) * LDVh + e0 + vcol_off) * 2));
                MMA_F16(acc2[eb * 2], a, b0, b1);
                MMA_F16(acc2[eb * 2 + 1], a, b2, b3);
            }
        }
    }

    // cross: stage state (fp32 -> fp16), qr @ state
    __syncthreads();
    {
        const float* sp = state + ((size_t)((b * NCd + n) * Hd + h)) * (KDd * HDd);
        int row = tid >> 2, col = (tid & 3) * 32;
        const float4* sp4 = (const float4*)&sp[row * HDd + col];
#pragma unroll
        for (int i = 0; i < 8; i++) {
            float4 a4 = sp4[i];
            *(__half2*)&v_s[row * LDVh + col + i * 4]     = __floats2half2_rn(a4.x, a4.y);
            *(__half2*)&v_s[row * LDVh + col + i * 4 + 2] = __floats2half2_rn(a4.z, a4.w);
        }
    }
    __syncthreads();

    float acc3[8][4];
#pragma unroll
    for (int ni = 0; ni < 8; ni++)
#pragma unroll
        for (int r = 0; r < 4; r++) acc3[ni][r] = 0.f;
#pragma unroll
    for (int ks = 0; ks < 4; ks++) {
        int kk = ks * 16 + 2 * qcol;
        uint32_t a[4];
        a[0] = *(const uint32_t*)&qr_s[clr * LDAh + kk];
        a[1] = *(const uint32_t*)&qr_s[(clr + 8) * LDAh + kk];
        a[2] = *(const uint32_t*)&qr_s[clr * LDAh + kk + 8];
        a[3] = *(const uint32_t*)&qr_s[(clr + 8) * LDAh + kk + 8];
#pragma unroll
        for (int eb = 0; eb < 4; eb++) {
            int e0 = wn * 64 + eb * 16;
            uint32_t b0, b1, b2, b3;
            LDSM4T(b0, b1, b2, b3,
                   sv + (uint32_t)(((ks * 16 + vrow_off) * LDVh + e0 + vcol_off) * 2));
            MMA_F16(acc3[eb * 2], a, b0, b1);
            MMA_F16(acc3[eb * 2 + 1], a, b2, b3);
        }
    }

    // combine row-sums
    rs_lo += __shfl_xor_sync(0xffffffff, rs_lo, 1);
    rs_lo += __shfl_xor_sync(0xffffffff, rs_lo, 2);
    rs_hi += __shfl_xor_sync(0xffffffff, rs_hi, 1);
    rs_hi += __shfl_xor_sync(0xffffffff, rs_hi, 2);
    if ((lane & 3) == 0) {
        ipart[wn * 64 + clr] = rs_lo;
        ipart[wn * 64 + clr + 8] = rs_hi;
    }
    __syncthreads();

    float csc = cs[(b * NCd + n) * Hd + h];
    float is_lo = fmaxf(1.f, ipart[clr] + ipart[64 + clr]);
    float is_hi = fmaxf(1.f, ipart[clr + 8] + ipart[64 + clr + 8]);
    float inv_lo = 1.f / fmaxf(is_lo, csc);
    float inv_hi = 1.f / fmaxf(is_hi, csc);
    float qd_lo = qid_s[clr], qd_hi = qid_s[clr + 8];

    float ss_lo = 0.f, ss_hi = 0.f;
#pragma unroll
    for (int ni = 0; ni < 8; ni++) {
        acc2[ni][0] = (acc2[ni][0] + qd_lo * acc3[ni][0]) * inv_lo;
        acc2[ni][1] = (acc2[ni][1] + qd_lo * acc3[ni][1]) * inv_lo;
        acc2[ni][2] = (acc2[ni][2] + qd_hi * acc3[ni][2]) * inv_hi;
        acc2[ni][3] = (acc2[ni][3] + qd_hi * acc3[ni][3]) * inv_hi;
        ss_lo += acc2[ni][0] * acc2[ni][0] + acc2[ni][1] * acc2[ni][1];
        ss_hi += acc2[ni][2] * acc2[ni][2] + acc2[ni][3] * acc2[ni][3];
    }
    ss_lo += __shfl_xor_sync(0xffffffff, ss_lo, 1);
    ss_lo += __shfl_xor_sync(0xffffffff, ss_lo, 2);
    ss_hi += __shfl_xor_sync(0xffffffff, ss_hi, 1);
    ss_hi += __shfl_xor_sync(0xffffffff, ss_hi, 2);
    if ((lane & 3) == 0) {
        rpart[wn * 64 + clr] = ss_lo;
        rpart[wn * 64 + clr + 8] = ss_hi;
    }
    __syncthreads();

    float rn_lo = rsqrtf((rpart[clr] + rpart[64 + clr]) * (1.f / 128.f) + 1e-6f);
    float rn_hi = rsqrtf((rpart[clr + 8] + rpart[64 + clr + 8]) * (1.f / 128.f) + 1e-6f);

    long grow_lo = row0 + cb * 64 + clr;
    long grow_hi = grow_lo + 8;
#pragma unroll
    for (int ni = 0; ni < 8; ni++) {
        int e = wn * 64 + ni * 8 + 2 * qcol;
        float2 gl = __half22float2(*(const __half2*)&g[grow_lo * E2d + h * HDd + e]);
        float2 gh = __half22float2(*(const __half2*)&g[grow_hi * E2d + h * HDd + e]);
        float o0 = acc2[ni][0] * rn_lo * gl.x / (1.f + expf(-gl.x));
        float o1 = acc2[ni][1] * rn_lo * gl.y / (1.f + expf(-gl.y));
        float o2 = acc2[ni][2] * rn_hi * gh.x / (1.f + expf(-gh.x));
        float o3 = acc2[ni][3] * rn_hi * gh.y / (1.f + expf(-gh.y));
        *(__half2*)&act[grow_lo * E2d + h * HDd + e] = __floats2half2_rn(o0, o1);
        *(__half2*)&act[grow_hi * E2d + h * HDd + e] = __floats2half2_rn(o2, o3);
    }
}

// ---------------- host launch ----------------
extern "C" void kernel_launch(void* const* d_in, const int* in_sizes, int n_in,
                              void* d_out, int out_size)
{
    const float* x    = (const float*)d_in[0];
    const float* sinp = (const float*)d_in[1];
    const float* cosp = (const float*)d_in[2];
    const float* mask = (const float*)d_in[3];
    const float* cdec = (const float*)d_in[4];
    const float* qid  = (const float*)d_in[5];
    const float* vid  = (const float*)d_in[6];
    const float* Wq   = (const float*)d_in[7];
    const float* Wk   = (const float*)d_in[8];
    const float* Wv   = (const float*)d_in[9];
    const float* Wg   = (const float*)d_in[10];
    const float* Wo   = (const float*)d_in[11];
    float* out = (float*)d_out;

    float *p_kv, *p_state, *p_cs;
    __half *p_q, *p_k, *p_v, *p_g, *p_xh, *p_act, *p_wt;
    cudaGetSymbolAddress((void**)&p_q, g_q);
    cudaGetSymbolAddress((void**)&p_k, g_k);
    cudaGetSymbolAddress((void**)&p_v, g_v);
    cudaGetSymbolAddress((void**)&p_g, g_g);
    cudaGetSymbolAddress((void**)&p_act, g_act);
    cudaGetSymbolAddress((void**)&p_xh, g_xh);
    cudaGetSymbolAddress((void**)&p_kv, g_kv);
    cudaGetSymbolAddress((void**)&p_state, g_state);
    cudaGetSymbolAddress((void**)&p_cs, g_cscale);
    cudaGetSymbolAddress((void**)&p_wt, g_wt);

    __half* wtq = p_wt;
    __half* wtk = p_wt + 262144;
    __half* wtv = p_wt + 524288;
    __half* wtg = p_wt + 1048576;
    __half* wto = p_wt + 1572864;

    cudaFuncSetAttribute(attn_kernel, cudaFuncAttributeMaxDynamicSharedMemorySize, ATTN_SMEM);
    cudaFuncSetAttribute(mma_gemm<true, true>, cudaFuncAttributeMaxDynamicSharedMemorySize, GEMM_SMEM);
    cudaFuncSetAttribute(mma_gemm<false, true>, cudaFuncAttributeMaxDynamicSharedMemorySize, GEMM_SMEM);
    cudaFuncSetAttribute(mma_gemm<false, false>, cudaFuncAttributeMaxDynamicSharedMemorySize, GEMM_SMEM);

    // x -> fp16; weights transpose -> fp16 (0.125 folded into Wk)
    tohalf_kernel<<<(Mtot * Ed / 4) / 256, 256>>>(x, p_xh);
    transpose_kernel<<<dim3(16, 16), dim3(32, 8)>>>(Wq, wtq, Ed, Ed, 1.0f);
    transpose_kernel<<<dim3(16, 16), dim3(32, 8)>>>(Wk, wtk, Ed, Ed, 0.125f);
    transpose_kernel<<<dim3(32, 16), dim3(32, 8)>>>(Wv, wtv, Ed, E2d, 1.0f);
    transpose_kernel<<<dim3(32, 16), dim3(32, 8)>>>(Wg, wtg, Ed, E2d, 1.0f);
    transpose_kernel<<<dim3(16, 32), dim3(32, 8)>>>(Wo, wto, E2d, Ed, 1.0f);

    // projections (fp16 out); rotary fused into q/k epilogues
    mma_gemm<true, true><<<dim3(4, 256), 256, GEMM_SMEM>>>(p_xh, wtq, p_q, Mtot, Ed, Ed, sinp, cosp);
    mma_gemm<true, true><<<dim3(4, 256), 256, GEMM_SMEM>>>(p_xh, wtk, p_k, Mtot, Ed, Ed, sinp, cosp);
    mma_gemm<false, true><<<dim3(8, 256), 256, GEMM_SMEM>>>(p_xh, wtv, p_v, Mtot, E2d, Ed, nullptr, nullptr);
    mma_gemm<false, true><<<dim3(8, 256), 256, GEMM_SMEM>>>(p_xh, wtg, p_g, Mtot, E2d, Ed, nullptr, nullptr);

    // per-chunk kv (tensor cores), scan, cross scale
    kv_kernel<<<Bz * NCd * Hd, 256>>>(p_k, p_v, vid, p_kv);
    scan_kernel<<<(Bz * Hd * KDd * HDd / 4) / 256, 256>>>(
        (const float4*)p_kv, cdec, (float4*)p_state);
    cscale_kernel<<<Bz * NCd * Hd, 128>>>(p_state, p_cs);

    // fp16 tensor-core fused attention
    attn_kernel<<<Bz * NCd * Hd * 4, 256, ATTN_SMEM>>>(
        p_q, p_k, p_v, p_g, p_state, p_cs, mask, qid, p_act);

    // output projection (fp32 out)
    mma_gemm<false, false><<<dim3(4, 256), 256, GEMM_SMEM>>>(p_act, wto, out, Mtot, Ed, E2d, nullptr, nullptr);
}

// round 8
// speedup vs baseline: 6.3019x; 1.1121x over previous
#include <cuda_runtime.h>
#include <cuda_fp16.h>
#include <math.h>
#include <stdint.h>

// Dims (fixed for this problem)
#define Bz    4
#define Tl    8192
#define Ed    512
#define Hd    8
#define KDd   64
#define HDd   128
#define Cd    256
#define NCd   32
#define E2d   1024
#define Mtot  32768   // B*T

// ---------------- scratch (device globals; no runtime alloc) ----------------
__device__ __half g_q[(size_t)Mtot * Ed];
__device__ __half g_k[(size_t)Mtot * Ed];
__device__ __half g_v[(size_t)Mtot * E2d];
__device__ __half g_g[(size_t)Mtot * E2d];
__device__ __half g_act[(size_t)Mtot * E2d];
__device__ __half g_xh[(size_t)Mtot * Ed];    // fp16 x
__device__ float  g_kv[(size_t)Bz * NCd * Hd * KDd * HDd];
__device__ float  g_state[(size_t)Bz * NCd * Hd * KDd * HDd];
__device__ float  g_cscale[Bz * NCd * Hd];
__device__ __half g_wt[2621440];   // fused [3072,512] + Wo [512,1024]

__device__ __forceinline__ uint32_t smem_u32(const void* p) {
    uint32_t a;
    asm("{ .reg .u64 t; cvta.to.shared.u64 t, %1; cvt.u32.u64 %0, t; }"
        : "=r"(a) : "l"(p));
    return a;
}

#define LDSM4(r0, r1, r2, r3, a)                                               \
    asm volatile("ldmatrix.sync.aligned.m8n8.x4.shared.b16 {%0,%1,%2,%3}, [%4];" \
                 : "=r"(r0), "=r"(r1), "=r"(r2), "=r"(r3) : "r"(a))

#define LDSM4T(r0, r1, r2, r3, a)                                              \
    asm volatile("ldmatrix.sync.aligned.m8n8.x4.trans.shared.b16 {%0,%1,%2,%3}, [%4];" \
                 : "=r"(r0), "=r"(r1), "=r"(r2), "=r"(r3) : "r"(a))

#define MMA_F16(c, a, b0, b1)                                                  \
    asm volatile("mma.sync.aligned.m16n8k16.row.col.f32.f16.f16.f32 "          \
                 "{%0,%1,%2,%3},{%4,%5,%6,%7},{%8,%9},{%0,%1,%2,%3};"          \
                 : "+f"((c)[0]), "+f"((c)[1]), "+f"((c)[2]), "+f"((c)[3])      \
                 : "r"((a)[0]), "r"((a)[1]), "r"((a)[2]), "r"((a)[3]),         \
                   "r"(b0), "r"(b1))

#define CP_ASYNC16(dst, src)                                                   \
    asm volatile("cp.async.cg.shared.global [%0], [%1], 16;"                   \
                 :: "r"(dst), "l"(src))
#define CP_COMMIT asm volatile("cp.async.commit_group;" ::: "memory")
#define CP_WAIT(n) asm volatile("cp.async.wait_group %0;" :: "n"(n) : "memory")

// ---------------- x -> fp16 ----------------
__global__ void tohalf_kernel(const float* __restrict__ in, __half* __restrict__ out)
{
    int i = blockIdx.x * 256 + threadIdx.x;
    float4 v = ((const float4*)in)[i];
    ((__half2*)out)[i * 2]     = __floats2half2_rn(v.x, v.y);
    ((__half2*)out)[i * 2 + 1] = __floats2half2_rn(v.z, v.w);
}

// ---------------- weight transpose (+scale) to fp16 ----------------
__global__ void transpose_kernel(const float* __restrict__ W, __half* __restrict__ Wt,
                                 int K, int N, float scale)
{
    __shared__ float t[32][33];
    int n0 = blockIdx.x * 32, k0 = blockIdx.y * 32;
    int tx = threadIdx.x, ty = threadIdx.y;  // 32 x 8
#pragma unroll
    for (int i = 0; i < 4; i++)
        t[ty + i * 8][tx] = W[(size_t)(k0 + ty + i * 8) * N + n0 + tx];
    __syncthreads();
#pragma unroll
    for (int i = 0; i < 4; i++)
        Wt[(size_t)(n0 + ty + i * 8) * K + k0 + tx] = __float2half_rn(t[tx][ty + i * 8] * scale);
}

// ================= GEMM core (shared mainloop as macro-free inline) =========
#define STAGES 3
#define STG_BYTES 16384
#define GEMM_SMEM (STAGES * 2 * STG_BYTES)

#define GEMM_PREFETCH(kt, st, Kdim) do {                                       \
    int _k0 = (kt) * 64;                                                       \
    uint32_t _b = sbase + (st) * STG_BYTES;                                    \
    _Pragma("unroll")                                                          \
    for (int p = 0; p < 4; p++) {                                              \
        int row = p * 32 + ldrow;                                              \
        uint32_t sw = row * 128 + (((uint32_t)(kh * 2)) ^ ((row & 7) << 4));   \
        CP_ASYNC16(_b + sw, &A[(size_t)(rowBlk + row) * (Kdim) + _k0 + kh]);   \
        CP_ASYNC16(_b + BOFF + sw, &Bt[(size_t)(colBlk + row) * (Kdim) + _k0 + kh]); \
    }                                                                          \
    CP_COMMIT;                                                                 \
} while (0)

#define GEMM_MAINLOOP(Kdim) do {                                               \
    const int L = (Kdim) >> 6;                                                 \
    GEMM_PREFETCH(0, 0, Kdim);                                                 \
    GEMM_PREFETCH(1, 1, Kdim);                                                 \
    for (int kt = 0; kt < L; kt++) {                                           \
        CP_WAIT(STAGES - 2);                                                   \
        __syncthreads();                                                       \
        int nf = kt + STAGES - 1;                                              \
        if (nf < L) GEMM_PREFETCH(nf, nf % STAGES, Kdim);                      \
        int st = kt % STAGES;                                                  \
        uint32_t baA = sbase + st * STG_BYTES + offA;                          \
        uint32_t baB = sbase + st * STG_BYTES + BOFF + offB;                   \
        _Pragma("unroll")                                                      \
        for (int s = 0; s < 4; s++) {                                          \
            uint32_t af[4][4];                                                 \
            _Pragma("unroll")                                                  \
            for (int mi = 0; mi < 4; mi++)                                     \
                LDSM4(af[mi][0], af[mi][1], af[mi][2], af[mi][3],              \
                      (baA + mi * 2048) ^ (uint32_t)(s * 32));                 \
            uint32_t bf[8];                                                    \
            LDSM4(bf[0], bf[1], bf[2], bf[3], baB ^ (uint32_t)(s * 32));       \
            LDSM4(bf[4], bf[5], bf[6], bf[7], (baB + 2048) ^ (uint32_t)(s * 32)); \
            _Pragma("unroll")                                                  \
            for (int mi = 0; mi < 4; mi++)                                     \
                _Pragma("unroll")                                              \
                for (int ni = 0; ni < 4; ni++)                                 \
                    MMA_F16(acc[mi][ni], af[mi], bf[ni * 2], bf[ni * 2 + 1]);  \
        }                                                                      \
    }                                                                          \
} while (0)

#define GEMM_PROLOG                                                            \
    extern __shared__ float smemf[];                                           \
    uint32_t sbase = smem_u32(smemf);                                          \
    const uint32_t BOFF = STAGES * STG_BYTES;                                  \
    int tid = threadIdx.x;                                                     \
    int lane = tid & 31;                                                       \
    int w = tid >> 5;                                                          \
    int wm = w & 1;                                                            \
    int wn = w >> 1;                                                           \
    float acc[4][4][4];                                                        \
    _Pragma("unroll")                                                          \
    for (int mi = 0; mi < 4; mi++)                                             \
        _Pragma("unroll")                                                      \
        for (int ni = 0; ni < 4; ni++)                                         \
            _Pragma("unroll")                                                  \
            for (int r = 0; r < 4; r++) acc[mi][ni][r] = 0.f;                  \
    int ldrow = tid >> 3;                                                      \
    int kh = (tid & 7) * 8;                                                    \
    int rowA0 = wm * 64 + (lane & 15);                                         \
    uint32_t offA = rowA0 * 128 + (((lane >> 4) * 16) ^ ((rowA0 & 7) << 4));   \
    int nB0 = wn * 32 + (lane & 7) + ((lane & 16) ? 8 : 0);                    \
    uint32_t offB = nB0 * 128 + ((((lane >> 3) & 1) * 16) ^ ((nB0 & 7) << 4));

// ---------------- fused QKVG projection GEMM ----------------
// A = xh [Mtot, 512]; Bt = fused weights [3072, 512]; one launch.
// Column blocks: 0-3 -> q (rot), 4-7 -> k (rot), 8-15 -> v, 16-23 -> g.
__global__ __launch_bounds__(256) void qkvg_gemm(
    const __half* __restrict__ A, const __half* __restrict__ Bt,
    __half* __restrict__ qp, __half* __restrict__ kp,
    __half* __restrict__ vp, __half* __restrict__ gp,
    const float* __restrict__ sinp, const float* __restrict__ cosp)
{
    GEMM_PROLOG
    int rowBlk = blockIdx.y * 128;
    int colBlk = blockIdx.x * 128;   // row offset into fused Bt

    GEMM_MAINLOOP(Ed);

    int cbk = blockIdx.x;
    __half* dst; int N2; int col0; bool rot;
    if (cbk < 4)       { dst = qp; N2 = Ed;  col0 = cbk * 128;        rot = true; }
    else if (cbk < 8)  { dst = kp; N2 = Ed;  col0 = (cbk - 4) * 128;  rot = true; }
    else if (cbk < 16) { dst = vp; N2 = E2d; col0 = (cbk - 8) * 128;  rot = false; }
    else               { dst = gp; N2 = E2d; col0 = (cbk - 16) * 128; rot = false; }

    int r0 = lane >> 2, cp = (lane & 3) * 2;
#pragma unroll
    for (int mi = 0; mi < 4; mi++) {
#pragma unroll
        for (int ni = 0; ni < 4; ni++) {
            size_t row = (size_t)(rowBlk + wm * 64 + mi * 16 + r0);
            int col = col0 + wn * 32 + ni * 8 + cp;
            float o0 = acc[mi][ni][0], o1 = acc[mi][ni][1];
            float o2 = acc[mi][ni][2], o3 = acc[mi][ni][3];
            if (rot) {
                int t = (int)(row % Tl);
                int d = col & 63;
                float2 sl = *(const float2*)&sinp[t * KDd + d];
                float2 cl = *(const float2*)&cosp[t * KDd + d];
                float2 sh = *(const float2*)&sinp[(t + 8) * KDd + d];
                float2 ch = *(const float2*)&cosp[(t + 8) * KDd + d];
                float n0 = o0 * cl.x - o1 * sl.x;
                float n1 = o1 * cl.y + o0 * sl.y;
                float n2 = o2 * ch.x - o3 * sh.x;
                float n3 = o3 * ch.y + o2 * sh.y;
                o0 = n0; o1 = n1; o2 = n2; o3 = n3;
            }
            *(__half2*)&dst[row * N2 + col] = __floats2half2_rn(o0, o1);
            *(__half2*)&dst[(row + 8) * N2 + col] = __floats2half2_rn(o2, o3);
        }
    }
}

// ---------------- output projection GEMM (fp32 out) ----------------
__global__ __launch_bounds__(256) void out_gemm(
    const __half* __restrict__ A, const __half* __restrict__ Bt,
    float* __restrict__ C)
{
    GEMM_PROLOG
    int rowBlk = blockIdx.y * 128;
    int colBlk = blockIdx.x * 128;

    GEMM_MAINLOOP(E2d);

    int r0 = lane >> 2, cp = (lane & 3) * 2;
#pragma unroll
    for (int mi = 0; mi < 4; mi++) {
#pragma unroll
        for (int ni = 0; ni < 4; ni++) {
            size_t row = (size_t)(rowBlk + wm * 64 + mi * 16 + r0);
            int col = colBlk + wn * 32 + ni * 8 + cp;
            float2 w0 = {acc[mi][ni][0], acc[mi][ni][1]};
            float2 w1 = {acc[mi][ni][2], acc[mi][ni][3]};
            *(float2*)&C[row * Ed + col] = w0;
            *(float2*)&C[(row + 8) * Ed + col] = w1;
        }
    }
}

// ---------------- kv per chunk (fp16 tensor cores) ----------------
#define LDAh 72
#define LDVh 136
__global__ __launch_bounds__(256) void kv_kernel(const __half* __restrict__ k,
                                                 const __half* __restrict__ v,
                                                 const float* __restrict__ vid,
                                                 float* __restrict__ kv)
{
    __shared__ __half kr_s[64 * LDAh];
    __shared__ __half vv_s[64 * LDVh];
    int bx = blockIdx.x;
    int h = bx % Hd;
    int n = (bx / Hd) % NCd;
    int b = bx / (Hd * NCd);
    int tid = threadIdx.x;
    int lane = tid & 31;
    int w = tid >> 5;
    int wm3 = w & 3;
    int wn3 = w >> 2;
    int qrow = lane >> 2, qcol = lane & 3;
    int j = lane >> 3, rr = lane & 7;
    uint32_t skr = smem_u32(kr_s), svv = smem_u32(vv_s);
    int arow_off = rr + ((j >> 1) << 3);
    int acol = wm3 * 16 + ((j & 1) << 3);
    int brow_off = rr + ((j & 1) << 3);
    int bcol_off = (j >> 1) << 3;

    float acc[8][4];
#pragma unroll
    for (int ni = 0; ni < 8; ni++)
#pragma unroll
        for (int r = 0; r < 4; r++) acc[ni][r] = 0.f;

    long row0 = (long)b * Tl + n * Cd;
    for (int cc = 0; cc < 4; cc++) {
        __syncthreads();
        {
            int kg = (tid & 3) * 16, row = tid >> 2;
            const uint4* ks_ = (const uint4*)&k[(row0 + cc * 64 + row) * Ed + h * KDd + kg];
            *(uint4*)&kr_s[row * LDAh + kg] = ks_[0];
            *(uint4*)&kr_s[row * LDAh + kg + 8] = ks_[1];
            float vv = vid[h * Cd + cc * 64 + row];
            int ec = (tid & 3) * 32;
            const __half2* vp = (const __half2*)&v[(row0 + cc * 64 + row) * E2d + h * HDd + ec];
#pragma unroll
            for (int i = 0; i < 16; i++) {
                float2 f = __half22float2(vp[i]);
                *(__half2*)&vv_s[row * LDVh + ec + i * 2] = __floats2half2_rn(f.x * vv, f.y * vv);
            }
        }
        __syncthreads();
#pragma unroll
        for (int ks = 0; ks < 4; ks++) {
            uint32_t a[4];
            LDSM4T(a[0], a[1], a[2], a[3],
                   skr + (uint32_t)(((ks * 16 + arow_off) * LDAh + acol) * 2));
#pragma unroll
            for (int eb = 0; eb < 4; eb++) {
                uint32_t b0, b1, b2, b3;
                LDSM4T(b0, b1, b2, b3,
                       svv + (uint32_t)(((ks * 16 + brow_off) * LDVh + wn3 * 64 + eb * 16 + bcol_off) * 2));
                MMA_F16(acc[eb * 2], a, b0, b1);
                MMA_F16(acc[eb * 2 + 1], a, b2, b3);
            }
        }
    }

    float* outp = kv + (size_t)bx * (KDd * HDd);
    int r = wm3 * 16 + qrow;
#pragma unroll
    for (int ni = 0; ni < 8; ni++) {
        int e = wn3 * 64 + ni * 8 + 2 * qcol;
        float2 o0 = {acc[ni][0], acc[ni][1]};
        float2 o1 = {acc[ni][2], acc[ni][3]};
        *(float2*)&outp[r * HDd + e] = o0;
        *(float2*)&outp[(r + 8) * HDd + e] = o1;
    }
}

// ---------------- scan (float4 per thread) ----------------
__global__ void scan_kernel(const float4* __restrict__ kv,
                            const float* __restrict__ cd,
                            float4* __restrict__ state)
{
    int idx = blockIdx.x * 256 + threadIdx.x;
    const int EQ = KDd * HDd / 4;
    int e4 = idx % EQ;
    int bh = idx / EQ;
    int h = bh % Hd, b = bh / Hd;
    float c = cd[h];
    float4 s = {0.f, 0.f, 0.f, 0.f};
    for (int n = 0; n < NCd; n++) {
        size_t off = ((size_t)((b * NCd + n) * Hd + h)) * EQ + e4;
        state[off] = s;
        float4 kvv = kv[off];
        s.x = s.x * c + kvv.x;
        s.y = s.y * c + kvv.y;
        s.z = s.z * c + kvv.z;
        s.w = s.w * c + kvv.w;
    }
}

// ---------------- cross_scale ----------------
__global__ void cscale_kernel(const float* __restrict__ state, float* __restrict__ cs)
{
    int bx = blockIdx.x;
    int e = threadIdx.x;
    const float* sp = state + (size_t)bx * (KDd * HDd);
    float s = 0.f;
#pragma unroll 8
    for (int k2 = 0; k2 < KDd; k2++) s += fabsf(sp[k2 * HDd + e]);
#pragma unroll
    for (int o = 16; o > 0; o >>= 1) s = fmaxf(s, __shfl_xor_sync(0xffffffff, s, o));
    __shared__ float wmax[4];
    if ((e & 31) == 0) wmax[e >> 5] = s;
    __syncthreads();
    if (e == 0) {
        float m = fmaxf(fmaxf(wmax[0], wmax[1]), fmaxf(wmax[2], wmax[3]));
        cs[bx] = fmaxf(m, 1.0f);
    }
}

// ---------------- fp16 tensor-core fused attention per (b,n,h,64-row slab) ---
// Causal skip: mask[c][d] == 0 for d > c, so only chunks dc <= cb are computed.
#define ATTN_SMEM ((3 * 64 * LDAh + 64 * LDVh) * 2 + (128 + 128 + 64) * 4)
__global__ __launch_bounds__(256) void attn_kernel(
    const __half* __restrict__ q, const __half* __restrict__ k,
    const __half* __restrict__ v, const __half* __restrict__ g,
    const float* __restrict__ state, const float* __restrict__ cs,
    const float* __restrict__ mask, const float* __restrict__ qid,
    __half* __restrict__ act)
{
    extern __shared__ char smraw[];
    __half* qr_s = (__half*)smraw;
    __half* kr_s = qr_s + 64 * LDAh;
    __half* qk_s = kr_s + 64 * LDAh;
    __half* v_s  = qk_s + 64 * LDAh;
    float* ipart = (float*)(v_s + 64 * LDVh);
    float* rpart = ipart + 128;
    float* qid_s = rpart + 128;

    int bx = blockIdx.x;
    int cb = bx % 4;
    int h  = (bx / 4) % Hd;
    int n  = (bx / (4 * Hd)) % NCd;
    int b  = bx / (4 * Hd * NCd);
    int tid = threadIdx.x;
    int lane = tid & 31;
    int w = tid >> 5;
    int wm = w >> 1;
    int wn = w & 1;
    int qrow = lane >> 2, qcol = lane & 3;
    int j = lane >> 3, rr = lane & 7;
    int clr = wm * 16 + qrow;
    uint32_t sv = smem_u32(v_s);
    int vrow_off = rr + ((j & 1) << 3);
    int vcol_off = (j >> 1) << 3;
    long row0 = (long)b * Tl + n * Cd;

    {
        int kg = (tid & 3) * 16, row = tid >> 2;
        const uint4* src = (const uint4*)&q[(row0 + cb * 64 + row) * Ed + h * KDd + kg];
        *(uint4*)&qr_s[row * LDAh + kg] = src[0];
        *(uint4*)&qr_s[row * LDAh + kg + 8] = src[1];
        if (tid < 64) qid_s[tid] = qid[h * Cd + cb * 64 + tid];
    }

    const float* mrow = mask + ((size_t)h * Cd + cb * 64) * Cd;
    float rs_lo = 0.f, rs_hi = 0.f;
    float acc2[8][4];
#pragma unroll
    for (int ni = 0; ni < 8; ni++)
#pragma unroll
        for (int r = 0; r < 4; r++) acc2[ni][r] = 0.f;

    for (int dc = 0; dc <= cb; dc++) {   // causal skip: dc > cb is all-zero
        __syncthreads();
        {
            int kg = (tid & 3) * 16, row = tid >> 2;
            const uint4* ks_ = (const uint4*)&k[(row0 + dc * 64 + row) * Ed + h * KDd + kg];
            *(uint4*)&kr_s[row * LDAh + kg] = ks_[0];
            *(uint4*)&kr_s[row * LDAh + kg + 8] = ks_[1];
            int ec = (tid & 3) * 32;
            const uint4* vp = (const uint4*)&v[(row0 + dc * 64 + row) * E2d + h * HDd + ec];
            *(uint4*)&v_s[row * LDVh + ec]      = vp[0];
            *(uint4*)&v_s[row * LDVh + ec + 8]  = vp[1];
            *(uint4*)&v_s[row * LDVh + ec + 16] = vp[2];
            *(uint4*)&v_s[row * LDVh + ec + 24] = vp[3];
        }
        __syncthreads();

        float acc1[4][4];
#pragma unroll
        for (int ni = 0; ni < 4; ni++)
#pragma unroll
            for (int r = 0; r < 4; r++) acc1[ni][r] = 0.f;
#pragma unroll
        for (int ks = 0; ks < 4; ks++) {
            int kk = ks * 16 + 2 * qcol;
            uint32_t a[4];
            a[0] = *(const uint32_t*)&qr_s[clr * LDAh + kk];
            a[1] = *(const uint32_t*)&qr_s[(clr + 8) * LDAh + kk];
            a[2] = *(const uint32_t*)&qr_s[clr * LDAh + kk + 8];
            a[3] = *(const uint32_t*)&qr_s[(clr + 8) * LDAh + kk + 8];
#pragma unroll
            for (int ni = 0; ni < 4; ni++) {
                int br = wn * 32 + ni * 8 + qrow;
                uint32_t b0 = *(const uint32_t*)&kr_s[br * LDAh + kk];
                uint32_t b1 = *(const uint32_t*)&kr_s[br * LDAh + kk + 8];
                MMA_F16(acc1[ni], a, b0, b1);
            }
        }

#pragma unroll
        for (int ni = 0; ni < 4; ni++) {
            int dl = wn * 32 + ni * 8 + 2 * qcol;
            int d = dc * 64 + dl;
            float2 mlo = *(const float2*)&mrow[(size_t)clr * Cd + d];
            float2 mhi = *(const float2*)&mrow[(size_t)(clr + 8) * Cd + d];
            acc1[ni][0] *= mlo.x; acc1[ni][1] *= mlo.y;
            acc1[ni][2] *= mhi.x; acc1[ni][3] *= mhi.y;
            rs_lo += fabsf(acc1[ni][0]) + fabsf(acc1[ni][1]);
            rs_hi += fabsf(acc1[ni][2]) + fabsf(acc1[ni][3]);
            *(__half2*)&qk_s[clr * LDAh + dl] = __floats2half2_rn(acc1[ni][0], acc1[ni][1]);
            *(__half2*)&qk_s[(clr + 8) * LDAh + dl] = __floats2half2_rn(acc1[ni][2], acc1[ni][3]);
        }
        __syncthreads();

#pragma unroll
        for (int ks = 0; ks < 4; ks++) {
            int kk = ks * 16 + 2 * qcol;
            uint32_t a[4];
            a[0] = *(const uint32_t*)&qk_s[clr * LDAh + kk];
            a[1] = *(const uint32_t*)&qk_s[(clr + 8) * LDAh + kk];
            a[2] = *(const uint32_t*)&qk_s[clr * LDAh + kk + 8];
            a[3] = *(const uint32_t*)&qk_s[(clr + 8) * LDAh + kk + 8];
#pragma unroll
            for (int eb = 0; eb < 4; eb++) {
                int e0 = wn * 64 + eb * 16;
                uint32_t b0, b1, b2, b3;
                LDSM4T(b0, b1, b2, b3,
                       sv + (uint32_t)(((ks * 16 + vrow_off) * LDVh + e0 + vcol_off) * 2));
                MMA_F16(acc2[eb * 2], a, b0, b1);
                MMA_F16(acc2[eb * 2 + 1], a, b2, b3);
            }
        }
    }

    // cross: stage state (fp32 -> fp16), qr @ state
    __syncthreads();
    {
        const float* sp = state + ((size_t)((b * NCd + n) * Hd + h)) * (KDd * HDd);
        int row = tid >> 2, col = (tid & 3) * 32;
        const float4* sp4 = (const float4*)&sp[row * HDd + col];
#pragma unroll
        for (int i = 0; i < 8; i++) {
            float4 a4 = sp4[i];
            *(__half2*)&v_s[row * LDVh + col + i * 4]     = __floats2half2_rn(a4.x, a4.y);
            *(__half2*)&v_s[row * LDVh + col + i * 4 + 2] = __floats2half2_rn(a4.z, a4.w);
        }
    }
    __syncthreads();

    float acc3[8][4];
#pragma unroll
    for (int ni = 0; ni < 8; ni++)
#pragma unroll
        for (int r = 0; r < 4; r++) acc3[ni][r] = 0.f;
#pragma unroll
    for (int ks = 0; ks < 4; ks++) {
        int kk = ks * 16 + 2 * qcol;
        uint32_t a[4];
        a[0] = *(const uint32_t*)&qr_s[clr * LDAh + kk];
        a[1] = *(const uint32_t*)&qr_s[(clr + 8) * LDAh + kk];
        a[2] = *(const uint32_t*)&qr_s[clr * LDAh + kk + 8];
        a[3] = *(const uint32_t*)&qr_s[(clr + 8) * LDAh + kk + 8];
#pragma unroll
        for (int eb = 0; eb < 4; eb++) {
            int e0 = wn * 64 + eb * 16;
            uint32_t b0, b1, b2, b3;
            LDSM4T(b0, b1, b2, b3,
                   sv + (uint32_t)(((ks * 16 + vrow_off) * LDVh + e0 + vcol_off) * 2));
            MMA_F16(acc3[eb * 2], a, b0, b1);
            MMA_F16(acc3[eb * 2 + 1], a, b2, b3);
        }
    }

    rs_lo += __shfl_xor_sync(0xffffffff, rs_lo, 1);
    rs_lo += __shfl_xor_sync(0xffffffff, rs_lo, 2);
    rs_hi += __shfl_xor_sync(0xffffffff, rs_hi, 1);
    rs_hi += __shfl_xor_sync(0xffffffff, rs_hi, 2);
    if ((lane & 3) == 0) {
        ipart[wn * 64 + clr] = rs_lo;
        ipart[wn * 64 + clr + 8] = rs_hi;
    }
    __syncthreads();

    float csc = cs[(b * NCd + n) * Hd + h];
    float is_lo = fmaxf(1.f, ipart[clr] + ipart[64 + clr]);
    float is_hi = fmaxf(1.f, ipart[clr + 8] + ipart[64 + clr + 8]);
    float inv_lo = 1.f / fmaxf(is_lo, csc);
    float inv_hi = 1.f / fmaxf(is_hi, csc);
    float qd_lo = qid_s[clr], qd_hi = qid_s[clr + 8];

    float ss_lo = 0.f, ss_hi = 0.f;
#pragma unroll
    for (int ni = 0; ni < 8; ni++) {
        acc2[ni][0] = (acc2[ni][0] + qd_lo * acc3[ni][0]) * inv_lo;
        acc2[ni][1] = (acc2[ni][1] + qd_lo * acc3[ni][1]) * inv_lo;
        acc2[ni][2] = (acc2[ni][2] + qd_hi * acc3[ni][2]) * inv_hi;
        acc2[ni][3] = (acc2[ni][3] + qd_hi * acc3[ni][3]) * inv_hi;
        ss_lo += acc2[ni][0] * acc2[ni][0] + acc2[ni][1] * acc2[ni][1];
        ss_hi += acc2[ni][2] * acc2[ni][2] + acc2[ni][3] * acc2[ni][3];
    }
    ss_lo += __shfl_xor_sync(0xffffffff, ss_lo, 1);
    ss_lo += __shfl_xor_sync(0xffffffff, ss_lo, 2);
    ss_hi += __shfl_xor_sync(0xffffffff, ss_hi, 1);
    ss_hi += __shfl_xor_sync(0xffffffff, ss_hi, 2);
    if ((lane & 3) == 0) {
        rpart[wn * 64 + clr] = ss_lo;
        rpart[wn * 64 + clr + 8] = ss_hi;
    }
    __syncthreads();

    float rn_lo = rsqrtf((rpart[clr] + rpart[64 + clr]) * (1.f / 128.f) + 1e-6f);
    float rn_hi = rsqrtf((rpart[clr + 8] + rpart[64 + clr + 8]) * (1.f / 128.f) + 1e-6f);

    long grow_lo = row0 + cb * 64 + clr;
    long grow_hi = grow_lo + 8;
#pragma unroll
    for (int ni = 0; ni < 8; ni++) {
        int e = wn * 64 + ni * 8 + 2 * qcol;
        float2 gl = __half22float2(*(const __half2*)&g[grow_lo * E2d + h * HDd + e]);
        float2 gh = __half22float2(*(const __half2*)&g[grow_hi * E2d + h * HDd + e]);
        float o0 = acc2[ni][0] * rn_lo * gl.x / (1.f + expf(-gl.x));
        float o1 = acc2[ni][1] * rn_lo * gl.y / (1.f + expf(-gl.y));
        float o2 = acc2[ni][2] * rn_hi * gh.x / (1.f + expf(-gh.x));
        float o3 = acc2[ni][3] * rn_hi * gh.y / (1.f + expf(-gh.y));
        *(__half2*)&act[grow_lo * E2d + h * HDd + e] = __floats2half2_rn(o0, o1);
        *(__half2*)&act[grow_hi * E2d + h * HDd + e] = __floats2half2_rn(o2, o3);
    }
}

// ---------------- host launch ----------------
extern "C" void kernel_launch(void* const* d_in, const int* in_sizes, int n_in,
                              void* d_out, int out_size)
{
    const float* x    = (const float*)d_in[0];
    const float* sinp = (const float*)d_in[1];
    const float* cosp = (const float*)d_in[2];
    const float* mask = (const float*)d_in[3];
    const float* cdec = (const float*)d_in[4];
    const float* qid  = (const float*)d_in[5];
    const float* vid  = (const float*)d_in[6];
    const float* Wq   = (const float*)d_in[7];
    const float* Wk   = (const float*)d_in[8];
    const float* Wv   = (const float*)d_in[9];
    const float* Wg   = (const float*)d_in[10];
    const float* Wo   = (const float*)d_in[11];
    float* out = (float*)d_out;

    float *p_kv, *p_state, *p_cs;
    __half *p_q, *p_k, *p_v, *p_g, *p_xh, *p_act, *p_wt;
    cudaGetSymbolAddress((void**)&p_q, g_q);
    cudaGetSymbolAddress((void**)&p_k, g_k);
    cudaGetSymbolAddress((void**)&p_v, g_v);
    cudaGetSymbolAddress((void**)&p_g, g_g);
    cudaGetSymbolAddress((void**)&p_act, g_act);
    cudaGetSymbolAddress((void**)&p_xh, g_xh);
    cudaGetSymbolAddress((void**)&p_kv, g_kv);
    cudaGetSymbolAddress((void**)&p_state, g_state);
    cudaGetSymbolAddress((void**)&p_cs, g_cscale);
    cudaGetSymbolAddress((void**)&p_wt, g_wt);

    // fused projection weights [3072, 512]: q rows 0-511, k 512-1023, v 1024-2047, g 2048-3071
    __half* wtf = p_wt;
    __half* wto = p_wt + 1572864;   // [512, 1024]

    cudaFuncSetAttribute(attn_kernel, cudaFuncAttributeMaxDynamicSharedMemorySize, ATTN_SMEM);
    cudaFuncSetAttribute(qkvg_gemm, cudaFuncAttributeMaxDynamicSharedMemorySize, GEMM_SMEM);
    cudaFuncSetAttribute(out_gemm, cudaFuncAttributeMaxDynamicSharedMemorySize, GEMM_SMEM);

    // x -> fp16; weights transpose -> fp16 into fused buffer (0.125 folded into Wk)
    tohalf_kernel<<<(Mtot * Ed / 4) / 256, 256>>>(x, p_xh);
    transpose_kernel<<<dim3(16, 16), dim3(32, 8)>>>(Wq, wtf,               Ed, Ed, 1.0f);
    transpose_kernel<<<dim3(16, 16), dim3(32, 8)>>>(Wk, wtf + 262144,      Ed, Ed, 0.125f);
    transpose_kernel<<<dim3(32, 16), dim3(32, 8)>>>(Wv, wtf + 524288,      Ed, E2d, 1.0f);
    transpose_kernel<<<dim3(32, 16), dim3(32, 8)>>>(Wg, wtf + 1048576,     Ed, E2d, 1.0f);
    transpose_kernel<<<dim3(16, 32), dim3(32, 8)>>>(Wo, wto,               E2d, Ed, 1.0f);

    // fused QKVG projection (one launch; rotary fused for q/k blocks)
    qkvg_gemm<<<dim3(24, 256), 256, GEMM_SMEM>>>(p_xh, wtf, p_q, p_k, p_v, p_g, sinp, cosp);

    // per-chunk kv (tensor cores), scan, cross scale
    kv_kernel<<<Bz * NCd * Hd, 256>>>(p_k, p_v, vid, p_kv);
    scan_kernel<<<(Bz * Hd * KDd * HDd / 4) / 256, 256>>>(
        (const float4*)p_kv, cdec, (float4*)p_state);
    cscale_kernel<<<Bz * NCd * Hd, 128>>>(p_state, p_cs);

    // fp16 tensor-core fused attention (causal chunk skip)
    attn_kernel<<<Bz * NCd * Hd * 4, 256, ATTN_SMEM>>>(
        p_q, p_k, p_v, p_g, p_state, p_cs, mask, qid, p_act);

    // output projection (fp32 out)
    out_gemm<<<dim3(4, 256), 256, GEMM_SMEM>>>(p_act, wto, out);
}

// round 9
// speedup vs baseline: 6.4101x; 1.0172x over previous
#include <cuda_runtime.h>
#include <cuda_fp16.h>
#include <math.h>
#include <stdint.h>

// Dims (fixed for this problem)
#define Bz    4
#define Tl    8192
#define Ed    512
#define Hd    8
#define KDd   64
#define HDd   128
#define Cd    256
#define NCd   32
#define E2d   1024
#define Mtot  32768   // B*T

// ---------------- scratch (device globals; no runtime alloc) ----------------
__device__ __half g_q[(size_t)Mtot * Ed];
__device__ __half g_k[(size_t)Mtot * Ed];
__device__ __half g_v[(size_t)Mtot * E2d];
__device__ __half g_g[(size_t)Mtot * E2d];
__device__ __half g_act[(size_t)Mtot * E2d];
__device__ __half g_xh[(size_t)Mtot * Ed];    // fp16 x
__device__ float  g_kv[(size_t)Bz * NCd * Hd * KDd * HDd];
__device__ float  g_state[(size_t)Bz * NCd * Hd * KDd * HDd];
__device__ float  g_cscale[Bz * NCd * Hd];
__device__ __half g_wt[2621440];   // fused [3072,512] + Wo [512,1024]

__device__ __forceinline__ uint32_t smem_u32(const void* p) {
    uint32_t a;
    asm("{ .reg .u64 t; cvta.to.shared.u64 t, %1; cvt.u32.u64 %0, t; }"
        : "=r"(a) : "l"(p));
    return a;
}

#define LDSM4(r0, r1, r2, r3, a)                                               \
    asm volatile("ldmatrix.sync.aligned.m8n8.x4.shared.b16 {%0,%1,%2,%3}, [%4];" \
                 : "=r"(r0), "=r"(r1), "=r"(r2), "=r"(r3) : "r"(a))

#define LDSM4T(r0, r1, r2, r3, a)                                              \
    asm volatile("ldmatrix.sync.aligned.m8n8.x4.trans.shared.b16 {%0,%1,%2,%3}, [%4];" \
                 : "=r"(r0), "=r"(r1), "=r"(r2), "=r"(r3) : "r"(a))

#define MMA_F16(c, a, b0, b1)                                                  \
    asm volatile("mma.sync.aligned.m16n8k16.row.col.f32.f16.f16.f32 "          \
                 "{%0,%1,%2,%3},{%4,%5,%6,%7},{%8,%9},{%0,%1,%2,%3};"          \
                 : "+f"((c)[0]), "+f"((c)[1]), "+f"((c)[2]), "+f"((c)[3])      \
                 : "r"((a)[0]), "r"((a)[1]), "r"((a)[2]), "r"((a)[3]),         \
                   "r"(b0), "r"(b1))

#define CP_ASYNC16(dst, src)                                                   \
    asm volatile("cp.async.cg.shared.global [%0], [%1], 16;"                   \
                 :: "r"(dst), "l"(src))
#define CP_COMMIT asm volatile("cp.async.commit_group;" ::: "memory")
#define CP_WAIT(n) asm volatile("cp.async.wait_group %0;" :: "n"(n) : "memory")

// ---------------- fused prologue: x->fp16 + all 5 weight transposes ----------
// blocks [0, 16384): tohalf of x.  blocks [16384, 18432): transposes.
#define PRO_X_BLKS 16384
__global__ __launch_bounds__(256) void prologue_kernel(
    const float* __restrict__ x, __half* __restrict__ xh,
    const float* __restrict__ Wq, const float* __restrict__ Wk,
    const float* __restrict__ Wv, const float* __restrict__ Wg,
    const float* __restrict__ Wo, __half* __restrict__ wtf, __half* __restrict__ wto)
{
    int bx = blockIdx.x;
    int tid = threadIdx.x;
    if (bx < PRO_X_BLKS) {
        int i = bx * 256 + tid;
        float4 v = ((const float4*)x)[i];
        ((__half2*)xh)[i * 2]     = __floats2half2_rn(v.x, v.y);
        ((__half2*)xh)[i * 2 + 1] = __floats2half2_rn(v.z, v.w);
        return;
    }
    int t = bx - PRO_X_BLKS;
    const float* W; __half* Wt; int K, N; float scale; int gx, gy;
    if (t < 256)        { W = Wq; Wt = wtf;           K = Ed;  N = Ed;  scale = 1.0f;   gx = t % 16;          gy = t / 16; }
    else if (t < 512)   { W = Wk; Wt = wtf + 262144;  K = Ed;  N = Ed;  scale = 0.125f; gx = (t - 256) % 16;  gy = (t - 256) / 16; }
    else if (t < 1024)  { W = Wv; Wt = wtf + 524288;  K = Ed;  N = E2d; scale = 1.0f;   gx = (t - 512) % 32;  gy = (t - 512) / 32; }
    else if (t < 1536)  { W = Wg; Wt = wtf + 1048576; K = Ed;  N = E2d; scale = 1.0f;   gx = (t - 1024) % 32; gy = (t - 1024) / 32; }
    else                { W = Wo; Wt = wto;           K = E2d; N = Ed;  scale = 1.0f;   gx = (t - 1536) % 16; gy = (t - 1536) / 16; }

    __shared__ float tsm[32][33];
    int n0 = gx * 32, k0 = gy * 32;
    int tx = tid & 31, ty = tid >> 5;  // 32 x 8
#pragma unroll
    for (int i = 0; i < 4; i++)
        tsm[ty + i * 8][tx] = W[(size_t)(k0 + ty + i * 8) * N + n0 + tx];
    __syncthreads();
#pragma unroll
    for (int i = 0; i < 4; i++)
        Wt[(size_t)(n0 + ty + i * 8) * K + k0 + tx] = __float2half_rn(tsm[tx][ty + i * 8] * scale);
}

// ================= GEMM core =========
#define STAGES 3
#define STG_BYTES 16384
#define GEMM_SMEM (STAGES * 2 * STG_BYTES)

#define GEMM_PREFETCH(kt, st, Kdim) do {                                       \
    int _k0 = (kt) * 64;                                                       \
    uint32_t _b = sbase + (st) * STG_BYTES;                                    \
    _Pragma("unroll")                                                          \
    for (int p = 0; p < 4; p++) {                                              \
        int row = p * 32 + ldrow;                                              \
        uint32_t sw = row * 128 + (((uint32_t)(kh * 2)) ^ ((row & 7) << 4));   \
        CP_ASYNC16(_b + sw, &A[(size_t)(rowBlk + row) * (Kdim) + _k0 + kh]);   \
        CP_ASYNC16(_b + BOFF + sw, &Bt[(size_t)(colBlk + row) * (Kdim) + _k0 + kh]); \
    }                                                                          \
    CP_COMMIT;                                                                 \
} while (0)

#define GEMM_MAINLOOP(Kdim) do {                                               \
    const int L = (Kdim) >> 6;                                                 \
    GEMM_PREFETCH(0, 0, Kdim);                                                 \
    GEMM_PREFETCH(1, 1, Kdim);                                                 \
    for (int kt = 0; kt < L; kt++) {                                           \
        CP_WAIT(STAGES - 2);                                                   \
        __syncthreads();                                                       \
        int nf = kt + STAGES - 1;                                              \
        if (nf < L) GEMM_PREFETCH(nf, nf % STAGES, Kdim);                      \
        int st = kt % STAGES;                                                  \
        uint32_t baA = sbase + st * STG_BYTES + offA;                          \
        uint32_t baB = sbase + st * STG_BYTES + BOFF + offB;                   \
        _Pragma("unroll")                                                      \
        for (int s = 0; s < 4; s++) {                                          \
            uint32_t af[4][4];                                                 \
            _Pragma("unroll")                                                  \
            for (int mi = 0; mi < 4; mi++)                                     \
                LDSM4(af[mi][0], af[mi][1], af[mi][2], af[mi][3],              \
                      (baA + mi * 2048) ^ (uint32_t)(s * 32));                 \
            uint32_t bf[8];                                                    \
            LDSM4(bf[0], bf[1], bf[2], bf[3], baB ^ (uint32_t)(s * 32));       \
            LDSM4(bf[4], bf[5], bf[6], bf[7], (baB + 2048) ^ (uint32_t)(s * 32)); \
            _Pragma("unroll")                                                  \
            for (int mi = 0; mi < 4; mi++)                                     \
                _Pragma("unroll")                                              \
                for (int ni = 0; ni < 4; ni++)                                 \
                    MMA_F16(acc[mi][ni], af[mi], bf[ni * 2], bf[ni * 2 + 1]);  \
        }                                                                      \
    }                                                                          \
} while (0)

#define GEMM_PROLOG                                                            \
    extern __shared__ float smemf[];                                           \
    uint32_t sbase = smem_u32(smemf);                                          \
    const uint32_t BOFF = STAGES * STG_BYTES;                                  \
    int tid = threadIdx.x;                                                     \
    int lane = tid & 31;                                                       \
    int w = tid >> 5;                                                          \
    int wm = w & 1;                                                            \
    int wn = w >> 1;                                                           \
    float acc[4][4][4];                                                        \
    _Pragma("unroll")                                                          \
    for (int mi = 0; mi < 4; mi++)                                             \
        _Pragma("unroll")                                                      \
        for (int ni = 0; ni < 4; ni++)                                         \
            _Pragma("unroll")                                                  \
            for (int r = 0; r < 4; r++) acc[mi][ni][r] = 0.f;                  \
    int ldrow = tid >> 3;                                                      \
    int kh = (tid & 7) * 8;                                                    \
    int rowA0 = wm * 64 + (lane & 15);                                         \
    uint32_t offA = rowA0 * 128 + (((lane >> 4) * 16) ^ ((rowA0 & 7) << 4));   \
    int nB0 = wn * 32 + (lane & 7) + ((lane & 16) ? 8 : 0);                    \
    uint32_t offB = nB0 * 128 + ((((lane >> 3) & 1) * 16) ^ ((nB0 & 7) << 4));

// ---------------- fused QKVG projection GEMM ----------------
__global__ __launch_bounds__(256) void qkvg_gemm(
    const __half* __restrict__ A, const __half* __restrict__ Bt,
    __half* __restrict__ qp, __half* __restrict__ kp,
    __half* __restrict__ vp, __half* __restrict__ gp,
    const float* __restrict__ sinp, const float* __restrict__ cosp)
{
    GEMM_PROLOG
    int rowBlk = blockIdx.y * 128;
    int colBlk = blockIdx.x * 128;

    GEMM_MAINLOOP(Ed);

    int cbk = blockIdx.x;
    __half* dst; int N2; int col0; bool rot;
    if (cbk < 4)       { dst = qp; N2 = Ed;  col0 = cbk * 128;        rot = true; }
    else if (cbk < 8)  { dst = kp; N2 = Ed;  col0 = (cbk - 4) * 128;  rot = true; }
    else if (cbk < 16) { dst = vp; N2 = E2d; col0 = (cbk - 8) * 128;  rot = false; }
    else               { dst = gp; N2 = E2d; col0 = (cbk - 16) * 128; rot = false; }

    int r0 = lane >> 2, cp = (lane & 3) * 2;
#pragma unroll
    for (int mi = 0; mi < 4; mi++) {
#pragma unroll
        for (int ni = 0; ni < 4; ni++) {
            size_t row = (size_t)(rowBlk + wm * 64 + mi * 16 + r0);
            int col = col0 + wn * 32 + ni * 8 + cp;
            float o0 = acc[mi][ni][0], o1 = acc[mi][ni][1];
            float o2 = acc[mi][ni][2], o3 = acc[mi][ni][3];
            if (rot) {
                int t = (int)(row % Tl);
                int d = col & 63;
                float2 sl = *(const float2*)&sinp[t * KDd + d];
                float2 cl = *(const float2*)&cosp[t * KDd + d];
                float2 sh = *(const float2*)&sinp[(t + 8) * KDd + d];
                float2 ch = *(const float2*)&cosp[(t + 8) * KDd + d];
                float n0 = o0 * cl.x - o1 * sl.x;
                float n1 = o1 * cl.y + o0 * sl.y;
                float n2 = o2 * ch.x - o3 * sh.x;
                float n3 = o3 * ch.y + o2 * sh.y;
                o0 = n0; o1 = n1; o2 = n2; o3 = n3;
            }
            *(__half2*)&dst[row * N2 + col] = __floats2half2_rn(o0, o1);
            *(__half2*)&dst[(row + 8) * N2 + col] = __floats2half2_rn(o2, o3);
        }
    }
}

// ---------------- output projection GEMM (fp32 out) ----------------
__global__ __launch_bounds__(256) void out_gemm(
    const __half* __restrict__ A, const __half* __restrict__ Bt,
    float* __restrict__ C)
{
    GEMM_PROLOG
    int rowBlk = blockIdx.y * 128;
    int colBlk = blockIdx.x * 128;

    GEMM_MAINLOOP(E2d);

    int r0 = lane >> 2, cp = (lane & 3) * 2;
#pragma unroll
    for (int mi = 0; mi < 4; mi++) {
#pragma unroll
        for (int ni = 0; ni < 4; ni++) {
            size_t row = (size_t)(rowBlk + wm * 64 + mi * 16 + r0);
            int col = colBlk + wn * 32 + ni * 8 + cp;
            float2 w0 = {acc[mi][ni][0], acc[mi][ni][1]};
            float2 w1 = {acc[mi][ni][2], acc[mi][ni][3]};
            *(float2*)&C[row * Ed + col] = w0;
            *(float2*)&C[(row + 8) * Ed + col] = w1;
        }
    }
}

// ---------------- kv per chunk (fp16 tensor cores) ----------------
#define LDAh 72
#define LDVh 136
__global__ __launch_bounds__(256) void kv_kernel(const __half* __restrict__ k,
                                                 const __half* __restrict__ v,
                                                 const float* __restrict__ vid,
                                                 float* __restrict__ kv)
{
    __shared__ __half kr_s[64 * LDAh];
    __shared__ __half vv_s[64 * LDVh];
    int bx = blockIdx.x;
    int h = bx % Hd;
    int n = (bx / Hd) % NCd;
    int b = bx / (Hd * NCd);
    int tid = threadIdx.x;
    int lane = tid & 31;
    int w = tid >> 5;
    int wm3 = w & 3;
    int wn3 = w >> 2;
    int qrow = lane >> 2, qcol = lane & 3;
    int j = lane >> 3, rr = lane & 7;
    uint32_t skr = smem_u32(kr_s), svv = smem_u32(vv_s);
    int arow_off = rr + ((j >> 1) << 3);
    int acol = wm3 * 16 + ((j & 1) << 3);
    int brow_off = rr + ((j & 1) << 3);
    int bcol_off = (j >> 1) << 3;

    float acc[8][4];
#pragma unroll
    for (int ni = 0; ni < 8; ni++)
#pragma unroll
        for (int r = 0; r < 4; r++) acc[ni][r] = 0.f;

    long row0 = (long)b * Tl + n * Cd;
    for (int cc = 0; cc < 4; cc++) {
        __syncthreads();
        {
            int kg = (tid & 3) * 16, row = tid >> 2;
            const uint4* ks_ = (const uint4*)&k[(row0 + cc * 64 + row) * Ed + h * KDd + kg];
            *(uint4*)&kr_s[row * LDAh + kg] = ks_[0];
            *(uint4*)&kr_s[row * LDAh + kg + 8] = ks_[1];
            float vvf = vid[h * Cd + cc * 64 + row];
            __half2 vvh = __floats2half2_rn(vvf, vvf);
            int ec = (tid & 3) * 32;
            const __half2* vp = (const __half2*)&v[(row0 + cc * 64 + row) * E2d + h * HDd + ec];
#pragma unroll
            for (int i = 0; i < 16; i++)
                *(__half2*)&vv_s[row * LDVh + ec + i * 2] = __hmul2(vp[i], vvh);
        }
        __syncthreads();
#pragma unroll
        for (int ks = 0; ks < 4; ks++) {
            uint32_t a[4];
            LDSM4T(a[0], a[1], a[2], a[3],
                   skr + (uint32_t)(((ks * 16 + arow_off) * LDAh + acol) * 2));
#pragma unroll
            for (int eb = 0; eb < 4; eb++) {
                uint32_t b0, b1, b2, b3;
                LDSM4T(b0, b1, b2, b3,
                       svv + (uint32_t)(((ks * 16 + brow_off) * LDVh + wn3 * 64 + eb * 16 + bcol_off) * 2));
                MMA_F16(acc[eb * 2], a, b0, b1);
                MMA_F16(acc[eb * 2 + 1], a, b2, b3);
            }
        }
    }

    float* outp = kv + (size_t)bx * (KDd * HDd);
    int r = wm3 * 16 + qrow;
#pragma unroll
    for (int ni = 0; ni < 8; ni++) {
        int e = wn3 * 64 + ni * 8 + 2 * qcol;
        float2 o0 = {acc[ni][0], acc[ni][1]};
        float2 o1 = {acc[ni][2], acc[ni][3]};
        *(float2*)&outp[r * HDd + e] = o0;
        *(float2*)&outp[(r + 8) * HDd + e] = o1;
    }
}

// ---------------- scan (float4 per thread) ----------------
__global__ void scan_kernel(const float4* __restrict__ kv,
                            const float* __restrict__ cd,
                            float4* __restrict__ state)
{
    int idx = blockIdx.x * 256 + threadIdx.x;
    const int EQ = KDd * HDd / 4;
    int e4 = idx % EQ;
    int bh = idx / EQ;
    int h = bh % Hd, b = bh / Hd;
    float c = cd[h];
    float4 s = {0.f, 0.f, 0.f, 0.f};
    for (int n = 0; n < NCd; n++) {
        size_t off = ((size_t)((b * NCd + n) * Hd + h)) * EQ + e4;
        state[off] = s;
        float4 kvv = kv[off];
        s.x = s.x * c + kvv.x;
        s.y = s.y * c + kvv.y;
        s.z = s.z * c + kvv.z;
        s.w = s.w * c + kvv.w;
    }
}

// ---------------- cross_scale ----------------
__global__ void cscale_kernel(const float* __restrict__ state, float* __restrict__ cs)
{
    int bx = blockIdx.x;
    int e = threadIdx.x;
    const float* sp = state + (size_t)bx * (KDd * HDd);
    float s = 0.f;
#pragma unroll 8
    for (int k2 = 0; k2 < KDd; k2++) s += fabsf(sp[k2 * HDd + e]);
#pragma unroll
    for (int o = 16; o > 0; o >>= 1) s = fmaxf(s, __shfl_xor_sync(0xffffffff, s, o));
    __shared__ float wmax[4];
    if ((e & 31) == 0) wmax[e >> 5] = s;
    __syncthreads();
    if (e == 0) {
        float m = fmaxf(fmaxf(wmax[0], wmax[1]), fmaxf(wmax[2], wmax[3]));
        cs[bx] = fmaxf(m, 1.0f);
    }
}

// ---------------- fp16 tensor-core fused attention per (b,n,h,64-row slab) ---
#define ATTN_SMEM ((3 * 64 * LDAh + 64 * LDVh) * 2 + (128 + 128 + 64) * 4)
__global__ __launch_bounds__(256) void attn_kernel(
    const __half* __restrict__ q, const __half* __restrict__ k,
    const __half* __restrict__ v, const __half* __restrict__ g,
    const float* __restrict__ state, const float* __restrict__ cs,
    const float* __restrict__ mask, const float* __restrict__ qid,
    __half* __restrict__ act)
{
    extern __shared__ char smraw[];
    __half* qr_s = (__half*)smraw;
    __half* kr_s = qr_s + 64 * LDAh;
    __half* qk_s = kr_s + 64 * LDAh;
    __half* v_s  = qk_s + 64 * LDAh;
    float* ipart = (float*)(v_s + 64 * LDVh);
    float* rpart = ipart + 128;
    float* qid_s = rpart + 128;

    int bx = blockIdx.x;
    int cb = bx % 4;
    int h  = (bx / 4) % Hd;
    int n  = (bx / (4 * Hd)) % NCd;
    int b  = bx / (4 * Hd * NCd);
    int tid = threadIdx.x;
    int lane = tid & 31;
    int w = tid >> 5;
    int wm = w >> 1;
    int wn = w & 1;
    int qrow = lane >> 2, qcol = lane & 3;
    int j = lane >> 3, rr = lane & 7;
    int clr = wm * 16 + qrow;
    uint32_t sv = smem_u32(v_s);
    int vrow_off = rr + ((j & 1) << 3);
    int vcol_off = (j >> 1) << 3;
    long row0 = (long)b * Tl + n * Cd;

    {
        int kg = (tid & 3) * 16, row = tid >> 2;
        const uint4* src = (const uint4*)&q[(row0 + cb * 64 + row) * Ed + h * KDd + kg];
        *(uint4*)&qr_s[row * LDAh + kg] = src[0];
        *(uint4*)&qr_s[row * LDAh + kg + 8] = src[1];
        if (tid < 64) qid_s[tid] = qid[h * Cd + cb * 64 + tid];
    }

    const float* mrow = mask + ((size_t)h * Cd + cb * 64) * Cd;
    float rs_lo = 0.f, rs_hi = 0.f;
    float acc2[8][4];
#pragma unroll
    for (int ni = 0; ni < 8; ni++)
#pragma unroll
        for (int r = 0; r < 4; r++) acc2[ni][r] = 0.f;

    for (int dc = 0; dc <= cb; dc++) {   // causal skip
        __syncthreads();
        {
            int kg = (tid & 3) * 16, row = tid >> 2;
            const uint4* ks_ = (const uint4*)&k[(row0 + dc * 64 + row) * Ed + h * KDd + kg];
            *(uint4*)&kr_s[row * LDAh + kg] = ks_[0];
            *(uint4*)&kr_s[row * LDAh + kg + 8] = ks_[1];
            int ec = (tid & 3) * 32;
            const uint4* vp = (const uint4*)&v[(row0 + dc * 64 + row) * E2d + h * HDd + ec];
            *(uint4*)&v_s[row * LDVh + ec]      = vp[0];
            *(uint4*)&v_s[row * LDVh + ec + 8]  = vp[1];
            *(uint4*)&v_s[row * LDVh + ec + 16] = vp[2];
            *(uint4*)&v_s[row * LDVh + ec + 24] = vp[3];
        }
        __syncthreads();

        float acc1[4][4];
#pragma unroll
        for (int ni = 0; ni < 4; ni++)
#pragma unroll
            for (int r = 0; r < 4; r++) acc1[ni][r] = 0.f;
#pragma unroll
        for (int ks = 0; ks < 4; ks++) {
            int kk = ks * 16 + 2 * qcol;
            uint32_t a[4];
            a[0] = *(const uint32_t*)&qr_s[clr * LDAh + kk];
            a[1] = *(const uint32_t*)&qr_s[(clr + 8) * LDAh + kk];
            a[2] = *(const uint32_t*)&qr_s[clr * LDAh + kk + 8];
            a[3] = *(const uint32_t*)&qr_s[(clr + 8) * LDAh + kk + 8];
#pragma unroll
            for (int ni = 0; ni < 4; ni++) {
                int br = wn * 32 + ni * 8 + qrow;
                uint32_t b0 = *(const uint32_t*)&kr_s[br * LDAh + kk];
                uint32_t b1 = *(const uint32_t*)&kr_s[br * LDAh + kk + 8];
                MMA_F16(acc1[ni], a, b0, b1);
            }
        }

#pragma unroll
        for (int ni = 0; ni < 4; ni++) {
            int dl = wn * 32 + ni * 8 + 2 * qcol;
            int d = dc * 64 + dl;
            float2 mlo = *(const float2*)&mrow[(size_t)clr * Cd + d];
            float2 mhi = *(const float2*)&mrow[(size_t)(clr + 8) * Cd + d];
            acc1[ni][0] *= mlo.x; acc1[ni][1] *= mlo.y;
            acc1[ni][2] *= mhi.x; acc1[ni][3] *= mhi.y;
            rs_lo += fabsf(acc1[ni][0]) + fabsf(acc1[ni][1]);
            rs_hi += fabsf(acc1[ni][2]) + fabsf(acc1[ni][3]);
            *(__half2*)&qk_s[clr * LDAh + dl] = __floats2half2_rn(acc1[ni][0], acc1[ni][1]);
            *(__half2*)&qk_s[(clr + 8) * LDAh + dl] = __floats2half2_rn(acc1[ni][2], acc1[ni][3]);
        }
        __syncthreads();

#pragma unroll
        for (int ks = 0; ks < 4; ks++) {
            int kk = ks * 16 + 2 * qcol;
            uint32_t a[4];
            a[0] = *(const uint32_t*)&qk_s[clr * LDAh + kk];
            a[1] = *(const uint32_t*)&qk_s[(clr + 8) * LDAh + kk];
            a[2] = *(const uint32_t*)&qk_s[clr * LDAh + kk + 8];
            a[3] = *(const uint32_t*)&qk_s[(clr + 8) * LDAh + kk + 8];
#pragma unroll
            for (int eb = 0; eb < 4; eb++) {
                int e0 = wn * 64 + eb * 16;
                uint32_t b0, b1, b2, b3;
                LDSM4T(b0, b1, b2, b3,
                       sv + (uint32_t)(((ks * 16 + vrow_off) * LDVh + e0 + vcol_off) * 2));
                MMA_F16(acc2[eb * 2], a, b0, b1);
                MMA_F16(acc2[eb * 2 + 1], a, b2, b3);
            }
        }
    }

    __syncthreads();
    {
        const float* sp = state + ((size_t)((b * NCd + n) * Hd + h)) * (KDd * HDd);
        int row = tid >> 2, col = (tid & 3) * 32;
        const float4* sp4 = (const float4*)&sp[row * HDd + col];
#pragma unroll
        for (int i = 0; i < 8; i++) {
            float4 a4 = sp4[i];
            *(__half2*)&v_s[row * LDVh + col + i * 4]     = __floats2half2_rn(a4.x, a4.y);
            *(__half2*)&v_s[row * LDVh + col + i * 4 + 2] = __floats2half2_rn(a4.z, a4.w);
        }
    }
    __syncthreads();

    float acc3[8][4];
#pragma unroll
    for (int ni = 0; ni < 8; ni++)
#pragma unroll
        for (int r = 0; r < 4; r++) acc3[ni][r] = 0.f;
#pragma unroll
    for (int ks = 0; ks < 4; ks++) {
        int kk = ks * 16 + 2 * qcol;
        uint32_t a[4];
        a[0] = *(const uint32_t*)&qr_s[clr * LDAh + kk];
        a[1] = *(const uint32_t*)&qr_s[(clr + 8) * LDAh + kk];
        a[2] = *(const uint32_t*)&qr_s[clr * LDAh + kk + 8];
        a[3] = *(const uint32_t*)&qr_s[(clr + 8) * LDAh + kk + 8];
#pragma unroll
        for (int eb = 0; eb < 4; eb++) {
            int e0 = wn * 64 + eb * 16;
            uint32_t b0, b1, b2, b3;
            LDSM4T(b0, b1, b2, b3,
                   sv + (uint32_t)(((ks * 16 + vrow_off) * LDVh + e0 + vcol_off) * 2));
            MMA_F16(acc3[eb * 2], a, b0, b1);
            MMA_F16(acc3[eb * 2 + 1], a, b2, b3);
        }
    }

    rs_lo += __shfl_xor_sync(0xffffffff, rs_lo, 1);
    rs_lo += __shfl_xor_sync(0xffffffff, rs_lo, 2);
    rs_hi += __shfl_xor_sync(0xffffffff, rs_hi, 1);
    rs_hi += __shfl_xor_sync(0xffffffff, rs_hi, 2);
    if ((lane & 3) == 0) {
        ipart[wn * 64 + clr] = rs_lo;
        ipart[wn * 64 + clr + 8] = rs_hi;
    }
    __syncthreads();

    float csc = cs[(b * NCd + n) * Hd + h];
    float is_lo = fmaxf(1.f, ipart[clr] + ipart[64 + clr]);
    float is_hi = fmaxf(1.f, ipart[clr + 8] + ipart[64 + clr + 8]);
    float inv_lo = 1.f / fmaxf(is_lo, csc);
    float inv_hi = 1.f / fmaxf(is_hi, csc);
    float qd_lo = qid_s[clr], qd_hi = qid_s[clr + 8];

    float ss_lo = 0.f, ss_hi = 0.f;
#pragma unroll
    for (int ni = 0; ni < 8; ni++) {
        acc2[ni][0] = (acc2[ni][0] + qd_lo * acc3[ni][0]) * inv_lo;
        acc2[ni][1] = (acc2[ni][1] + qd_lo * acc3[ni][1]) * inv_lo;
        acc2[ni][2] = (acc2[ni][2] + qd_hi * acc3[ni][2]) * inv_hi;
        acc2[ni][3] = (acc2[ni][3] + qd_hi * acc3[ni][3]) * inv_hi;
        ss_lo += acc2[ni][0] * acc2[ni][0] + acc2[ni][1] * acc2[ni][1];
        ss_hi += acc2[ni][2] * acc2[ni][2] + acc2[ni][3] * acc2[ni][3];
    }
    ss_lo += __shfl_xor_sync(0xffffffff, ss_lo, 1);
    ss_lo += __shfl_xor_sync(0xffffffff, ss_lo, 2);
    ss_hi += __shfl_xor_sync(0xffffffff, ss_hi, 1);
    ss_hi += __shfl_xor_sync(0xffffffff, ss_hi, 2);
    if ((lane & 3) == 0) {
        rpart[wn * 64 + clr] = ss_lo;
        rpart[wn * 64 + clr + 8] = ss_hi;
    }
    __syncthreads();

    float rn_lo = rsqrtf((rpart[clr] + rpart[64 + clr]) * (1.f / 128.f) + 1e-6f);
    float rn_hi = rsqrtf((rpart[clr + 8] + rpart[64 + clr + 8]) * (1.f / 128.f) + 1e-6f);

    long grow_lo = row0 + cb * 64 + clr;
    long grow_hi = grow_lo + 8;
#pragma unroll
    for (int ni = 0; ni < 8; ni++) {
        int e = wn * 64 + ni * 8 + 2 * qcol;
        float2 gl = __half22float2(*(const __half2*)&g[grow_lo * E2d + h * HDd + e]);
        float2 gh = __half22float2(*(const __half2*)&g[grow_hi * E2d + h * HDd + e]);
        float o0 = acc2[ni][0] * rn_lo * gl.x / (1.f + expf(-gl.x));
        float o1 = acc2[ni][1] * rn_lo * gl.y / (1.f + expf(-gl.y));
        float o2 = acc2[ni][2] * rn_hi * gh.x / (1.f + expf(-gh.x));
        float o3 = acc2[ni][3] * rn_hi * gh.y / (1.f + expf(-gh.y));
        *(__half2*)&act[grow_lo * E2d + h * HDd + e] = __floats2half2_rn(o0, o1);
        *(__half2*)&act[grow_hi * E2d + h * HDd + e] = __floats2half2_rn(o2, o3);
    }
}

// ---------------- host launch ----------------
extern "C" void kernel_launch(void* const* d_in, const int* in_sizes, int n_in,
                              void* d_out, int out_size)
{
    const float* x    = (const float*)d_in[0];
    const float* sinp = (const float*)d_in[1];
    const float* cosp = (const float*)d_in[2];
    const float* mask = (const float*)d_in[3];
    const float* cdec = (const float*)d_in[4];
    const float* qid  = (const float*)d_in[5];
    const float* vid  = (const float*)d_in[6];
    const float* Wq   = (const float*)d_in[7];
    const float* Wk   = (const float*)d_in[8];
    const float* Wv   = (const float*)d_in[9];
    const float* Wg   = (const float*)d_in[10];
    const float* Wo   = (const float*)d_in[11];
    float* out = (float*)d_out;

    float *p_kv, *p_state, *p_cs;
    __half *p_q, *p_k, *p_v, *p_g, *p_xh, *p_act, *p_wt;
    cudaGetSymbolAddress((void**)&p_q, g_q);
    cudaGetSymbolAddress((void**)&p_k, g_k);
    cudaGetSymbolAddress((void**)&p_v, g_v);
    cudaGetSymbolAddress((void**)&p_g, g_g);
    cudaGetSymbolAddress((void**)&p_act, g_act);
    cudaGetSymbolAddress((void**)&p_xh, g_xh);
    cudaGetSymbolAddress((void**)&p_kv, g_kv);
    cudaGetSymbolAddress((void**)&p_state, g_state);
    cudaGetSymbolAddress((void**)&p_cs, g_cscale);
    cudaGetSymbolAddress((void**)&p_wt, g_wt);

    __half* wtf = p_wt;
    __half* wto = p_wt + 1572864;

    cudaFuncSetAttribute(attn_kernel, cudaFuncAttributeMaxDynamicSharedMemorySize, ATTN_SMEM);
    cudaFuncSetAttribute(qkvg_gemm, cudaFuncAttributeMaxDynamicSharedMemorySize, GEMM_SMEM);
    cudaFuncSetAttribute(out_gemm, cudaFuncAttributeMaxDynamicSharedMemorySize, GEMM_SMEM);

    // fused prologue: x->fp16 + all weight transposes in one launch
    prologue_kernel<<<PRO_X_BLKS + 2048, 256>>>(x, p_xh, Wq, Wk, Wv, Wg, Wo, wtf, wto);

    // fused QKVG projection (one launch; rotary fused for q/k blocks)
    qkvg_gemm<<<dim3(24, 256), 256, GEMM_SMEM>>>(p_xh, wtf, p_q, p_k, p_v, p_g, sinp, cosp);

    // per-chunk kv (tensor cores), scan, cross scale
    kv_kernel<<<Bz * NCd * Hd, 256>>>(p_k, p_v, vid, p_kv);
    scan_kernel<<<(Bz * Hd * KDd * HDd / 4) / 256, 256>>>(
        (const float4*)p_kv, cdec, (float4*)p_state);
    cscale_kernel<<<Bz * NCd * Hd, 128>>>(p_state, p_cs);

    // fp16 tensor-core fused attention (causal chunk skip)
    attn_kernel<<<Bz * NCd * Hd * 4, 256, ATTN_SMEM>>>(
        p_q, p_k, p_v, p_g, p_state, p_cs, mask, qid, p_act);

    // output projection (fp32 out)
    out_gemm<<<dim3(4, 256), 256, GEMM_SMEM>>>(p_act, wto, out);
}